// round 9
// baseline (speedup 1.0000x reference)
#include <cuda_runtime.h>
#include <math.h>

// Problem constants
#define Bq 2
#define Sq 2048
#define DM 1024
#define Hq 16
#define DHq 64

// ---------------------------------------------------------------------------
// Scratch (__device__ globals)
// All tf32 BIT PATTERNS with within-8-group K/D permutation r -> (r&3)*2|(r>>2)
// qh additionally carries the 1/8 score scale.
// ---------------------------------------------------------------------------
__device__ unsigned g_qh [(size_t)Bq * Hq * Sq * DHq];   // [B,H,S,DH] tf32, d-perm, x0.125
__device__ unsigned g_kh [(size_t)Bq * Hq * Sq * DHq];   // [B,H,S,DH] tf32, d-perm
__device__ unsigned g_vh [(size_t)Bq * Hq * Sq * DHq];   // [B,H,S,DH] tf32, NO perm
__device__ unsigned g_ctx[(size_t)Bq * Sq * DM];          // [B,S,DM]   tf32, d-perm
// prep outputs: inputs and weights, tf32 bits, K-dim permuted
__device__ unsigned g_xq[(size_t)Bq * Sq * DM];
__device__ unsigned g_xk[(size_t)Bq * Sq * DM];
__device__ unsigned g_xv[(size_t)Bq * Sq * DM];
__device__ unsigned g_wq[(size_t)DM * DM];
__device__ unsigned g_wk[(size_t)DM * DM];
__device__ unsigned g_wv[(size_t)DM * DM];
__device__ unsigned g_wo[(size_t)DM * DM];

// ---------------------------------------------------------------------------
// Helpers
// ---------------------------------------------------------------------------
__device__ __forceinline__ unsigned f2tf32(float f) {
    unsigned r; asm("cvt.rna.tf32.f32 %0, %1;" : "=r"(r) : "f"(f)); return r;
}
__device__ __forceinline__ int perm8(int r) { return ((r & 3) << 1) | (r >> 2); }
__device__ __forceinline__ void cpa16(void* dst, const void* src) {
    unsigned d = (unsigned)__cvta_generic_to_shared(dst);
    asm volatile("cp.async.cg.shared.global [%0], [%1], 16;" :: "r"(d), "l"(src));
}
__device__ __forceinline__ void cp_commit() { asm volatile("cp.async.commit_group;"); }
__device__ __forceinline__ void cp_wait1()  { asm volatile("cp.async.wait_group 1;"); }

__device__ __forceinline__ void mma8(float* c, unsigned a0, unsigned a1, unsigned a2,
                                     unsigned a3, unsigned b0, unsigned b1) {
    asm volatile(
        "mma.sync.aligned.m16n8k8.row.col.f32.tf32.tf32.f32 "
        "{%0,%1,%2,%3}, {%4,%5,%6,%7}, {%8,%9}, {%0,%1,%2,%3};"
        : "+f"(c[0]), "+f"(c[1]), "+f"(c[2]), "+f"(c[3])
        : "r"(a0), "r"(a1), "r"(a2), "r"(a3), "r"(b0), "r"(b1));
}

// ---------------------------------------------------------------------------
// Prep: fp32 -> tf32 bits with K-permutation (within 8-groups).
// z selects tensor: 0..3 weights (1M el), 4..6 inputs (4M el).
// ---------------------------------------------------------------------------
struct PrepP { const float* in[7]; unsigned* out[7]; };

__global__ __launch_bounds__(256)
void prep_cvt(PrepP pp)
{
    int z = blockIdx.y;
    int n = (z < 4) ? (DM * DM) : (Bq * Sq * DM);
    int idx4 = (blockIdx.x * 256 + threadIdx.x) * 4;
    if (idx4 >= n) return;
    const float* in = pp.in[z];
    unsigned* out = pp.out[z];
    float4 v = *(const float4*)&in[idx4];
    int base = idx4 & ~7;
    int off  = (idx4 & 7) ? 1 : 0;   // idx4%8 is 0 or 4
    out[base + off + 0] = f2tf32(v.x);
    out[base + off + 2] = f2tf32(v.y);
    out[base + off + 4] = f2tf32(v.z);
    out[base + off + 6] = f2tf32(v.w);
}

// ---------------------------------------------------------------------------
// GEMM: Y = (A @ W^T + bias), A & W pre-converted tf32 bits, K-permuted.
// Mainloop: zero cvt, paired LDS.64 fragment loads.
// OUT_HEAD=true: head layout ((b*H+h)*S+s)*DH+d, tf32 store, optional d-perm,
//                per-z pscale. OUT_HEAD=false: plain fp32 Y[m*N+n].
// ---------------------------------------------------------------------------
struct GemmP {
    const unsigned *X, *X1, *X2;
    const unsigned *W, *W1, *W2;
    const float *b0_, *b1_, *b2_;
    void *Y, *Y1, *Y2;
    int M, N, K;
    int qkv;
    float ps[3];
    int nperm[3];
};

#define AS   36
#define A_WORDS 4608     // 128*36
#define G_SMEM_BYTES (4 * A_WORDS * 4)

template <bool OUT_HEAD>
__global__ __launch_bounds__(256, 2)
void gemm_tc(GemmP p)
{
    const int m0 = blockIdx.y * 128;
    const int n0 = blockIdx.x * 128;
    const int z  = blockIdx.z;
    const int tid = threadIdx.x, lane = tid & 31, warp = tid >> 5;
    const int wm = warp & 1, wn = warp >> 1;

    const unsigned *X = p.X, *W = p.W; const float* bias = p.b0_; void* Y = p.Y;
    float pscale = p.ps[0]; int nperm = p.nperm[0];
    if (p.qkv) {
        if (z == 1) { X = p.X1; W = p.W1; bias = p.b1_; Y = p.Y1; pscale = p.ps[1]; nperm = p.nperm[1]; }
        else if (z == 2) { X = p.X2; W = p.W2; bias = p.b2_; Y = p.Y2; pscale = p.ps[2]; nperm = p.nperm[2]; }
    }

    extern __shared__ unsigned smu[];
    unsigned* Abuf[2] = { smu,               smu + A_WORDS     };
    unsigned* Bbuf[2] = { smu + 2 * A_WORDS, smu + 3 * A_WORDS };

    auto loadA = [&](unsigned* As_, int k0) {
        int r0 = tid >> 3, c = (tid & 7) * 4;
#pragma unroll
        for (int it = 0; it < 4; it++) {
            int r = r0 + it * 32;
            cpa16(&As_[r * AS + c], &X[(long long)(m0 + r) * p.K + k0 + c]);
        }
    };
    auto loadB = [&](unsigned* Bs_, int k0) {
        int r0 = tid >> 3, c = (tid & 7) * 4;
#pragma unroll
        for (int it = 0; it < 4; it++) {
            int r = r0 + it * 32;
            cpa16(&Bs_[r * AS + c], &W[(long long)(n0 + r) * p.K + k0 + c]);
        }
    };

    float acc[4][4][4] = {};

    loadA(Abuf[0], 0); loadB(Bbuf[0], 0); cp_commit();
    int st = 0;
    for (int k0 = 0; k0 < p.K; k0 += 32) {
        if (k0 + 32 < p.K) { loadA(Abuf[st ^ 1], k0 + 32); loadB(Bbuf[st ^ 1], k0 + 32); }
        cp_commit();
        cp_wait1();
        __syncthreads();

        const unsigned* As_ = Abuf[st];
        const unsigned* Bs_ = Bbuf[st];
#pragma unroll
        for (int kk = 0; kk < 32; kk += 8) {
            const int kp = kk + 2 * (lane & 3);
            unsigned a[4][4];
#pragma unroll
            for (int i = 0; i < 4; i++) {
                int mr = wm * 64 + i * 16 + (lane >> 2);
                uint2 lo = *(const uint2*)&As_[mr * AS + kp];
                uint2 hi = *(const uint2*)&As_[(mr + 8) * AS + kp];
                a[i][0] = lo.x; a[i][1] = hi.x; a[i][2] = lo.y; a[i][3] = hi.y;
            }
            unsigned b[4][2];
#pragma unroll
            for (int j = 0; j < 4; j++) {
                int nr = wn * 32 + j * 8 + (lane >> 2);
                uint2 bb = *(const uint2*)&Bs_[nr * AS + kp];
                b[j][0] = bb.x; b[j][1] = bb.y;
            }
#pragma unroll
            for (int i = 0; i < 4; i++)
#pragma unroll
                for (int j = 0; j < 4; j++)
                    mma8(acc[i][j], a[i][0], a[i][1], a[i][2], a[i][3], b[j][0], b[j][1]);
        }
        __syncthreads();
        st ^= 1;
    }

#pragma unroll
    for (int i = 0; i < 4; i++)
#pragma unroll
        for (int j = 0; j < 4; j++)
#pragma unroll
            for (int h = 0; h < 2; h++) {
                int m = m0 + wm * 64 + i * 16 + (lane >> 2) + h * 8;
                int n = n0 + wn * 32 + j * 8 + (lane & 3) * 2;
                float v0 = acc[i][j][h * 2]     + (bias ? bias[n]     : 0.f);
                float v1 = acc[i][j][h * 2 + 1] + (bias ? bias[n + 1] : 0.f);
                if (OUT_HEAD) {
                    int b_ = m >> 11;
                    int s  = m & (Sq - 1);
                    int hh = n >> 6;
                    int d  = n & (DHq - 1);
                    long long rowb = (((long long)b_ * Hq + hh) * Sq + s) * DHq;
                    unsigned u0 = f2tf32(v0 * pscale);
                    unsigned u1 = f2tf32(v1 * pscale);
                    unsigned* Yu = (unsigned*)Y;
                    if (nperm) {
                        int r0 = d & 7;
                        Yu[rowb + (d & ~7) + perm8(r0)]     = u0;
                        Yu[rowb + (d & ~7) + perm8(r0 + 1)] = u1;
                    } else {
                        *(uint2*)&Yu[rowb + d] = make_uint2(u0, u1);
                    }
                } else {
                    long long idx = (long long)m * p.N + n;
                    *(float2*)((float*)Y + idx) = make_float2(v0, v1);
                }
            }
}

// ---------------------------------------------------------------------------
// Fused flash attention. 256 threads, 8 warps x 16 rows. Q/K tf32 d-permuted
// (paired LDS.64 fragment loads, zero cvt); V tf32 unpermuted. ctx written as
// tf32 bits, d-permuted (consumed raw by out-proj). qt reversed.
// ---------------------------------------------------------------------------
#define QS_OFF 0
#define KS_OFF 8704            // Qs: 128*68
#define VS_OFF (8704 + 2*8704) // Ks: 2 x 128*68
#define F_SMEM_WORDS (26112 + 2*9216)
#define F_SMEM_BYTES (F_SMEM_WORDS * 4)

__global__ __launch_bounds__(256, 1)
void attn_flash(const unsigned* __restrict__ qh, const unsigned* __restrict__ kh,
                const unsigned* __restrict__ vh, unsigned* __restrict__ ctx,
                float* __restrict__ attn, int write_attn)
{
    const int qt = (int)gridDim.x - 1 - (int)blockIdx.x;
    const int z  = blockIdx.y;
    const int tid = threadIdx.x, lane = tid & 31, warp = tid >> 5;

    extern __shared__ unsigned smu[];
    unsigned* Qs = smu + QS_OFF;
    unsigned* Ksb[2] = { smu + KS_OFF, smu + KS_OFF + 8704 };
    unsigned* Vsb[2] = { smu + VS_OFF, smu + VS_OFF + 9216 };

    const unsigned* Qg = qh + ((long long)z * Sq + qt * 128) * DHq;
    const unsigned* Kg = kh + (long long)z * Sq * DHq;
    const unsigned* Vg = vh + (long long)z * Sq * DHq;

    for (int i = tid; i < 128 * 16; i += 256) {
        int r = i >> 4, c4 = (i & 15) * 4;
        *(uint4*)&Qs[r * 68 + c4] = *(const uint4*)&Qg[r * 64 + c4];
    }

    auto loadK = [&](int kt, int buf) {
        for (int i = tid; i < 128 * 16; i += 256) {
            int r = i >> 4, c4 = (i & 15) * 4;
            cpa16(&Ksb[buf][r * 68 + c4], &Kg[((long long)kt * 128 + r) * 64 + c4]);
        }
    };
    auto loadV = [&](int kt, int buf) {
        for (int i = tid; i < 128 * 16; i += 256) {
            int r = i >> 4, c4 = (i & 15) * 4;
            cpa16(&Vsb[buf][r * 72 + c4], &Vg[((long long)kt * 128 + r) * 64 + c4]);
        }
    };

    const unsigned* Qw = &Qs[(warp * 16) * 68];
    const int rq = lane >> 2;
    const int q4 = lane & 3;
    const int rbase = qt * 128 + warp * 16 + rq;

    float cacc[8][4] = {};
    float l0 = 0.f, l1 = 0.f;
    float p[16][4];

    loadK(0, 0); loadV(0, 0); cp_commit();

    for (int kt = 0; kt <= qt; kt++) {
        int buf = kt & 1;
        __syncthreads();
        if (kt < qt) { loadK(kt + 1, buf ^ 1); loadV(kt + 1, buf ^ 1); }
        cp_commit();
        cp_wait1();
        __syncthreads();

        const unsigned* Kb = Ksb[buf];
        const unsigned* Vb = Vsb[buf];

        // ---- S = Q @ K^T : paired LDS.64 frag loads, zero cvt ----
#pragma unroll
        for (int j = 0; j < 16; j++) { p[j][0] = p[j][1] = p[j][2] = p[j][3] = 0.f; }
#pragma unroll
        for (int ks = 0; ks < 8; ks++) {
            const int kp = ks * 8 + 2 * q4;
            uint2 qlo = *(const uint2*)&Qw[rq * 68 + kp];
            uint2 qhi = *(const uint2*)&Qw[(rq + 8) * 68 + kp];
#pragma unroll
            for (int j = 0; j < 16; j++) {
                int n = j * 8 + rq;
                uint2 kb = *(const uint2*)&Kb[n * 68 + kp];
                mma8(p[j], qlo.x, qhi.x, qlo.y, qhi.y, kb.x, kb.y);
            }
        }

        // ---- mask + exp + row-sum ----
        bool diag = (kt == qt);
#pragma unroll
        for (int j = 0; j < 16; j++) {
            int c0 = kt * 128 + j * 8 + 2 * q4;
            float e0 = (!diag || c0     <= rbase    ) ? __expf(p[j][0]) : 0.f;
            float e1 = (!diag || c0 + 1 <= rbase    ) ? __expf(p[j][1]) : 0.f;
            float e2 = (!diag || c0     <= rbase + 8) ? __expf(p[j][2]) : 0.f;
            float e3 = (!diag || c0 + 1 <= rbase + 8) ? __expf(p[j][3]) : 0.f;
            p[j][0] = e0; p[j][1] = e1; p[j][2] = e2; p[j][3] = e3;
            l0 += e0 + e1; l1 += e2 + e3;
        }

        // ---- ctx += P @ V (quad shuffles for A-frags; V raw tf32) ----
        int hlo = (lane & ~3) | (q4 >> 1);
        int hhi = hlo | 2;
        bool odd = lane & 1;
#pragma unroll
        for (int t = 0; t < 16; t++) {
            float v00 = __shfl_sync(0xffffffffu, p[t][0], hlo);
            float v01 = __shfl_sync(0xffffffffu, p[t][1], hlo);
            float v20 = __shfl_sync(0xffffffffu, p[t][2], hlo);
            float v21 = __shfl_sync(0xffffffffu, p[t][3], hlo);
            float w00 = __shfl_sync(0xffffffffu, p[t][0], hhi);
            float w01 = __shfl_sync(0xffffffffu, p[t][1], hhi);
            float w20 = __shfl_sync(0xffffffffu, p[t][2], hhi);
            float w21 = __shfl_sync(0xffffffffu, p[t][3], hhi);
            unsigned a0 = f2tf32(odd ? v01 : v00);
            unsigned a1 = f2tf32(odd ? v21 : v20);
            unsigned a2 = f2tf32(odd ? w01 : w00);
            unsigned a3 = f2tf32(odd ? w21 : w20);
            int kr = t * 8 + q4;
#pragma unroll
            for (int j = 0; j < 8; j++) {
                int n = j * 8 + rq;
                mma8(cacc[j], a0, a1, a2, a3, Vb[kr * 72 + n], Vb[(kr + 4) * 72 + n]);
            }
        }
    }

    l0 += __shfl_xor_sync(0xffffffffu, l0, 1);
    l0 += __shfl_xor_sync(0xffffffffu, l0, 2);
    l1 += __shfl_xor_sync(0xffffffffu, l1, 1);
    l1 += __shfl_xor_sync(0xffffffffu, l1, 2);
    float inv0 = 1.0f / l0, inv1 = 1.0f / l1;

    // ---- ctx epilogue -> tf32 bits, d-permuted (for out-proj raw A-path) ----
    {
        int b_ = z >> 4, h_ = z & 15;
        long long base0 = ((long long)b_ * Sq + rbase) * DM + h_ * 64;
        long long base1 = base0 + 8LL * DM;
        int r0 = 2 * q4;
        int p0 = perm8(r0), p1 = perm8(r0 + 1);
#pragma unroll
        for (int j = 0; j < 8; j++) {
            int g = j * 8;
            ctx[base0 + g + p0] = f2tf32(cacc[j][0] * inv0);
            ctx[base0 + g + p1] = f2tf32(cacc[j][1] * inv0);
            ctx[base1 + g + p0] = f2tf32(cacc[j][2] * inv1);
            ctx[base1 + g + p1] = f2tf32(cacc[j][3] * inv1);
        }
    }

    // ---- Pass B: recompute S, write normalized attn ----
    if (write_attn) {
        float* A = attn + (long long)z * Sq * Sq;
        __syncthreads();
        loadK(0, 0); cp_commit();
        for (int kt = 0; kt <= qt; kt++) {
            int buf = kt & 1;
            __syncthreads();
            if (kt < qt) loadK(kt + 1, buf ^ 1);
            cp_commit();
            cp_wait1();
            __syncthreads();

            const unsigned* Kb = Ksb[buf];
#pragma unroll
            for (int j = 0; j < 16; j++) { p[j][0] = p[j][1] = p[j][2] = p[j][3] = 0.f; }
#pragma unroll
            for (int ks = 0; ks < 8; ks++) {
                const int kp = ks * 8 + 2 * q4;
                uint2 qlo = *(const uint2*)&Qw[rq * 68 + kp];
                uint2 qhi = *(const uint2*)&Qw[(rq + 8) * 68 + kp];
#pragma unroll
                for (int j = 0; j < 16; j++) {
                    int n = j * 8 + rq;
                    uint2 kb = *(const uint2*)&Kb[n * 68 + kp];
                    mma8(p[j], qlo.x, qhi.x, qlo.y, qhi.y, kb.x, kb.y);
                }
            }
            bool diag = (kt == qt);
            long long row0 = (long long)rbase * Sq;
            long long row1 = (long long)(rbase + 8) * Sq;
#pragma unroll
            for (int j = 0; j < 16; j++) {
                int c0 = kt * 128 + j * 8 + 2 * q4;
                float e0 = (!diag || c0     <= rbase    ) ? __expf(p[j][0]) * inv0 : 0.f;
                float e1 = (!diag || c0 + 1 <= rbase    ) ? __expf(p[j][1]) * inv0 : 0.f;
                float e2 = (!diag || c0     <= rbase + 8) ? __expf(p[j][2]) * inv1 : 0.f;
                float e3 = (!diag || c0 + 1 <= rbase + 8) ? __expf(p[j][3]) * inv1 : 0.f;
                *(float2*)&A[row0 + c0] = make_float2(e0, e1);
                *(float2*)&A[row1 + c0] = make_float2(e2, e3);
            }
        }
        int cEnd = (qt + 1) * 128;
        int nz4 = (Sq - cEnd) >> 2;
        if (nz4 > 0) {
            float4 z4 = make_float4(0.f, 0.f, 0.f, 0.f);
            for (int i = tid; i < 128 * nz4; i += 256) {
                int r = i / nz4, c = (i - r * nz4) * 4;
                *(float4*)&A[(long long)(qt * 128 + r) * Sq + cEnd + c] = z4;
            }
        }
    }
}

// ---------------------------------------------------------------------------
// kernel_launch
// ---------------------------------------------------------------------------
extern "C" void kernel_launch(void* const* d_in, const int* in_sizes, int n_in,
                              void* d_out, int out_size)
{
    const float* q  = (const float*)d_in[0];
    const float* k  = (const float*)d_in[1];
    const float* v  = (const float*)d_in[2];
    // d_in[3] = causal tril mask (handled analytically)
    const float* wq = (const float*)d_in[4];
    const float* bq = (const float*)d_in[5];
    const float* wk = (const float*)d_in[6];
    const float* bk = (const float*)d_in[7];
    const float* wv = (const float*)d_in[8];
    const float* bv = (const float*)d_in[9];
    const float* wo = (const float*)d_in[10];
    const float* bo = (const float*)d_in[11];
    float* out = (float*)d_out;

    unsigned *qh, *kh, *vh, *ctx, *xq, *xk, *xv, *pwq, *pwk, *pwv, *pwo;
    cudaGetSymbolAddress((void**)&qh,  g_qh);
    cudaGetSymbolAddress((void**)&kh,  g_kh);
    cudaGetSymbolAddress((void**)&vh,  g_vh);
    cudaGetSymbolAddress((void**)&ctx, g_ctx);
    cudaGetSymbolAddress((void**)&xq,  g_xq);
    cudaGetSymbolAddress((void**)&xk,  g_xk);
    cudaGetSymbolAddress((void**)&xv,  g_xv);
    cudaGetSymbolAddress((void**)&pwq, g_wq);
    cudaGetSymbolAddress((void**)&pwk, g_wk);
    cudaGetSymbolAddress((void**)&pwv, g_wv);
    cudaGetSymbolAddress((void**)&pwo, g_wo);

    const long long OUT_E  = (long long)Bq * Sq * DM;
    const long long ATTN_E = (long long)Bq * Hq * Sq * Sq;
    int write_attn = ((long long)out_size >= OUT_E + ATTN_E) ? 1 : 0;
    float* attn = out + OUT_E;

    static int attr_done = 0;
    if (!attr_done) {
        cudaFuncSetAttribute(gemm_tc<true>,
                             cudaFuncAttributeMaxDynamicSharedMemorySize, G_SMEM_BYTES);
        cudaFuncSetAttribute(gemm_tc<false>,
                             cudaFuncAttributeMaxDynamicSharedMemorySize, G_SMEM_BYTES);
        cudaFuncSetAttribute(attn_flash,
                             cudaFuncAttributeMaxDynamicSharedMemorySize, F_SMEM_BYTES);
        attr_done = 1;
    }

    // 0: prep — weights + inputs -> tf32 bits, K-permuted
    PrepP pp;
    pp.in[0] = wq; pp.out[0] = pwq;
    pp.in[1] = wk; pp.out[1] = pwk;
    pp.in[2] = wv; pp.out[2] = pwv;
    pp.in[3] = wo; pp.out[3] = pwo;
    pp.in[4] = q;  pp.out[4] = xq;
    pp.in[5] = k;  pp.out[5] = xk;
    pp.in[6] = v;  pp.out[6] = xv;
    prep_cvt<<<dim3((Bq * Sq * DM) / (256 * 4), 7), 256>>>(pp);

    // 1: fused QKV projections (raw tf32 mainloop)
    GemmP pq = {};
    pq.X  = xq; pq.W  = pwq; pq.b0_ = bq; pq.Y  = qh;
    pq.X1 = xk; pq.W1 = pwk; pq.b1_ = bk; pq.Y1 = kh;
    pq.X2 = xv; pq.W2 = pwv; pq.b2_ = bv; pq.Y2 = vh;
    pq.M = Bq * Sq; pq.N = DM; pq.K = DM; pq.qkv = 1;
    pq.ps[0] = 0.125f; pq.ps[1] = 1.f; pq.ps[2] = 1.f;
    pq.nperm[0] = 1; pq.nperm[1] = 1; pq.nperm[2] = 0;
    gemm_tc<true><<<dim3(DM / 128, (Bq * Sq) / 128, 3), 256, G_SMEM_BYTES>>>(pq);

    // 2: fused flash attention (+ attn output); ctx -> tf32 d-permuted
    attn_flash<<<dim3(Sq / 128, Bq * Hq, 1), 256, F_SMEM_BYTES>>>(
        qh, kh, vh, ctx, attn, write_attn);

    // 3: out = ctx @ wo^T + bo (raw tf32 mainloop, fp32 output)
    GemmP po = {};
    po.X = ctx; po.W = pwo; po.b0_ = bo; po.Y = out;
    po.M = Bq * Sq; po.N = DM; po.K = DM; po.qkv = 0;
    po.ps[0] = 1.f; po.nperm[0] = 0;
    gemm_tc<false><<<dim3(DM / 128, (Bq * Sq) / 128, 1), 256, G_SMEM_BYTES>>>(po);
}

// round 10
// speedup vs baseline: 1.1647x; 1.1647x over previous
#include <cuda_runtime.h>
#include <math.h>

// Problem constants
#define Bq 2
#define Sq 2048
#define DM 1024
#define Hq 16
#define DHq 64

// ---------------------------------------------------------------------------
// Scratch (__device__ globals)
// tf32 BIT PATTERNS; K/D-dim permuted within 8-groups: k -> ((k&3)<<1)|(k>>2)
// so each mma fragment pair (k, k+4) is ADJACENT -> one LDS.64, zero cvt.
// qh carries the 1/8 score scale. vh is NOT permuted (PV path wants raw rows).
// ---------------------------------------------------------------------------
__device__ unsigned g_qh [(size_t)Bq * Hq * Sq * DHq];   // [B,H,S,DH] tf32, d-perm, x0.125
__device__ unsigned g_kh [(size_t)Bq * Hq * Sq * DHq];   // [B,H,S,DH] tf32, d-perm
__device__ unsigned g_vh [(size_t)Bq * Hq * Sq * DHq];   // [B,H,S,DH] tf32, no perm
__device__ unsigned g_ctx[(size_t)Bq * Sq * DM];          // [B,S,DM]   tf32, d-perm
__device__ unsigned g_xq[(size_t)Bq * Sq * DM];           // inputs, tf32, k-perm
__device__ unsigned g_xk[(size_t)Bq * Sq * DM];
__device__ unsigned g_xv[(size_t)Bq * Sq * DM];
__device__ unsigned g_wq[(size_t)DM * DM];                // weights, tf32, k-perm
__device__ unsigned g_wk[(size_t)DM * DM];
__device__ unsigned g_wv[(size_t)DM * DM];
__device__ unsigned g_wo[(size_t)DM * DM];

// ---------------------------------------------------------------------------
// Helpers
// ---------------------------------------------------------------------------
__device__ __forceinline__ unsigned f2tf32(float f) {
    unsigned r; asm("cvt.rna.tf32.f32 %0, %1;" : "=r"(r) : "f"(f)); return r;
}
__device__ __forceinline__ int perm8(int r) { return ((r & 3) << 1) | (r >> 2); }
__device__ __forceinline__ void cpa16(void* dst, const void* src) {
    unsigned d = (unsigned)__cvta_generic_to_shared(dst);
    asm volatile("cp.async.cg.shared.global [%0], [%1], 16;" :: "r"(d), "l"(src));
}
__device__ __forceinline__ void cp_commit() { asm volatile("cp.async.commit_group;"); }
__device__ __forceinline__ void cp_wait1()  { asm volatile("cp.async.wait_group 1;"); }

__device__ __forceinline__ void mma8(float* c, unsigned a0, unsigned a1, unsigned a2,
                                     unsigned a3, unsigned b0, unsigned b1) {
    asm volatile(
        "mma.sync.aligned.m16n8k8.row.col.f32.tf32.tf32.f32 "
        "{%0,%1,%2,%3}, {%4,%5,%6,%7}, {%8,%9}, {%0,%1,%2,%3};"
        : "+f"(c[0]), "+f"(c[1]), "+f"(c[2]), "+f"(c[3])
        : "r"(a0), "r"(a1), "r"(a2), "r"(a3), "r"(b0), "r"(b1));
}

// ---------------------------------------------------------------------------
// Prep: fp32 -> tf32 bits, K-dim permuted within 8-groups.
// z: 0..3 weights (DM*DM), 4..6 inputs (B*S*DM).
// ---------------------------------------------------------------------------
struct PrepP { const float* in[7]; unsigned* out[7]; };

__global__ __launch_bounds__(256)
void prep_cvt(PrepP pp)
{
    int z = blockIdx.y;
    int n = (z < 4) ? (DM * DM) : (Bq * Sq * DM);
    int idx4 = (blockIdx.x * 256 + threadIdx.x) * 4;
    if (idx4 >= n) return;
    const float* in = pp.in[z];
    unsigned* out = pp.out[z];
    float4 v = *(const float4*)&in[idx4];
    int base = idx4 & ~7;
    int off  = (idx4 & 7) ? 1 : 0;
    out[base + off + 0] = f2tf32(v.x);
    out[base + off + 2] = f2tf32(v.y);
    out[base + off + 4] = f2tf32(v.z);
    out[base + off + 6] = f2tf32(v.w);
}

// ---------------------------------------------------------------------------
// GEMM: Y = A @ W^T + bias. A,W pre-converted tf32 bits, K-permuted.
// Mainloop: zero cvt; paired LDS.64 frag loads; stride 40 (mod 32 == 8 ->
// conflict-free phases: banks 8r+2c all distinct).
// OUT_HEAD: head layout tf32 store (optional d-perm, per-z pscale);
// else plain fp32 Y[m*N+n].
// ---------------------------------------------------------------------------
struct GemmP {
    const unsigned *X, *X1, *X2;
    const unsigned *W, *W1, *W2;
    const float *b0_, *b1_, *b2_;
    void *Y, *Y1, *Y2;
    int M, N, K;
    int qkv;
    float ps[3];
    int nperm[3];
};

#define AS   40
#define A_WORDS 5120     // 128*40
#define G_SMEM_BYTES (4 * A_WORDS * 4)

template <bool OUT_HEAD>
__global__ __launch_bounds__(256, 2)
void gemm_tc(GemmP p)
{
    const int m0 = blockIdx.y * 128;
    const int n0 = blockIdx.x * 128;
    const int z  = blockIdx.z;
    const int tid = threadIdx.x, lane = tid & 31, warp = tid >> 5;
    const int wm = warp & 1, wn = warp >> 1;

    const unsigned *X = p.X, *W = p.W; const float* bias = p.b0_; void* Y = p.Y;
    float pscale = p.ps[0]; int nperm = p.nperm[0];
    if (p.qkv) {
        if (z == 1) { X = p.X1; W = p.W1; bias = p.b1_; Y = p.Y1; pscale = p.ps[1]; nperm = p.nperm[1]; }
        else if (z == 2) { X = p.X2; W = p.W2; bias = p.b2_; Y = p.Y2; pscale = p.ps[2]; nperm = p.nperm[2]; }
    }

    extern __shared__ unsigned smu[];
    unsigned* Abuf[2] = { smu,               smu + A_WORDS     };
    unsigned* Bbuf[2] = { smu + 2 * A_WORDS, smu + 3 * A_WORDS };

    auto loadA = [&](unsigned* As_, int k0) {
        int r0 = tid >> 3, c = (tid & 7) * 4;
#pragma unroll
        for (int it = 0; it < 4; it++) {
            int r = r0 + it * 32;
            cpa16(&As_[r * AS + c], &X[(long long)(m0 + r) * p.K + k0 + c]);
        }
    };
    auto loadB = [&](unsigned* Bs_, int k0) {
        int r0 = tid >> 3, c = (tid & 7) * 4;
#pragma unroll
        for (int it = 0; it < 4; it++) {
            int r = r0 + it * 32;
            cpa16(&Bs_[r * AS + c], &W[(long long)(n0 + r) * p.K + k0 + c]);
        }
    };

    float acc[4][4][4] = {};

    loadA(Abuf[0], 0); loadB(Bbuf[0], 0); cp_commit();
    int st = 0;
    for (int k0 = 0; k0 < p.K; k0 += 32) {
        if (k0 + 32 < p.K) { loadA(Abuf[st ^ 1], k0 + 32); loadB(Bbuf[st ^ 1], k0 + 32); }
        cp_commit();
        cp_wait1();
        __syncthreads();

        const unsigned* As_ = Abuf[st];
        const unsigned* Bs_ = Bbuf[st];
#pragma unroll
        for (int kk = 0; kk < 32; kk += 8) {
            const int kp = kk + 2 * (lane & 3);
            unsigned a[4][4];
#pragma unroll
            for (int i = 0; i < 4; i++) {
                int mr = wm * 64 + i * 16 + (lane >> 2);
                uint2 lo = *(const uint2*)&As_[mr * AS + kp];
                uint2 hi = *(const uint2*)&As_[(mr + 8) * AS + kp];
                a[i][0] = lo.x; a[i][1] = hi.x; a[i][2] = lo.y; a[i][3] = hi.y;
            }
            unsigned b[4][2];
#pragma unroll
            for (int j = 0; j < 4; j++) {
                int nr = wn * 32 + j * 8 + (lane >> 2);
                uint2 bb = *(const uint2*)&Bs_[nr * AS + kp];
                b[j][0] = bb.x; b[j][1] = bb.y;
            }
#pragma unroll
            for (int i = 0; i < 4; i++)
#pragma unroll
                for (int j = 0; j < 4; j++)
                    mma8(acc[i][j], a[i][0], a[i][1], a[i][2], a[i][3], b[j][0], b[j][1]);
        }
        __syncthreads();
        st ^= 1;
    }

#pragma unroll
    for (int i = 0; i < 4; i++)
#pragma unroll
        for (int j = 0; j < 4; j++)
#pragma unroll
            for (int h = 0; h < 2; h++) {
                int m = m0 + wm * 64 + i * 16 + (lane >> 2) + h * 8;
                int n = n0 + wn * 32 + j * 8 + (lane & 3) * 2;
                float v0 = acc[i][j][h * 2]     + (bias ? bias[n]     : 0.f);
                float v1 = acc[i][j][h * 2 + 1] + (bias ? bias[n + 1] : 0.f);
                if (OUT_HEAD) {
                    int b_ = m >> 11;
                    int s  = m & (Sq - 1);
                    int hh = n >> 6;
                    int d  = n & (DHq - 1);
                    long long rowb = (((long long)b_ * Hq + hh) * Sq + s) * DHq;
                    unsigned u0 = f2tf32(v0 * pscale);
                    unsigned u1 = f2tf32(v1 * pscale);
                    unsigned* Yu = (unsigned*)Y;
                    if (nperm) {
                        int r0 = d & 7;
                        Yu[rowb + (d & ~7) + perm8(r0)]     = u0;
                        Yu[rowb + (d & ~7) + perm8(r0 + 1)] = u1;
                    } else {
                        *(uint2*)&Yu[rowb + d] = make_uint2(u0, u1);
                    }
                } else {
                    long long idx = (long long)m * p.N + n;
                    *(float2*)((float*)Y + idx) = make_float2(v0, v1);
                }
            }
}

// ---------------------------------------------------------------------------
// Fused flash attention. 256 threads, 8 warps x 16 rows.
// Q/K tf32 d-permuted -> paired LDS.64 S-phase loads (stride 72: conflict-free).
// V tf32 unpermuted (stride 72, scalar loads as in round 8).
// ctx epilogue -> tf32 d-permuted (raw A-path for out-proj). qt reversed.
// ---------------------------------------------------------------------------
#define KST 72
#define QS_OFF 0
#define KS_OFF 9216              // Qs: 128*72
#define VS_OFF (9216 + 2*9216)   // Ks: 2 x 128*72
#define F_SMEM_WORDS (9216 * 5)
#define F_SMEM_BYTES (F_SMEM_WORDS * 4)

__global__ __launch_bounds__(256, 1)
void attn_flash(const unsigned* __restrict__ qh, const unsigned* __restrict__ kh,
                const unsigned* __restrict__ vh, unsigned* __restrict__ ctx,
                float* __restrict__ attn, int write_attn)
{
    const int qt = (int)gridDim.x - 1 - (int)blockIdx.x;
    const int z  = blockIdx.y;
    const int tid = threadIdx.x, lane = tid & 31, warp = tid >> 5;

    extern __shared__ unsigned smu[];
    unsigned* Qs = smu + QS_OFF;
    unsigned* Ksb[2] = { smu + KS_OFF, smu + KS_OFF + 9216 };
    unsigned* Vsb[2] = { smu + VS_OFF, smu + VS_OFF + 9216 };

    const unsigned* Qg = qh + ((long long)z * Sq + qt * 128) * DHq;
    const unsigned* Kg = kh + (long long)z * Sq * DHq;
    const unsigned* Vg = vh + (long long)z * Sq * DHq;

    for (int i = tid; i < 128 * 16; i += 256) {
        int r = i >> 4, c4 = (i & 15) * 4;
        *(uint4*)&Qs[r * KST + c4] = *(const uint4*)&Qg[r * 64 + c4];
    }

    auto loadK = [&](int kt, int buf) {
        for (int i = tid; i < 128 * 16; i += 256) {
            int r = i >> 4, c4 = (i & 15) * 4;
            cpa16(&Ksb[buf][r * KST + c4], &Kg[((long long)kt * 128 + r) * 64 + c4]);
        }
    };
    auto loadV = [&](int kt, int buf) {
        for (int i = tid; i < 128 * 16; i += 256) {
            int r = i >> 4, c4 = (i & 15) * 4;
            cpa16(&Vsb[buf][r * KST + c4], &Vg[((long long)kt * 128 + r) * 64 + c4]);
        }
    };

    const unsigned* Qw = &Qs[(warp * 16) * KST];
    const int rq = lane >> 2;
    const int q4 = lane & 3;
    const int rbase = qt * 128 + warp * 16 + rq;

    float cacc[8][4] = {};
    float l0 = 0.f, l1 = 0.f;
    float p[16][4];

    loadK(0, 0); loadV(0, 0); cp_commit();

    for (int kt = 0; kt <= qt; kt++) {
        int buf = kt & 1;
        __syncthreads();
        if (kt < qt) { loadK(kt + 1, buf ^ 1); loadV(kt + 1, buf ^ 1); }
        cp_commit();
        cp_wait1();
        __syncthreads();

        const unsigned* Kb = Ksb[buf];
        const unsigned* Vb = Vsb[buf];

        // ---- S = Q @ K^T : paired LDS.64, zero cvt ----
#pragma unroll
        for (int j = 0; j < 16; j++) { p[j][0] = p[j][1] = p[j][2] = p[j][3] = 0.f; }
#pragma unroll
        for (int ks = 0; ks < 8; ks++) {
            const int kp = ks * 8 + 2 * q4;
            uint2 qlo = *(const uint2*)&Qw[rq * KST + kp];
            uint2 qhi = *(const uint2*)&Qw[(rq + 8) * KST + kp];
#pragma unroll
            for (int j = 0; j < 16; j++) {
                int n = j * 8 + rq;
                uint2 kb = *(const uint2*)&Kb[n * KST + kp];
                mma8(p[j], qlo.x, qhi.x, qlo.y, qhi.y, kb.x, kb.y);
            }
        }

        // ---- mask + exp + row-sum ----
        bool diag = (kt == qt);
#pragma unroll
        for (int j = 0; j < 16; j++) {
            int c0 = kt * 128 + j * 8 + 2 * q4;
            float e0 = (!diag || c0     <= rbase    ) ? __expf(p[j][0]) : 0.f;
            float e1 = (!diag || c0 + 1 <= rbase    ) ? __expf(p[j][1]) : 0.f;
            float e2 = (!diag || c0     <= rbase + 8) ? __expf(p[j][2]) : 0.f;
            float e3 = (!diag || c0 + 1 <= rbase + 8) ? __expf(p[j][3]) : 0.f;
            p[j][0] = e0; p[j][1] = e1; p[j][2] = e2; p[j][3] = e3;
            l0 += e0 + e1; l1 += e2 + e3;
        }

        // ---- ctx += P @ V (quad shuffles for A-frags; V scalar tf32) ----
        int hlo = (lane & ~3) | (q4 >> 1);
        int hhi = hlo | 2;
        bool odd = lane & 1;
#pragma unroll
        for (int t = 0; t < 16; t++) {
            float v00 = __shfl_sync(0xffffffffu, p[t][0], hlo);
            float v01 = __shfl_sync(0xffffffffu, p[t][1], hlo);
            float v20 = __shfl_sync(0xffffffffu, p[t][2], hlo);
            float v21 = __shfl_sync(0xffffffffu, p[t][3], hlo);
            float w00 = __shfl_sync(0xffffffffu, p[t][0], hhi);
            float w01 = __shfl_sync(0xffffffffu, p[t][1], hhi);
            float w20 = __shfl_sync(0xffffffffu, p[t][2], hhi);
            float w21 = __shfl_sync(0xffffffffu, p[t][3], hhi);
            unsigned a0 = f2tf32(odd ? v01 : v00);
            unsigned a1 = f2tf32(odd ? v21 : v20);
            unsigned a2 = f2tf32(odd ? w01 : w00);
            unsigned a3 = f2tf32(odd ? w21 : w20);
            int kr = t * 8 + q4;
#pragma unroll
            for (int j = 0; j < 8; j++) {
                int n = j * 8 + rq;
                mma8(cacc[j], a0, a1, a2, a3, Vb[kr * KST + n], Vb[(kr + 4) * KST + n]);
            }
        }
    }

    l0 += __shfl_xor_sync(0xffffffffu, l0, 1);
    l0 += __shfl_xor_sync(0xffffffffu, l0, 2);
    l1 += __shfl_xor_sync(0xffffffffu, l1, 1);
    l1 += __shfl_xor_sync(0xffffffffu, l1, 2);
    float inv0 = 1.0f / l0, inv1 = 1.0f / l1;

    // ---- ctx epilogue -> tf32 bits, d-permuted ----
    {
        int b_ = z >> 4, h_ = z & 15;
        long long base0 = ((long long)b_ * Sq + rbase) * DM + h_ * 64;
        long long base1 = base0 + 8LL * DM;
        int r0 = 2 * q4;
        int p0 = perm8(r0), p1 = perm8(r0 + 1);
#pragma unroll
        for (int j = 0; j < 8; j++) {
            int g = j * 8;
            ctx[base0 + g + p0] = f2tf32(cacc[j][0] * inv0);
            ctx[base0 + g + p1] = f2tf32(cacc[j][1] * inv0);
            ctx[base1 + g + p0] = f2tf32(cacc[j][2] * inv1);
            ctx[base1 + g + p1] = f2tf32(cacc[j][3] * inv1);
        }
    }

    // ---- Pass B: recompute S (paired loads), write normalized attn ----
    if (write_attn) {
        float* A = attn + (long long)z * Sq * Sq;
        __syncthreads();
        loadK(0, 0); cp_commit();
        for (int kt = 0; kt <= qt; kt++) {
            int buf = kt & 1;
            __syncthreads();
            if (kt < qt) loadK(kt + 1, buf ^ 1);
            cp_commit();
            cp_wait1();
            __syncthreads();

            const unsigned* Kb = Ksb[buf];
#pragma unroll
            for (int j = 0; j < 16; j++) { p[j][0] = p[j][1] = p[j][2] = p[j][3] = 0.f; }
#pragma unroll
            for (int ks = 0; ks < 8; ks++) {
                const int kp = ks * 8 + 2 * q4;
                uint2 qlo = *(const uint2*)&Qw[rq * KST + kp];
                uint2 qhi = *(const uint2*)&Qw[(rq + 8) * KST + kp];
#pragma unroll
                for (int j = 0; j < 16; j++) {
                    int n = j * 8 + rq;
                    uint2 kb = *(const uint2*)&Kb[n * KST + kp];
                    mma8(p[j], qlo.x, qhi.x, qlo.y, qhi.y, kb.x, kb.y);
                }
            }
            bool diag = (kt == qt);
            long long row0 = (long long)rbase * Sq;
            long long row1 = (long long)(rbase + 8) * Sq;
#pragma unroll
            for (int j = 0; j < 16; j++) {
                int c0 = kt * 128 + j * 8 + 2 * q4;
                float e0 = (!diag || c0     <= rbase    ) ? __expf(p[j][0]) * inv0 : 0.f;
                float e1 = (!diag || c0 + 1 <= rbase    ) ? __expf(p[j][1]) * inv0 : 0.f;
                float e2 = (!diag || c0     <= rbase + 8) ? __expf(p[j][2]) * inv1 : 0.f;
                float e3 = (!diag || c0 + 1 <= rbase + 8) ? __expf(p[j][3]) * inv1 : 0.f;
                *(float2*)&A[row0 + c0] = make_float2(e0, e1);
                *(float2*)&A[row1 + c0] = make_float2(e2, e3);
            }
        }
        int cEnd = (qt + 1) * 128;
        int nz4 = (Sq - cEnd) >> 2;
        if (nz4 > 0) {
            float4 z4 = make_float4(0.f, 0.f, 0.f, 0.f);
            for (int i = tid; i < 128 * nz4; i += 256) {
                int r = i / nz4, c = (i - r * nz4) * 4;
                *(float4*)&A[(long long)(qt * 128 + r) * Sq + cEnd + c] = z4;
            }
        }
    }
}

// ---------------------------------------------------------------------------
// kernel_launch
// ---------------------------------------------------------------------------
extern "C" void kernel_launch(void* const* d_in, const int* in_sizes, int n_in,
                              void* d_out, int out_size)
{
    const float* q  = (const float*)d_in[0];
    const float* k  = (const float*)d_in[1];
    const float* v  = (const float*)d_in[2];
    // d_in[3] = causal tril mask (handled analytically)
    const float* wq = (const float*)d_in[4];
    const float* bq = (const float*)d_in[5];
    const float* wk = (const float*)d_in[6];
    const float* bk = (const float*)d_in[7];
    const float* wv = (const float*)d_in[8];
    const float* bv = (const float*)d_in[9];
    const float* wo = (const float*)d_in[10];
    const float* bo = (const float*)d_in[11];
    float* out = (float*)d_out;

    unsigned *qh, *kh, *vh, *ctx, *xq, *xk, *xv, *pwq, *pwk, *pwv, *pwo;
    cudaGetSymbolAddress((void**)&qh,  g_qh);
    cudaGetSymbolAddress((void**)&kh,  g_kh);
    cudaGetSymbolAddress((void**)&vh,  g_vh);
    cudaGetSymbolAddress((void**)&ctx, g_ctx);
    cudaGetSymbolAddress((void**)&xq,  g_xq);
    cudaGetSymbolAddress((void**)&xk,  g_xk);
    cudaGetSymbolAddress((void**)&xv,  g_xv);
    cudaGetSymbolAddress((void**)&pwq, g_wq);
    cudaGetSymbolAddress((void**)&pwk, g_wk);
    cudaGetSymbolAddress((void**)&pwv, g_wv);
    cudaGetSymbolAddress((void**)&pwo, g_wo);

    const long long OUT_E  = (long long)Bq * Sq * DM;
    const long long ATTN_E = (long long)Bq * Hq * Sq * Sq;
    int write_attn = ((long long)out_size >= OUT_E + ATTN_E) ? 1 : 0;
    float* attn = out + OUT_E;

    static int attr_done = 0;
    if (!attr_done) {
        cudaFuncSetAttribute(gemm_tc<true>,
                             cudaFuncAttributeMaxDynamicSharedMemorySize, G_SMEM_BYTES);
        cudaFuncSetAttribute(gemm_tc<false>,
                             cudaFuncAttributeMaxDynamicSharedMemorySize, G_SMEM_BYTES);
        cudaFuncSetAttribute(attn_flash,
                             cudaFuncAttributeMaxDynamicSharedMemorySize, F_SMEM_BYTES);
        attr_done = 1;
    }

    // 0: prep — weights + inputs -> tf32 bits, K-permuted
    PrepP pp;
    pp.in[0] = wq; pp.out[0] = pwq;
    pp.in[1] = wk; pp.out[1] = pwk;
    pp.in[2] = wv; pp.out[2] = pwv;
    pp.in[3] = wo; pp.out[3] = pwo;
    pp.in[4] = q;  pp.out[4] = xq;
    pp.in[5] = k;  pp.out[5] = xk;
    pp.in[6] = v;  pp.out[6] = xv;
    prep_cvt<<<dim3((Bq * Sq * DM) / (256 * 4), 7), 256>>>(pp);

    // 1: fused QKV projections (zero-cvt mainloop; q/k outputs d-permuted)
    GemmP pq = {};
    pq.X  = xq; pq.W  = pwq; pq.b0_ = bq; pq.Y  = qh;
    pq.X1 = xk; pq.W1 = pwk; pq.b1_ = bk; pq.Y1 = kh;
    pq.X2 = xv; pq.W2 = pwv; pq.b2_ = bv; pq.Y2 = vh;
    pq.M = Bq * Sq; pq.N = DM; pq.K = DM; pq.qkv = 1;
    pq.ps[0] = 0.125f; pq.ps[1] = 1.f; pq.ps[2] = 1.f;
    pq.nperm[0] = 1; pq.nperm[1] = 1; pq.nperm[2] = 0;
    gemm_tc<true><<<dim3(DM / 128, (Bq * Sq) / 128, 3), 256, G_SMEM_BYTES>>>(pq);

    // 2: fused flash attention (+ attn output); ctx -> tf32 d-permuted
    attn_flash<<<dim3(Sq / 128, Bq * Hq, 1), 256, F_SMEM_BYTES>>>(
        qh, kh, vh, ctx, attn, write_attn);

    // 3: out = ctx @ wo^T + bo (zero-cvt mainloop, fp32 output)
    GemmP po = {};
    po.X = ctx; po.W = pwo; po.b0_ = bo; po.Y = out;
    po.M = Bq * Sq; po.N = DM; po.K = DM; po.qkv = 0;
    po.ps[0] = 1.f; po.nperm[0] = 0;
    gemm_tc<false><<<dim3(DM / 128, (Bq * Sq) / 128, 1), 256, G_SMEM_BYTES>>>(po);
}

// round 11
// speedup vs baseline: 1.2131x; 1.0416x over previous
#include <cuda_runtime.h>
#include <math.h>

// Problem constants
#define Bq 2
#define Sq 2048
#define DM 1024
#define Hq 16
#define DHq 64

// ---------------------------------------------------------------------------
// Scratch (__device__ globals)
// tf32 BIT PATTERNS; K/D-dim permuted within 8-groups: k -> ((k&3)<<1)|(k>>2)
// qh carries the 1/8 score scale.
// vh is TRANSPOSED per 128-row tile: [z][kt][d][128], rows perm8'd.
// ---------------------------------------------------------------------------
__device__ unsigned g_qh [(size_t)Bq * Hq * Sq * DHq];   // [B,H,S,DH] tf32, d-perm, x0.125
__device__ unsigned g_kh [(size_t)Bq * Hq * Sq * DHq];   // [B,H,S,DH] tf32, d-perm
__device__ unsigned g_vh [(size_t)Bq * Hq * Sq * DHq];   // [z][16][64][128] tf32, r-perm
__device__ unsigned g_ctx[(size_t)Bq * Sq * DM];          // [B,S,DM]   tf32, d-perm
__device__ unsigned g_xq[(size_t)Bq * Sq * DM];           // inputs, tf32, k-perm
__device__ unsigned g_xk[(size_t)Bq * Sq * DM];
__device__ unsigned g_xv[(size_t)Bq * Sq * DM];
__device__ unsigned g_wq[(size_t)DM * DM];                // weights, tf32, k-perm
__device__ unsigned g_wk[(size_t)DM * DM];
__device__ unsigned g_wv[(size_t)DM * DM];
__device__ unsigned g_wo[(size_t)DM * DM];

// ---------------------------------------------------------------------------
// Helpers
// ---------------------------------------------------------------------------
__device__ __forceinline__ unsigned f2tf32(float f) {
    unsigned r; asm("cvt.rna.tf32.f32 %0, %1;" : "=r"(r) : "f"(f)); return r;
}
__device__ __forceinline__ int perm8(int r) { return ((r & 3) << 1) | (r >> 2); }
__device__ __forceinline__ void cpa16(void* dst, const void* src) {
    unsigned d = (unsigned)__cvta_generic_to_shared(dst);
    asm volatile("cp.async.cg.shared.global [%0], [%1], 16;" :: "r"(d), "l"(src));
}
__device__ __forceinline__ void cp_commit() { asm volatile("cp.async.commit_group;"); }
__device__ __forceinline__ void cp_wait1()  { asm volatile("cp.async.wait_group 1;"); }
__device__ __forceinline__ void cp_wait0()  { asm volatile("cp.async.wait_group 0;"); }

__device__ __forceinline__ void mma8(float* c, unsigned a0, unsigned a1, unsigned a2,
                                     unsigned a3, unsigned b0, unsigned b1) {
    asm volatile(
        "mma.sync.aligned.m16n8k8.row.col.f32.tf32.tf32.f32 "
        "{%0,%1,%2,%3}, {%4,%5,%6,%7}, {%8,%9}, {%0,%1,%2,%3};"
        : "+f"(c[0]), "+f"(c[1]), "+f"(c[2]), "+f"(c[3])
        : "r"(a0), "r"(a1), "r"(a2), "r"(a3), "r"(b0), "r"(b1));
}

// ---------------------------------------------------------------------------
// Prep: fp32 -> tf32 bits, K-dim permuted within 8-groups.
// ---------------------------------------------------------------------------
struct PrepP { const float* in[7]; unsigned* out[7]; };

__global__ __launch_bounds__(256)
void prep_cvt(PrepP pp)
{
    int z = blockIdx.y;
    int n = (z < 4) ? (DM * DM) : (Bq * Sq * DM);
    int idx4 = (blockIdx.x * 256 + threadIdx.x) * 4;
    if (idx4 >= n) return;
    const float* in = pp.in[z];
    unsigned* out = pp.out[z];
    float4 v = *(const float4*)&in[idx4];
    int base = idx4 & ~7;
    int off  = (idx4 & 7) ? 1 : 0;
    out[base + off + 0] = f2tf32(v.x);
    out[base + off + 2] = f2tf32(v.y);
    out[base + off + 4] = f2tf32(v.z);
    out[base + off + 6] = f2tf32(v.w);
}

// ---------------------------------------------------------------------------
// GEMM: Y = A @ W^T + bias. A,W tf32 bits, K-permuted. Stride 40 smem
// (conflict-free paired LDS.64). OUT_HEAD variants per nperm:
//  0: head layout, uint2 tf32 store
//  1: head layout, d-perm scatter (q/k)
//  2: V transposed tile layout [z][kt][d][128] r-perm
// ---------------------------------------------------------------------------
struct GemmP {
    const unsigned *X, *X1, *X2;
    const unsigned *W, *W1, *W2;
    const float *b0_, *b1_, *b2_;
    void *Y, *Y1, *Y2;
    int M, N, K;
    int qkv;
    float ps[3];
    int nperm[3];
};

#define AS   40
#define A_WORDS 5120     // 128*40
#define G_SMEM_BYTES (4 * A_WORDS * 4)

template <bool OUT_HEAD>
__global__ __launch_bounds__(256, 2)
void gemm_tc(GemmP p)
{
    const int m0 = blockIdx.y * 128;
    const int n0 = blockIdx.x * 128;
    const int z  = blockIdx.z;
    const int tid = threadIdx.x, lane = tid & 31, warp = tid >> 5;
    const int wm = warp & 1, wn = warp >> 1;

    const unsigned *X = p.X, *W = p.W; const float* bias = p.b0_; void* Y = p.Y;
    float pscale = p.ps[0]; int nperm = p.nperm[0];
    if (p.qkv) {
        if (z == 1) { X = p.X1; W = p.W1; bias = p.b1_; Y = p.Y1; pscale = p.ps[1]; nperm = p.nperm[1]; }
        else if (z == 2) { X = p.X2; W = p.W2; bias = p.b2_; Y = p.Y2; pscale = p.ps[2]; nperm = p.nperm[2]; }
    }

    extern __shared__ unsigned smu[];
    unsigned* Abuf[2] = { smu,               smu + A_WORDS     };
    unsigned* Bbuf[2] = { smu + 2 * A_WORDS, smu + 3 * A_WORDS };

    auto loadA = [&](unsigned* As_, int k0) {
        int r0 = tid >> 3, c = (tid & 7) * 4;
#pragma unroll
        for (int it = 0; it < 4; it++) {
            int r = r0 + it * 32;
            cpa16(&As_[r * AS + c], &X[(long long)(m0 + r) * p.K + k0 + c]);
        }
    };
    auto loadB = [&](unsigned* Bs_, int k0) {
        int r0 = tid >> 3, c = (tid & 7) * 4;
#pragma unroll
        for (int it = 0; it < 4; it++) {
            int r = r0 + it * 32;
            cpa16(&Bs_[r * AS + c], &W[(long long)(n0 + r) * p.K + k0 + c]);
        }
    };

    float acc[4][4][4] = {};

    loadA(Abuf[0], 0); loadB(Bbuf[0], 0); cp_commit();
    int st = 0;
    for (int k0 = 0; k0 < p.K; k0 += 32) {
        if (k0 + 32 < p.K) { loadA(Abuf[st ^ 1], k0 + 32); loadB(Bbuf[st ^ 1], k0 + 32); }
        cp_commit();
        cp_wait1();
        __syncthreads();

        const unsigned* As_ = Abuf[st];
        const unsigned* Bs_ = Bbuf[st];
#pragma unroll
        for (int kk = 0; kk < 32; kk += 8) {
            const int kp = kk + 2 * (lane & 3);
            unsigned a[4][4];
#pragma unroll
            for (int i = 0; i < 4; i++) {
                int mr = wm * 64 + i * 16 + (lane >> 2);
                uint2 lo = *(const uint2*)&As_[mr * AS + kp];
                uint2 hi = *(const uint2*)&As_[(mr + 8) * AS + kp];
                a[i][0] = lo.x; a[i][1] = hi.x; a[i][2] = lo.y; a[i][3] = hi.y;
            }
            unsigned b[4][2];
#pragma unroll
            for (int j = 0; j < 4; j++) {
                int nr = wn * 32 + j * 8 + (lane >> 2);
                uint2 bb = *(const uint2*)&Bs_[nr * AS + kp];
                b[j][0] = bb.x; b[j][1] = bb.y;
            }
#pragma unroll
            for (int i = 0; i < 4; i++)
#pragma unroll
                for (int j = 0; j < 4; j++)
                    mma8(acc[i][j], a[i][0], a[i][1], a[i][2], a[i][3], b[j][0], b[j][1]);
        }
        __syncthreads();
        st ^= 1;
    }

#pragma unroll
    for (int i = 0; i < 4; i++)
#pragma unroll
        for (int j = 0; j < 4; j++)
#pragma unroll
            for (int h = 0; h < 2; h++) {
                int m = m0 + wm * 64 + i * 16 + (lane >> 2) + h * 8;
                int n = n0 + wn * 32 + j * 8 + (lane & 3) * 2;
                float v0 = acc[i][j][h * 2]     + (bias ? bias[n]     : 0.f);
                float v1 = acc[i][j][h * 2 + 1] + (bias ? bias[n + 1] : 0.f);
                if (OUT_HEAD) {
                    int b_ = m >> 11;
                    int s  = m & (Sq - 1);
                    int hh = n >> 6;
                    int d  = n & (DHq - 1);
                    unsigned u0 = f2tf32(v0 * pscale);
                    unsigned u1 = f2tf32(v1 * pscale);
                    unsigned* Yu = (unsigned*)Y;
                    int zz = b_ * Hq + hh;
                    if (nperm == 2) {
                        // V transposed tile layout: [z][s>>7][d][128], row perm8
                        long long a0 = (((long long)zz * 16 + (s >> 7)) * 64 + d) * 128
                                       + ((s & 127) & ~7) + perm8(s & 7);
                        Yu[a0]       = u0;
                        Yu[a0 + 128] = u1;   // d+1
                    } else {
                        long long rowb = ((long long)zz * Sq + s) * DHq;
                        if (nperm == 1) {
                            int r0 = d & 7;
                            Yu[rowb + (d & ~7) + perm8(r0)]     = u0;
                            Yu[rowb + (d & ~7) + perm8(r0 + 1)] = u1;
                        } else {
                            *(uint2*)&Yu[rowb + d] = make_uint2(u0, u1);
                        }
                    }
                } else {
                    long long idx = (long long)m * p.N + n;
                    *(float2*)((float*)Y + idx) = make_float2(v0, v1);
                }
            }
}

// ---------------------------------------------------------------------------
// Fused flash attention. 256 threads, 8 warps x 16 rows, 2 CTAs/SM.
// Single-buffered K/V smem (106 KB/CTA); cross-CTA load/compute overlap.
// S columns processed in two 64-col halves -> p[8][4] (persistent regs ~64).
// Q/K tf32 d-permuted (paired LDS.64, stride 72); V transposed r-perm
// (paired LDS.64, stride 136). ctx -> tf32 d-permuted. qt reversed.
// ---------------------------------------------------------------------------
#define QST 72
#define KST 72
#define VST 136
#define FQ_OFF 0
#define FK_OFF 9216
#define FV_OFF 18432
#define F_SMEM_WORDS 27136        // 9216 + 9216 + 64*136
#define F_SMEM_BYTES (F_SMEM_WORDS * 4)

__global__ __launch_bounds__(256, 2)
void attn_flash(const unsigned* __restrict__ qh, const unsigned* __restrict__ kh,
                const unsigned* __restrict__ vhT, unsigned* __restrict__ ctx,
                float* __restrict__ attn, int write_attn)
{
    const int qt = (int)gridDim.x - 1 - (int)blockIdx.x;
    const int z  = blockIdx.y;
    const int tid = threadIdx.x, lane = tid & 31, warp = tid >> 5;

    extern __shared__ unsigned smu[];
    unsigned* Qs = smu + FQ_OFF;
    unsigned* Ks = smu + FK_OFF;
    unsigned* Vs = smu + FV_OFF;

    const unsigned* Qg  = qh  + ((long long)z * Sq + qt * 128) * DHq;
    const unsigned* Kg  = kh  + (long long)z * Sq * DHq;
    const unsigned* VgT = vhT + (long long)z * Sq * DHq;   // [16][64][128]

    // Q fill (already tf32 bits, prescaled, d-perm)
    for (int i = tid; i < 128 * 16; i += 256) {
        int r = i >> 4, c4 = (i & 15) * 4;
        *(uint4*)&Qs[r * QST + c4] = *(const uint4*)&Qg[r * 64 + c4];
    }

    auto loadK = [&](int kt) {
        for (int i = tid; i < 128 * 16; i += 256) {
            int r = i >> 4, c4 = (i & 15) * 4;
            cpa16(&Ks[r * KST + c4], &Kg[((long long)kt * 128 + r) * 64 + c4]);
        }
    };
    auto loadV = [&](int kt) {
        for (int i = tid; i < 64 * 32; i += 256) {
            int d = i >> 5, c4 = (i & 31) * 4;
            cpa16(&Vs[d * VST + c4], &VgT[(long long)kt * 8192 + d * 128 + c4]);
        }
    };

    const unsigned* Qw = &Qs[(warp * 16) * QST];
    const int rq = lane >> 2;
    const int q4 = lane & 3;
    const int rbase = qt * 128 + warp * 16 + rq;
    const int hlo = (lane & ~3) | (q4 >> 1);
    const int hhi = hlo | 2;
    const bool odd = lane & 1;

    float cacc[8][4] = {};
    float l0 = 0.f, l1 = 0.f;
    float p[8][4];

    for (int kt = 0; kt <= qt; kt++) {
        __syncthreads();                 // prev compute done (also covers Q fill)
        loadK(kt); loadV(kt);
        cp_commit();
        cp_wait0();
        __syncthreads();

#pragma unroll
        for (int half = 0; half < 2; half++) {
            // ---- S half: 64 columns ----
#pragma unroll
            for (int j = 0; j < 8; j++) { p[j][0] = p[j][1] = p[j][2] = p[j][3] = 0.f; }
#pragma unroll
            for (int ks = 0; ks < 8; ks++) {
                const int kp = ks * 8 + 2 * q4;
                uint2 qlo = *(const uint2*)&Qw[rq * QST + kp];
                uint2 qhi = *(const uint2*)&Qw[(rq + 8) * QST + kp];
#pragma unroll
                for (int j = 0; j < 8; j++) {
                    int n = (half * 8 + j) * 8 + rq;
                    uint2 kb = *(const uint2*)&Ks[n * KST + kp];
                    mma8(p[j], qlo.x, qhi.x, qlo.y, qhi.y, kb.x, kb.y);
                }
            }

            // ---- mask + exp + row-sum ----
            bool diag = (kt == qt);
#pragma unroll
            for (int j = 0; j < 8; j++) {
                int c0 = kt * 128 + (half * 8 + j) * 8 + 2 * q4;
                float e0 = (!diag || c0     <= rbase    ) ? __expf(p[j][0]) : 0.f;
                float e1 = (!diag || c0 + 1 <= rbase    ) ? __expf(p[j][1]) : 0.f;
                float e2 = (!diag || c0     <= rbase + 8) ? __expf(p[j][2]) : 0.f;
                float e3 = (!diag || c0 + 1 <= rbase + 8) ? __expf(p[j][3]) : 0.f;
                p[j][0] = e0; p[j][1] = e1; p[j][2] = e2; p[j][3] = e3;
                l0 += e0 + e1; l1 += e2 + e3;
            }

            // ---- ctx += P_half @ V_half (paired LDS.64 on transposed V) ----
#pragma unroll
            for (int t = 0; t < 8; t++) {
                float v00 = __shfl_sync(0xffffffffu, p[t][0], hlo);
                float v01 = __shfl_sync(0xffffffffu, p[t][1], hlo);
                float v20 = __shfl_sync(0xffffffffu, p[t][2], hlo);
                float v21 = __shfl_sync(0xffffffffu, p[t][3], hlo);
                float w00 = __shfl_sync(0xffffffffu, p[t][0], hhi);
                float w01 = __shfl_sync(0xffffffffu, p[t][1], hhi);
                float w20 = __shfl_sync(0xffffffffu, p[t][2], hhi);
                float w21 = __shfl_sync(0xffffffffu, p[t][3], hhi);
                unsigned a0 = f2tf32(odd ? v01 : v00);
                unsigned a1 = f2tf32(odd ? v21 : v20);
                unsigned a2 = f2tf32(odd ? w01 : w00);
                unsigned a3 = f2tf32(odd ? w21 : w20);
                int krp = (half * 8 + t) * 8 + 2 * q4;
#pragma unroll
                for (int j = 0; j < 8; j++) {
                    int n = j * 8 + rq;
                    uint2 vb = *(const uint2*)&Vs[n * VST + krp];
                    mma8(cacc[j], a0, a1, a2, a3, vb.x, vb.y);
                }
            }
        }
    }

    l0 += __shfl_xor_sync(0xffffffffu, l0, 1);
    l0 += __shfl_xor_sync(0xffffffffu, l0, 2);
    l1 += __shfl_xor_sync(0xffffffffu, l1, 1);
    l1 += __shfl_xor_sync(0xffffffffu, l1, 2);
    float inv0 = 1.0f / l0, inv1 = 1.0f / l1;

    // ---- ctx epilogue -> tf32 bits, d-permuted ----
    {
        int b_ = z >> 4, h_ = z & 15;
        long long base0 = ((long long)b_ * Sq + rbase) * DM + h_ * 64;
        long long base1 = base0 + 8LL * DM;
        int r0 = 2 * q4;
        int p0 = perm8(r0), p1 = perm8(r0 + 1);
#pragma unroll
        for (int j = 0; j < 8; j++) {
            int g = j * 8;
            ctx[base0 + g + p0] = f2tf32(cacc[j][0] * inv0);
            ctx[base0 + g + p1] = f2tf32(cacc[j][1] * inv0);
            ctx[base1 + g + p0] = f2tf32(cacc[j][2] * inv1);
            ctx[base1 + g + p1] = f2tf32(cacc[j][3] * inv1);
        }
    }

    // ---- Pass B: recompute S, write normalized attn ----
    if (write_attn) {
        float* A = attn + (long long)z * Sq * Sq;
        for (int kt = 0; kt <= qt; kt++) {
            __syncthreads();
            loadK(kt);
            cp_commit();
            cp_wait0();
            __syncthreads();

            bool diag = (kt == qt);
            long long row0 = (long long)rbase * Sq;
            long long row1 = (long long)(rbase + 8) * Sq;
#pragma unroll
            for (int half = 0; half < 2; half++) {
#pragma unroll
                for (int j = 0; j < 8; j++) { p[j][0] = p[j][1] = p[j][2] = p[j][3] = 0.f; }
#pragma unroll
                for (int ks = 0; ks < 8; ks++) {
                    const int kp = ks * 8 + 2 * q4;
                    uint2 qlo = *(const uint2*)&Qw[rq * QST + kp];
                    uint2 qhi = *(const uint2*)&Qw[(rq + 8) * QST + kp];
#pragma unroll
                    for (int j = 0; j < 8; j++) {
                        int n = (half * 8 + j) * 8 + rq;
                        uint2 kb = *(const uint2*)&Ks[n * KST + kp];
                        mma8(p[j], qlo.x, qhi.x, qlo.y, qhi.y, kb.x, kb.y);
                    }
                }
#pragma unroll
                for (int j = 0; j < 8; j++) {
                    int c0 = kt * 128 + (half * 8 + j) * 8 + 2 * q4;
                    float e0 = (!diag || c0     <= rbase    ) ? __expf(p[j][0]) * inv0 : 0.f;
                    float e1 = (!diag || c0 + 1 <= rbase    ) ? __expf(p[j][1]) * inv0 : 0.f;
                    float e2 = (!diag || c0     <= rbase + 8) ? __expf(p[j][2]) * inv1 : 0.f;
                    float e3 = (!diag || c0 + 1 <= rbase + 8) ? __expf(p[j][3]) * inv1 : 0.f;
                    *(float2*)&A[row0 + c0] = make_float2(e0, e1);
                    *(float2*)&A[row1 + c0] = make_float2(e2, e3);
                }
            }
        }
        int cEnd = (qt + 1) * 128;
        int nz4 = (Sq - cEnd) >> 2;
        if (nz4 > 0) {
            float4 z4 = make_float4(0.f, 0.f, 0.f, 0.f);
            for (int i = tid; i < 128 * nz4; i += 256) {
                int r = i / nz4, c = (i - r * nz4) * 4;
                *(float4*)&A[(long long)(qt * 128 + r) * Sq + cEnd + c] = z4;
            }
        }
    }
}

// ---------------------------------------------------------------------------
// kernel_launch
// ---------------------------------------------------------------------------
extern "C" void kernel_launch(void* const* d_in, const int* in_sizes, int n_in,
                              void* d_out, int out_size)
{
    const float* q  = (const float*)d_in[0];
    const float* k  = (const float*)d_in[1];
    const float* v  = (const float*)d_in[2];
    // d_in[3] = causal tril mask (handled analytically)
    const float* wq = (const float*)d_in[4];
    const float* bq = (const float*)d_in[5];
    const float* wk = (const float*)d_in[6];
    const float* bk = (const float*)d_in[7];
    const float* wv = (const float*)d_in[8];
    const float* bv = (const float*)d_in[9];
    const float* wo = (const float*)d_in[10];
    const float* bo = (const float*)d_in[11];
    float* out = (float*)d_out;

    unsigned *qh, *kh, *vh, *ctx, *xq, *xk, *xv, *pwq, *pwk, *pwv, *pwo;
    cudaGetSymbolAddress((void**)&qh,  g_qh);
    cudaGetSymbolAddress((void**)&kh,  g_kh);
    cudaGetSymbolAddress((void**)&vh,  g_vh);
    cudaGetSymbolAddress((void**)&ctx, g_ctx);
    cudaGetSymbolAddress((void**)&xq,  g_xq);
    cudaGetSymbolAddress((void**)&xk,  g_xk);
    cudaGetSymbolAddress((void**)&xv,  g_xv);
    cudaGetSymbolAddress((void**)&pwq, g_wq);
    cudaGetSymbolAddress((void**)&pwk, g_wk);
    cudaGetSymbolAddress((void**)&pwv, g_wv);
    cudaGetSymbolAddress((void**)&pwo, g_wo);

    const long long OUT_E  = (long long)Bq * Sq * DM;
    const long long ATTN_E = (long long)Bq * Hq * Sq * Sq;
    int write_attn = ((long long)out_size >= OUT_E + ATTN_E) ? 1 : 0;
    float* attn = out + OUT_E;

    static int attr_done = 0;
    if (!attr_done) {
        cudaFuncSetAttribute(gemm_tc<true>,
                             cudaFuncAttributeMaxDynamicSharedMemorySize, G_SMEM_BYTES);
        cudaFuncSetAttribute(gemm_tc<false>,
                             cudaFuncAttributeMaxDynamicSharedMemorySize, G_SMEM_BYTES);
        cudaFuncSetAttribute(attn_flash,
                             cudaFuncAttributeMaxDynamicSharedMemorySize, F_SMEM_BYTES);
        attr_done = 1;
    }

    // 0: prep — weights + inputs -> tf32 bits, K-permuted
    PrepP pp;
    pp.in[0] = wq; pp.out[0] = pwq;
    pp.in[1] = wk; pp.out[1] = pwk;
    pp.in[2] = wv; pp.out[2] = pwv;
    pp.in[3] = wo; pp.out[3] = pwo;
    pp.in[4] = q;  pp.out[4] = xq;
    pp.in[5] = k;  pp.out[5] = xk;
    pp.in[6] = v;  pp.out[6] = xv;
    prep_cvt<<<dim3((Bq * Sq * DM) / (256 * 4), 7), 256>>>(pp);

    // 1: fused QKV projections (zero-cvt mainloop; q/k d-perm, v transposed)
    GemmP pq = {};
    pq.X  = xq; pq.W  = pwq; pq.b0_ = bq; pq.Y  = qh;
    pq.X1 = xk; pq.W1 = pwk; pq.b1_ = bk; pq.Y1 = kh;
    pq.X2 = xv; pq.W2 = pwv; pq.b2_ = bv; pq.Y2 = vh;
    pq.M = Bq * Sq; pq.N = DM; pq.K = DM; pq.qkv = 1;
    pq.ps[0] = 0.125f; pq.ps[1] = 1.f; pq.ps[2] = 1.f;
    pq.nperm[0] = 1; pq.nperm[1] = 1; pq.nperm[2] = 2;
    gemm_tc<true><<<dim3(DM / 128, (Bq * Sq) / 128, 3), 256, G_SMEM_BYTES>>>(pq);

    // 2: fused flash attention (2 CTAs/SM, single-buffered)
    attn_flash<<<dim3(Sq / 128, Bq * Hq, 1), 256, F_SMEM_BYTES>>>(
        qh, kh, vh, ctx, attn, write_attn);

    // 3: out = ctx @ wo^T + bo (zero-cvt mainloop, fp32 output)
    GemmP po = {};
    po.X = ctx; po.W = pwo; po.b0_ = bo; po.Y = out;
    po.M = Bq * Sq; po.N = DM; po.K = DM; po.qkv = 0;
    po.ps[0] = 1.f; po.nperm[0] = 0;
    gemm_tc<false><<<dim3(DM / 128, (Bq * Sq) / 128, 1), 256, G_SMEM_BYTES>>>(po);
}

// round 12
// speedup vs baseline: 1.3784x; 1.1362x over previous
#include <cuda_runtime.h>
#include <math.h>

// Problem constants
#define Bq 2
#define Sq 2048
#define DM 1024
#define Hq 16
#define DHq 64

// ---------------------------------------------------------------------------
// Scratch (__device__ globals)
// tf32 BIT PATTERNS; K/D permutation within 8-groups: k -> ((k&3)<<1)|(k>>2)
// qh carries the 1/8 score scale. vh transposed per 128-tile: [z][kt][d][128].
// ---------------------------------------------------------------------------
__device__ unsigned g_qh [(size_t)Bq * Hq * Sq * DHq];   // tf32, d-perm, x0.125
__device__ unsigned g_kh [(size_t)Bq * Hq * Sq * DHq];   // tf32, d-perm
__device__ unsigned g_vh [(size_t)Bq * Hq * Sq * DHq];   // [z][16][64][128] tf32, r-perm
__device__ unsigned g_ctx[(size_t)Bq * Sq * DM];          // tf32, d-perm
__device__ unsigned g_wq[(size_t)DM * DM];                // weights tf32, k-perm
__device__ unsigned g_wk[(size_t)DM * DM];
__device__ unsigned g_wv[(size_t)DM * DM];
__device__ unsigned g_wo[(size_t)DM * DM];

// ---------------------------------------------------------------------------
// Helpers
// ---------------------------------------------------------------------------
__device__ __forceinline__ unsigned f2tf32(float f) {
    unsigned r; asm("cvt.rna.tf32.f32 %0, %1;" : "=r"(r) : "f"(f)); return r;
}
__device__ __forceinline__ int perm8(int r) { return ((r & 3) << 1) | (r >> 2); }
__device__ __forceinline__ void cpa16(void* dst, const void* src) {
    unsigned d = (unsigned)__cvta_generic_to_shared(dst);
    asm volatile("cp.async.cg.shared.global [%0], [%1], 16;" :: "r"(d), "l"(src));
}
__device__ __forceinline__ void cp_commit() { asm volatile("cp.async.commit_group;"); }
__device__ __forceinline__ void cp_wait1()  { asm volatile("cp.async.wait_group 1;"); }
__device__ __forceinline__ void cp_wait0()  { asm volatile("cp.async.wait_group 0;"); }

__device__ __forceinline__ void mma8(float* c, unsigned a0, unsigned a1, unsigned a2,
                                     unsigned a3, unsigned b0, unsigned b1) {
    asm volatile(
        "mma.sync.aligned.m16n8k8.row.col.f32.tf32.tf32.f32 "
        "{%0,%1,%2,%3}, {%4,%5,%6,%7}, {%8,%9}, {%0,%1,%2,%3};"
        : "+f"(c[0]), "+f"(c[1]), "+f"(c[2]), "+f"(c[3])
        : "r"(a0), "r"(a1), "r"(a2), "r"(a3), "r"(b0), "r"(b1));
}

// ---------------------------------------------------------------------------
// Prep: WEIGHTS ONLY -> tf32 bits, K-dim permuted within 8-groups (~8 us).
// ---------------------------------------------------------------------------
struct PrepP { const float* in[4]; unsigned* out[4]; };

__global__ __launch_bounds__(256)
void prep_cvt(PrepP pp)
{
    int z = blockIdx.y;
    int idx4 = (blockIdx.x * 256 + threadIdx.x) * 4;
    const float* in = pp.in[z];
    unsigned* out = pp.out[z];
    float4 v = *(const float4*)&in[idx4];
    int base = idx4 & ~7;
    int off  = (idx4 & 7) ? 1 : 0;
    out[base + off + 0] = f2tf32(v.x);
    out[base + off + 2] = f2tf32(v.y);
    out[base + off + 4] = f2tf32(v.z);
    out[base + off + 6] = f2tf32(v.w);
}

// ---------------------------------------------------------------------------
// GEMM: Y = A @ W^T + bias. W always tf32 k-permuted (paired LDS.64, stride 40).
// A_F32=true: A raw fp32 (scalar LDS + cvt, stride 36, conflict-free).
// A_F32=false: A tf32 k/d-permuted (paired LDS.64, stride 40).
// OUT_HEAD epilogues per nperm: 0 plain head uint2; 1 d-perm scatter (q/k);
// 2 transposed V tile [z][kt][d][128] r-perm.
// ---------------------------------------------------------------------------
struct GemmP {
    const unsigned *X, *X1, *X2;
    const unsigned *W, *W1, *W2;
    const float *b0_, *b1_, *b2_;
    void *Y, *Y1, *Y2;
    int M, N, K;
    int qkv;
    float ps[3];
    int nperm[3];
};

#define BUF_WORDS 5120     // 128*40 (max of the two strides)
#define G_SMEM_BYTES (4 * BUF_WORDS * 4)

template <bool A_F32, bool OUT_HEAD>
__global__ __launch_bounds__(256, 2)
void gemm_tc(GemmP p)
{
    constexpr int ASA = A_F32 ? 36 : 40;   // A-tile stride
    constexpr int ASB = 40;                // B-tile stride

    const int m0 = blockIdx.y * 128;
    const int n0 = blockIdx.x * 128;
    const int z  = blockIdx.z;
    const int tid = threadIdx.x, lane = tid & 31, warp = tid >> 5;
    const int wm = warp & 1, wn = warp >> 1;

    const unsigned *X = p.X, *W = p.W; const float* bias = p.b0_; void* Y = p.Y;
    float pscale = p.ps[0]; int nperm = p.nperm[0];
    if (p.qkv) {
        if (z == 1) { X = p.X1; W = p.W1; bias = p.b1_; Y = p.Y1; pscale = p.ps[1]; nperm = p.nperm[1]; }
        else if (z == 2) { X = p.X2; W = p.W2; bias = p.b2_; Y = p.Y2; pscale = p.ps[2]; nperm = p.nperm[2]; }
    }

    extern __shared__ unsigned smu[];
    unsigned* Abuf[2] = { smu,                 smu + BUF_WORDS     };
    unsigned* Bbuf[2] = { smu + 2 * BUF_WORDS, smu + 3 * BUF_WORDS };

    auto loadA = [&](unsigned* As_, int k0) {
        int r0 = tid >> 3, c = (tid & 7) * 4;
#pragma unroll
        for (int it = 0; it < 4; it++) {
            int r = r0 + it * 32;
            cpa16(&As_[r * ASA + c], &X[(long long)(m0 + r) * p.K + k0 + c]);
        }
    };
    auto loadB = [&](unsigned* Bs_, int k0) {
        int r0 = tid >> 3, c = (tid & 7) * 4;
#pragma unroll
        for (int it = 0; it < 4; it++) {
            int r = r0 + it * 32;
            cpa16(&Bs_[r * ASB + c], &W[(long long)(n0 + r) * p.K + k0 + c]);
        }
    };

    float acc[4][4][4] = {};

    loadA(Abuf[0], 0); loadB(Bbuf[0], 0); cp_commit();
    int st = 0;
    for (int k0 = 0; k0 < p.K; k0 += 32) {
        if (k0 + 32 < p.K) { loadA(Abuf[st ^ 1], k0 + 32); loadB(Bbuf[st ^ 1], k0 + 32); }
        cp_commit();
        cp_wait1();
        __syncthreads();

        const unsigned* As_ = Abuf[st];
        const unsigned* Bs_ = Bbuf[st];
        const float* Af = (const float*)As_;
#pragma unroll
        for (int kk = 0; kk < 32; kk += 8) {
            const int kc = kk + (lane & 3);          // natural-k column (A_F32)
            const int kp = kk + 2 * (lane & 3);      // permuted pair base
            unsigned a[4][4];
#pragma unroll
            for (int i = 0; i < 4; i++) {
                int mr = wm * 64 + i * 16 + (lane >> 2);
                if (A_F32) {
                    a[i][0] = f2tf32(Af[mr * ASA + kc]);
                    a[i][1] = f2tf32(Af[(mr + 8) * ASA + kc]);
                    a[i][2] = f2tf32(Af[mr * ASA + kc + 4]);
                    a[i][3] = f2tf32(Af[(mr + 8) * ASA + kc + 4]);
                } else {
                    uint2 lo = *(const uint2*)&As_[mr * ASA + kp];
                    uint2 hi = *(const uint2*)&As_[(mr + 8) * ASA + kp];
                    a[i][0] = lo.x; a[i][1] = hi.x; a[i][2] = lo.y; a[i][3] = hi.y;
                }
            }
            unsigned b[4][2];
#pragma unroll
            for (int j = 0; j < 4; j++) {
                int nr = wn * 32 + j * 8 + (lane >> 2);
                uint2 bb = *(const uint2*)&Bs_[nr * ASB + kp];
                b[j][0] = bb.x; b[j][1] = bb.y;
            }
#pragma unroll
            for (int i = 0; i < 4; i++)
#pragma unroll
                for (int j = 0; j < 4; j++)
                    mma8(acc[i][j], a[i][0], a[i][1], a[i][2], a[i][3], b[j][0], b[j][1]);
        }
        __syncthreads();
        st ^= 1;
    }

#pragma unroll
    for (int i = 0; i < 4; i++)
#pragma unroll
        for (int j = 0; j < 4; j++)
#pragma unroll
            for (int h = 0; h < 2; h++) {
                int m = m0 + wm * 64 + i * 16 + (lane >> 2) + h * 8;
                int n = n0 + wn * 32 + j * 8 + (lane & 3) * 2;
                float v0 = acc[i][j][h * 2]     + (bias ? bias[n]     : 0.f);
                float v1 = acc[i][j][h * 2 + 1] + (bias ? bias[n + 1] : 0.f);
                if (OUT_HEAD) {
                    int b_ = m >> 11;
                    int s  = m & (Sq - 1);
                    int hh = n >> 6;
                    int d  = n & (DHq - 1);
                    unsigned u0 = f2tf32(v0 * pscale);
                    unsigned u1 = f2tf32(v1 * pscale);
                    unsigned* Yu = (unsigned*)Y;
                    int zz = b_ * Hq + hh;
                    if (nperm == 2) {
                        long long a0 = (((long long)zz * 16 + (s >> 7)) * 64 + d) * 128
                                       + ((s & 127) & ~7) + perm8(s & 7);
                        Yu[a0]       = u0;
                        Yu[a0 + 128] = u1;   // d+1
                    } else {
                        long long rowb = ((long long)zz * Sq + s) * DHq;
                        if (nperm == 1) {
                            int r0 = d & 7;
                            Yu[rowb + (d & ~7) + perm8(r0)]     = u0;
                            Yu[rowb + (d & ~7) + perm8(r0 + 1)] = u1;
                        } else {
                            *(uint2*)&Yu[rowb + d] = make_uint2(u0, u1);
                        }
                    }
                } else {
                    long long idx = (long long)m * p.N + n;
                    *(float2*)((float*)Y + idx) = make_float2(v0, v1);
                }
            }
}

// ---------------------------------------------------------------------------
// Fused flash attention. 256 threads, 8 warps x 16 rows, 2 CTAs/SM.
// Single-buffered; K and V in SEPARATE cp.async groups: S-half0 overlaps the
// V load. Q/K d-perm paired LDS.64 (stride 72); V transposed r-perm paired
// (stride 136). ctx -> tf32 d-permuted. qt reversed.
// ---------------------------------------------------------------------------
#define QST 72
#define KST 72
#define VST 136
#define FQ_OFF 0
#define FK_OFF 9216
#define FV_OFF 18432
#define F_SMEM_WORDS 27136        // 9216 + 9216 + 64*136
#define F_SMEM_BYTES (F_SMEM_WORDS * 4)

__global__ __launch_bounds__(256, 2)
void attn_flash(const unsigned* __restrict__ qh, const unsigned* __restrict__ kh,
                const unsigned* __restrict__ vhT, unsigned* __restrict__ ctx,
                float* __restrict__ attn, int write_attn)
{
    const int qt = (int)gridDim.x - 1 - (int)blockIdx.x;
    const int z  = blockIdx.y;
    const int tid = threadIdx.x, lane = tid & 31, warp = tid >> 5;

    extern __shared__ unsigned smu[];
    unsigned* Qs = smu + FQ_OFF;
    unsigned* Ks = smu + FK_OFF;
    unsigned* Vs = smu + FV_OFF;

    const unsigned* Qg  = qh  + ((long long)z * Sq + qt * 128) * DHq;
    const unsigned* Kg  = kh  + (long long)z * Sq * DHq;
    const unsigned* VgT = vhT + (long long)z * Sq * DHq;

    for (int i = tid; i < 128 * 16; i += 256) {
        int r = i >> 4, c4 = (i & 15) * 4;
        *(uint4*)&Qs[r * QST + c4] = *(const uint4*)&Qg[r * 64 + c4];
    }

    auto loadK = [&](int kt) {
        for (int i = tid; i < 128 * 16; i += 256) {
            int r = i >> 4, c4 = (i & 15) * 4;
            cpa16(&Ks[r * KST + c4], &Kg[((long long)kt * 128 + r) * 64 + c4]);
        }
    };
    auto loadV = [&](int kt) {
        for (int i = tid; i < 64 * 32; i += 256) {
            int d = i >> 5, c4 = (i & 31) * 4;
            cpa16(&Vs[d * VST + c4], &VgT[(long long)kt * 8192 + d * 128 + c4]);
        }
    };

    const unsigned* Qw = &Qs[(warp * 16) * QST];
    const int rq = lane >> 2;
    const int q4 = lane & 3;
    const int rbase = qt * 128 + warp * 16 + rq;
    const int hlo = (lane & ~3) | (q4 >> 1);
    const int hhi = hlo | 2;
    const bool odd = lane & 1;

    float cacc[8][4] = {};
    float l0 = 0.f, l1 = 0.f;
    float p[8][4];

    for (int kt = 0; kt <= qt; kt++) {
        __syncthreads();                 // prev compute done (also covers Q fill)
        loadK(kt); cp_commit();          // group: K
        loadV(kt); cp_commit();          // group: V
        cp_wait1();                      // K arrived (V may still be in flight)
        __syncthreads();

        bool diag = (kt == qt);

        // ---- S half 0 (overlaps V load) ----
#pragma unroll
        for (int j = 0; j < 8; j++) { p[j][0] = p[j][1] = p[j][2] = p[j][3] = 0.f; }
#pragma unroll
        for (int ks = 0; ks < 8; ks++) {
            const int kp = ks * 8 + 2 * q4;
            uint2 qlo = *(const uint2*)&Qw[rq * QST + kp];
            uint2 qhi = *(const uint2*)&Qw[(rq + 8) * QST + kp];
#pragma unroll
            for (int j = 0; j < 8; j++) {
                int n = j * 8 + rq;
                uint2 kb = *(const uint2*)&Ks[n * KST + kp];
                mma8(p[j], qlo.x, qhi.x, qlo.y, qhi.y, kb.x, kb.y);
            }
        }
#pragma unroll
        for (int j = 0; j < 8; j++) {
            int c0 = kt * 128 + j * 8 + 2 * q4;
            float e0 = (!diag || c0     <= rbase    ) ? __expf(p[j][0]) : 0.f;
            float e1 = (!diag || c0 + 1 <= rbase    ) ? __expf(p[j][1]) : 0.f;
            float e2 = (!diag || c0     <= rbase + 8) ? __expf(p[j][2]) : 0.f;
            float e3 = (!diag || c0 + 1 <= rbase + 8) ? __expf(p[j][3]) : 0.f;
            p[j][0] = e0; p[j][1] = e1; p[j][2] = e2; p[j][3] = e3;
            l0 += e0 + e1; l1 += e2 + e3;
        }

        cp_wait0();                      // V ready
        __syncthreads();

        // ---- PV half 0 ----
#pragma unroll
        for (int t = 0; t < 8; t++) {
            float v00 = __shfl_sync(0xffffffffu, p[t][0], hlo);
            float v01 = __shfl_sync(0xffffffffu, p[t][1], hlo);
            float v20 = __shfl_sync(0xffffffffu, p[t][2], hlo);
            float v21 = __shfl_sync(0xffffffffu, p[t][3], hlo);
            float w00 = __shfl_sync(0xffffffffu, p[t][0], hhi);
            float w01 = __shfl_sync(0xffffffffu, p[t][1], hhi);
            float w20 = __shfl_sync(0xffffffffu, p[t][2], hhi);
            float w21 = __shfl_sync(0xffffffffu, p[t][3], hhi);
            unsigned a0 = f2tf32(odd ? v01 : v00);
            unsigned a1 = f2tf32(odd ? v21 : v20);
            unsigned a2 = f2tf32(odd ? w01 : w00);
            unsigned a3 = f2tf32(odd ? w21 : w20);
            int krp = t * 8 + 2 * q4;
#pragma unroll
            for (int j = 0; j < 8; j++) {
                int n = j * 8 + rq;
                uint2 vb = *(const uint2*)&Vs[n * VST + krp];
                mma8(cacc[j], a0, a1, a2, a3, vb.x, vb.y);
            }
        }

        // ---- S half 1 + PV half 1 ----
#pragma unroll
        for (int j = 0; j < 8; j++) { p[j][0] = p[j][1] = p[j][2] = p[j][3] = 0.f; }
#pragma unroll
        for (int ks = 0; ks < 8; ks++) {
            const int kp = ks * 8 + 2 * q4;
            uint2 qlo = *(const uint2*)&Qw[rq * QST + kp];
            uint2 qhi = *(const uint2*)&Qw[(rq + 8) * QST + kp];
#pragma unroll
            for (int j = 0; j < 8; j++) {
                int n = (8 + j) * 8 + rq;
                uint2 kb = *(const uint2*)&Ks[n * KST + kp];
                mma8(p[j], qlo.x, qhi.x, qlo.y, qhi.y, kb.x, kb.y);
            }
        }
#pragma unroll
        for (int j = 0; j < 8; j++) {
            int c0 = kt * 128 + (8 + j) * 8 + 2 * q4;
            float e0 = (!diag || c0     <= rbase    ) ? __expf(p[j][0]) : 0.f;
            float e1 = (!diag || c0 + 1 <= rbase    ) ? __expf(p[j][1]) : 0.f;
            float e2 = (!diag || c0     <= rbase + 8) ? __expf(p[j][2]) : 0.f;
            float e3 = (!diag || c0 + 1 <= rbase + 8) ? __expf(p[j][3]) : 0.f;
            p[j][0] = e0; p[j][1] = e1; p[j][2] = e2; p[j][3] = e3;
            l0 += e0 + e1; l1 += e2 + e3;
        }
#pragma unroll
        for (int t = 0; t < 8; t++) {
            float v00 = __shfl_sync(0xffffffffu, p[t][0], hlo);
            float v01 = __shfl_sync(0xffffffffu, p[t][1], hlo);
            float v20 = __shfl_sync(0xffffffffu, p[t][2], hlo);
            float v21 = __shfl_sync(0xffffffffu, p[t][3], hlo);
            float w00 = __shfl_sync(0xffffffffu, p[t][0], hhi);
            float w01 = __shfl_sync(0xffffffffu, p[t][1], hhi);
            float w20 = __shfl_sync(0xffffffffu, p[t][2], hhi);
            float w21 = __shfl_sync(0xffffffffu, p[t][3], hhi);
            unsigned a0 = f2tf32(odd ? v01 : v00);
            unsigned a1 = f2tf32(odd ? v21 : v20);
            unsigned a2 = f2tf32(odd ? w01 : w00);
            unsigned a3 = f2tf32(odd ? w21 : w20);
            int krp = (8 + t) * 8 + 2 * q4;
#pragma unroll
            for (int j = 0; j < 8; j++) {
                int n = j * 8 + rq;
                uint2 vb = *(const uint2*)&Vs[n * VST + krp];
                mma8(cacc[j], a0, a1, a2, a3, vb.x, vb.y);
            }
        }
    }

    l0 += __shfl_xor_sync(0xffffffffu, l0, 1);
    l0 += __shfl_xor_sync(0xffffffffu, l0, 2);
    l1 += __shfl_xor_sync(0xffffffffu, l1, 1);
    l1 += __shfl_xor_sync(0xffffffffu, l1, 2);
    float inv0 = 1.0f / l0, inv1 = 1.0f / l1;

    // ---- ctx epilogue -> tf32 bits, d-permuted ----
    {
        int b_ = z >> 4, h_ = z & 15;
        long long base0 = ((long long)b_ * Sq + rbase) * DM + h_ * 64;
        long long base1 = base0 + 8LL * DM;
        int r0 = 2 * q4;
        int p0 = perm8(r0), p1 = perm8(r0 + 1);
#pragma unroll
        for (int j = 0; j < 8; j++) {
            int g = j * 8;
            ctx[base0 + g + p0] = f2tf32(cacc[j][0] * inv0);
            ctx[base0 + g + p1] = f2tf32(cacc[j][1] * inv0);
            ctx[base1 + g + p0] = f2tf32(cacc[j][2] * inv1);
            ctx[base1 + g + p1] = f2tf32(cacc[j][3] * inv1);
        }
    }

    // ---- Pass B: recompute S, write normalized attn ----
    if (write_attn) {
        float* A = attn + (long long)z * Sq * Sq;
        for (int kt = 0; kt <= qt; kt++) {
            __syncthreads();
            loadK(kt);
            cp_commit();
            cp_wait0();
            __syncthreads();

            bool diag = (kt == qt);
            long long row0 = (long long)rbase * Sq;
            long long row1 = (long long)(rbase + 8) * Sq;
#pragma unroll
            for (int half = 0; half < 2; half++) {
#pragma unroll
                for (int j = 0; j < 8; j++) { p[j][0] = p[j][1] = p[j][2] = p[j][3] = 0.f; }
#pragma unroll
                for (int ks = 0; ks < 8; ks++) {
                    const int kp = ks * 8 + 2 * q4;
                    uint2 qlo = *(const uint2*)&Qw[rq * QST + kp];
                    uint2 qhi = *(const uint2*)&Qw[(rq + 8) * QST + kp];
#pragma unroll
                    for (int j = 0; j < 8; j++) {
                        int n = (half * 8 + j) * 8 + rq;
                        uint2 kb = *(const uint2*)&Ks[n * KST + kp];
                        mma8(p[j], qlo.x, qhi.x, qlo.y, qhi.y, kb.x, kb.y);
                    }
                }
#pragma unroll
                for (int j = 0; j < 8; j++) {
                    int c0 = kt * 128 + (half * 8 + j) * 8 + 2 * q4;
                    float e0 = (!diag || c0     <= rbase    ) ? __expf(p[j][0]) * inv0 : 0.f;
                    float e1 = (!diag || c0 + 1 <= rbase    ) ? __expf(p[j][1]) * inv0 : 0.f;
                    float e2 = (!diag || c0     <= rbase + 8) ? __expf(p[j][2]) * inv1 : 0.f;
                    float e3 = (!diag || c0 + 1 <= rbase + 8) ? __expf(p[j][3]) * inv1 : 0.f;
                    *(float2*)&A[row0 + c0] = make_float2(e0, e1);
                    *(float2*)&A[row1 + c0] = make_float2(e2, e3);
                }
            }
        }
        int cEnd = (qt + 1) * 128;
        int nz4 = (Sq - cEnd) >> 2;
        if (nz4 > 0) {
            float4 z4 = make_float4(0.f, 0.f, 0.f, 0.f);
            for (int i = tid; i < 128 * nz4; i += 256) {
                int r = i / nz4, c = (i - r * nz4) * 4;
                *(float4*)&A[(long long)(qt * 128 + r) * Sq + cEnd + c] = z4;
            }
        }
    }
}

// ---------------------------------------------------------------------------
// kernel_launch
// ---------------------------------------------------------------------------
extern "C" void kernel_launch(void* const* d_in, const int* in_sizes, int n_in,
                              void* d_out, int out_size)
{
    const float* q  = (const float*)d_in[0];
    const float* k  = (const float*)d_in[1];
    const float* v  = (const float*)d_in[2];
    // d_in[3] = causal tril mask (handled analytically)
    const float* wq = (const float*)d_in[4];
    const float* bq = (const float*)d_in[5];
    const float* wk = (const float*)d_in[6];
    const float* bk = (const float*)d_in[7];
    const float* wv = (const float*)d_in[8];
    const float* bv = (const float*)d_in[9];
    const float* wo = (const float*)d_in[10];
    const float* bo = (const float*)d_in[11];
    float* out = (float*)d_out;

    unsigned *qh, *kh, *vh, *ctx, *pwq, *pwk, *pwv, *pwo;
    cudaGetSymbolAddress((void**)&qh,  g_qh);
    cudaGetSymbolAddress((void**)&kh,  g_kh);
    cudaGetSymbolAddress((void**)&vh,  g_vh);
    cudaGetSymbolAddress((void**)&ctx, g_ctx);
    cudaGetSymbolAddress((void**)&pwq, g_wq);
    cudaGetSymbolAddress((void**)&pwk, g_wk);
    cudaGetSymbolAddress((void**)&pwv, g_wv);
    cudaGetSymbolAddress((void**)&pwo, g_wo);

    const long long OUT_E  = (long long)Bq * Sq * DM;
    const long long ATTN_E = (long long)Bq * Hq * Sq * Sq;
    int write_attn = ((long long)out_size >= OUT_E + ATTN_E) ? 1 : 0;
    float* attn = out + OUT_E;

    static int attr_done = 0;
    if (!attr_done) {
        cudaFuncSetAttribute(gemm_tc<true, true>,
                             cudaFuncAttributeMaxDynamicSharedMemorySize, G_SMEM_BYTES);
        cudaFuncSetAttribute(gemm_tc<false, false>,
                             cudaFuncAttributeMaxDynamicSharedMemorySize, G_SMEM_BYTES);
        cudaFuncSetAttribute(attn_flash,
                             cudaFuncAttributeMaxDynamicSharedMemorySize, F_SMEM_BYTES);
        attr_done = 1;
    }

    // 0: prep — WEIGHTS only -> tf32 bits, K-permuted (~8 us)
    PrepP pp;
    pp.in[0] = wq; pp.out[0] = pwq;
    pp.in[1] = wk; pp.out[1] = pwk;
    pp.in[2] = wv; pp.out[2] = pwv;
    pp.in[3] = wo; pp.out[3] = pwo;
    prep_cvt<<<dim3((DM * DM) / (256 * 4), 4), 256>>>(pp);

    // 1: fused QKV projections (A raw fp32 + cvt; B raw tf32 paired)
    GemmP pq = {};
    pq.X  = (const unsigned*)q; pq.W  = pwq; pq.b0_ = bq; pq.Y  = qh;
    pq.X1 = (const unsigned*)k; pq.W1 = pwk; pq.b1_ = bk; pq.Y1 = kh;
    pq.X2 = (const unsigned*)v; pq.W2 = pwv; pq.b2_ = bv; pq.Y2 = vh;
    pq.M = Bq * Sq; pq.N = DM; pq.K = DM; pq.qkv = 1;
    pq.ps[0] = 0.125f; pq.ps[1] = 1.f; pq.ps[2] = 1.f;
    pq.nperm[0] = 1; pq.nperm[1] = 1; pq.nperm[2] = 2;
    gemm_tc<true, true><<<dim3(DM / 128, (Bq * Sq) / 128, 3), 256, G_SMEM_BYTES>>>(pq);

    // 2: fused flash attention (2 CTAs/SM; K/V split cp.async groups)
    attn_flash<<<dim3(Sq / 128, Bq * Hq, 1), 256, F_SMEM_BYTES>>>(
        qh, kh, vh, ctx, attn, write_attn);

    // 3: out = ctx @ wo^T + bo (both operands raw tf32 paired)
    GemmP po = {};
    po.X = ctx; po.W = pwo; po.b0_ = bo; po.Y = out;
    po.M = Bq * Sq; po.N = DM; po.K = DM; po.qkv = 0;
    po.ps[0] = 1.f; po.nperm[0] = 0;
    gemm_tc<false, false><<<dim3(DM / 128, (Bq * Sq) / 128, 1), 256, G_SMEM_BYTES>>>(po);
}

// round 13
// speedup vs baseline: 1.4489x; 1.0511x over previous
#include <cuda_runtime.h>
#include <math.h>

// Problem constants
#define Bq 2
#define Sq 2048
#define DM 1024
#define Hq 16
#define DHq 64

// ---------------------------------------------------------------------------
// Scratch (__device__ globals)
// tf32 BIT PATTERNS; K/D permutation within 8-groups: k -> ((k&3)<<1)|(k>>2)
// qh carries the 1/8 score scale. vh transposed per 128-tile: [z][kt][d][128].
// ---------------------------------------------------------------------------
__device__ unsigned g_qh [(size_t)Bq * Hq * Sq * DHq];   // tf32, d-perm, x0.125
__device__ unsigned g_kh [(size_t)Bq * Hq * Sq * DHq];   // tf32, d-perm
__device__ unsigned g_vh [(size_t)Bq * Hq * Sq * DHq];   // [z][16][64][128] tf32, r-perm
__device__ unsigned g_ctx[(size_t)Bq * Sq * DM];          // tf32, d-perm
__device__ unsigned g_wq[(size_t)DM * DM];                // weights tf32, k-perm
__device__ unsigned g_wk[(size_t)DM * DM];
__device__ unsigned g_wv[(size_t)DM * DM];
__device__ unsigned g_wo[(size_t)DM * DM];

// ---------------------------------------------------------------------------
// Helpers
// ---------------------------------------------------------------------------
__device__ __forceinline__ unsigned f2tf32(float f) {
    unsigned r; asm("cvt.rna.tf32.f32 %0, %1;" : "=r"(r) : "f"(f)); return r;
}
__device__ __forceinline__ int perm8(int r) { return ((r & 3) << 1) | (r >> 2); }
__device__ __forceinline__ void cpa16(void* dst, const void* src) {
    unsigned d = (unsigned)__cvta_generic_to_shared(dst);
    asm volatile("cp.async.cg.shared.global [%0], [%1], 16;" :: "r"(d), "l"(src));
}
__device__ __forceinline__ void cp_commit() { asm volatile("cp.async.commit_group;"); }
__device__ __forceinline__ void cp_wait1()  { asm volatile("cp.async.wait_group 1;"); }
__device__ __forceinline__ void cp_wait0()  { asm volatile("cp.async.wait_group 0;"); }

__device__ __forceinline__ void mma8(float* c, unsigned a0, unsigned a1, unsigned a2,
                                     unsigned a3, unsigned b0, unsigned b1) {
    asm volatile(
        "mma.sync.aligned.m16n8k8.row.col.f32.tf32.tf32.f32 "
        "{%0,%1,%2,%3}, {%4,%5,%6,%7}, {%8,%9}, {%0,%1,%2,%3};"
        : "+f"(c[0]), "+f"(c[1]), "+f"(c[2]), "+f"(c[3])
        : "r"(a0), "r"(a1), "r"(a2), "r"(a3), "r"(b0), "r"(b1));
}

// ---------------------------------------------------------------------------
// Prep: WEIGHTS ONLY -> tf32 bits, K-dim permuted within 8-groups (~8 us).
// ---------------------------------------------------------------------------
struct PrepP { const float* in[4]; unsigned* out[4]; };

__global__ __launch_bounds__(256)
void prep_cvt(PrepP pp)
{
    int z = blockIdx.y;
    int idx4 = (blockIdx.x * 256 + threadIdx.x) * 4;
    const float* in = pp.in[z];
    unsigned* out = pp.out[z];
    float4 v = *(const float4*)&in[idx4];
    int base = idx4 & ~7;
    int off  = (idx4 & 7) ? 1 : 0;
    out[base + off + 0] = f2tf32(v.x);
    out[base + off + 2] = f2tf32(v.y);
    out[base + off + 4] = f2tf32(v.z);
    out[base + off + 6] = f2tf32(v.w);
}

// ---------------------------------------------------------------------------
// GEMM: Y = A @ W^T + bias. W always tf32 k-permuted (paired LDS.64, stride 40).
// A_F32=true: A raw fp32 (scalar LDS + cvt, stride 36, conflict-free).
// A_F32=false: A tf32 k/d-permuted (paired LDS.64, stride 40).
// OUT_HEAD epilogues per nperm: 0 plain head uint2; 1 d-perm scatter (q/k);
// 2 transposed V tile [z][kt][d][128] r-perm.
// ---------------------------------------------------------------------------
struct GemmP {
    const unsigned *X, *X1, *X2;
    const unsigned *W, *W1, *W2;
    const float *b0_, *b1_, *b2_;
    void *Y, *Y1, *Y2;
    int M, N, K;
    int qkv;
    float ps[3];
    int nperm[3];
};

#define BUF_WORDS 5120     // 128*40 (max of the two strides)
#define G_SMEM_BYTES (4 * BUF_WORDS * 4)

template <bool A_F32, bool OUT_HEAD>
__global__ __launch_bounds__(256, 2)
void gemm_tc(GemmP p)
{
    constexpr int ASA = A_F32 ? 36 : 40;   // A-tile stride
    constexpr int ASB = 40;                // B-tile stride

    const int m0 = blockIdx.y * 128;
    const int n0 = blockIdx.x * 128;
    const int z  = blockIdx.z;
    const int tid = threadIdx.x, lane = tid & 31, warp = tid >> 5;
    const int wm = warp & 1, wn = warp >> 1;

    const unsigned *X = p.X, *W = p.W; const float* bias = p.b0_; void* Y = p.Y;
    float pscale = p.ps[0]; int nperm = p.nperm[0];
    if (p.qkv) {
        if (z == 1) { X = p.X1; W = p.W1; bias = p.b1_; Y = p.Y1; pscale = p.ps[1]; nperm = p.nperm[1]; }
        else if (z == 2) { X = p.X2; W = p.W2; bias = p.b2_; Y = p.Y2; pscale = p.ps[2]; nperm = p.nperm[2]; }
    }

    extern __shared__ unsigned smu[];
    unsigned* Abuf[2] = { smu,                 smu + BUF_WORDS     };
    unsigned* Bbuf[2] = { smu + 2 * BUF_WORDS, smu + 3 * BUF_WORDS };

    auto loadA = [&](unsigned* As_, int k0) {
        int r0 = tid >> 3, c = (tid & 7) * 4;
#pragma unroll
        for (int it = 0; it < 4; it++) {
            int r = r0 + it * 32;
            cpa16(&As_[r * ASA + c], &X[(long long)(m0 + r) * p.K + k0 + c]);
        }
    };
    auto loadB = [&](unsigned* Bs_, int k0) {
        int r0 = tid >> 3, c = (tid & 7) * 4;
#pragma unroll
        for (int it = 0; it < 4; it++) {
            int r = r0 + it * 32;
            cpa16(&Bs_[r * ASB + c], &W[(long long)(n0 + r) * p.K + k0 + c]);
        }
    };

    float acc[4][4][4] = {};

    loadA(Abuf[0], 0); loadB(Bbuf[0], 0); cp_commit();
    int st = 0;
    for (int k0 = 0; k0 < p.K; k0 += 32) {
        if (k0 + 32 < p.K) { loadA(Abuf[st ^ 1], k0 + 32); loadB(Bbuf[st ^ 1], k0 + 32); }
        cp_commit();
        cp_wait1();
        __syncthreads();

        const unsigned* As_ = Abuf[st];
        const unsigned* Bs_ = Bbuf[st];
        const float* Af = (const float*)As_;
#pragma unroll
        for (int kk = 0; kk < 32; kk += 8) {
            const int kc = kk + (lane & 3);          // natural-k column (A_F32)
            const int kp = kk + 2 * (lane & 3);      // permuted pair base
            unsigned a[4][4];
#pragma unroll
            for (int i = 0; i < 4; i++) {
                int mr = wm * 64 + i * 16 + (lane >> 2);
                if (A_F32) {
                    a[i][0] = f2tf32(Af[mr * ASA + kc]);
                    a[i][1] = f2tf32(Af[(mr + 8) * ASA + kc]);
                    a[i][2] = f2tf32(Af[mr * ASA + kc + 4]);
                    a[i][3] = f2tf32(Af[(mr + 8) * ASA + kc + 4]);
                } else {
                    uint2 lo = *(const uint2*)&As_[mr * ASA + kp];
                    uint2 hi = *(const uint2*)&As_[(mr + 8) * ASA + kp];
                    a[i][0] = lo.x; a[i][1] = hi.x; a[i][2] = lo.y; a[i][3] = hi.y;
                }
            }
            unsigned b[4][2];
#pragma unroll
            for (int j = 0; j < 4; j++) {
                int nr = wn * 32 + j * 8 + (lane >> 2);
                uint2 bb = *(const uint2*)&Bs_[nr * ASB + kp];
                b[j][0] = bb.x; b[j][1] = bb.y;
            }
#pragma unroll
            for (int i = 0; i < 4; i++)
#pragma unroll
                for (int j = 0; j < 4; j++)
                    mma8(acc[i][j], a[i][0], a[i][1], a[i][2], a[i][3], b[j][0], b[j][1]);
        }
        __syncthreads();
        st ^= 1;
    }

#pragma unroll
    for (int i = 0; i < 4; i++)
#pragma unroll
        for (int j = 0; j < 4; j++)
#pragma unroll
            for (int h = 0; h < 2; h++) {
                int m = m0 + wm * 64 + i * 16 + (lane >> 2) + h * 8;
                int n = n0 + wn * 32 + j * 8 + (lane & 3) * 2;
                float v0 = acc[i][j][h * 2]     + (bias ? bias[n]     : 0.f);
                float v1 = acc[i][j][h * 2 + 1] + (bias ? bias[n + 1] : 0.f);
                if (OUT_HEAD) {
                    int b_ = m >> 11;
                    int s  = m & (Sq - 1);
                    int hh = n >> 6;
                    int d  = n & (DHq - 1);
                    unsigned u0 = f2tf32(v0 * pscale);
                    unsigned u1 = f2tf32(v1 * pscale);
                    unsigned* Yu = (unsigned*)Y;
                    int zz = b_ * Hq + hh;
                    if (nperm == 2) {
                        long long a0 = (((long long)zz * 16 + (s >> 7)) * 64 + d) * 128
                                       + ((s & 127) & ~7) + perm8(s & 7);
                        Yu[a0]       = u0;
                        Yu[a0 + 128] = u1;   // d+1
                    } else {
                        long long rowb = ((long long)zz * Sq + s) * DHq;
                        if (nperm == 1) {
                            int r0 = d & 7;
                            Yu[rowb + (d & ~7) + perm8(r0)]     = u0;
                            Yu[rowb + (d & ~7) + perm8(r0 + 1)] = u1;
                        } else {
                            *(uint2*)&Yu[rowb + d] = make_uint2(u0, u1);
                        }
                    }
                } else {
                    long long idx = (long long)m * p.N + n;
                    *(float2*)((float*)Y + idx) = make_float2(v0, v1);
                }
            }
}

// ---------------------------------------------------------------------------
// Fused flash attention. 256 threads, 8 warps x 16 rows, 2 CTAs/SM.
// Software-pipelined single-buffer: loadK(kt+1) issued after the last S
// reader (hidden behind PV1); loadV(kt+1) issued after PV1 (hidden behind
// next S0). K and V in separate cp.async groups.
// Q/K d-perm paired LDS.64 (stride 72); V transposed r-perm paired (136).
// ctx -> tf32 d-permuted. qt reversed.
// ---------------------------------------------------------------------------
#define QST 72
#define KST 72
#define VST 136
#define FQ_OFF 0
#define FK_OFF 9216
#define FV_OFF 18432
#define F_SMEM_WORDS 27136        // 9216 + 9216 + 64*136
#define F_SMEM_BYTES (F_SMEM_WORDS * 4)

__global__ __launch_bounds__(256, 2)
void attn_flash(const unsigned* __restrict__ qh, const unsigned* __restrict__ kh,
                const unsigned* __restrict__ vhT, unsigned* __restrict__ ctx,
                float* __restrict__ attn, int write_attn)
{
    const int qt = (int)gridDim.x - 1 - (int)blockIdx.x;
    const int z  = blockIdx.y;
    const int tid = threadIdx.x, lane = tid & 31, warp = tid >> 5;

    extern __shared__ unsigned smu[];
    unsigned* Qs = smu + FQ_OFF;
    unsigned* Ks = smu + FK_OFF;
    unsigned* Vs = smu + FV_OFF;

    const unsigned* Qg  = qh  + ((long long)z * Sq + qt * 128) * DHq;
    const unsigned* Kg  = kh  + (long long)z * Sq * DHq;
    const unsigned* VgT = vhT + (long long)z * Sq * DHq;

    for (int i = tid; i < 128 * 16; i += 256) {
        int r = i >> 4, c4 = (i & 15) * 4;
        *(uint4*)&Qs[r * QST + c4] = *(const uint4*)&Qg[r * 64 + c4];
    }

    auto loadK = [&](int kt) {
        for (int i = tid; i < 128 * 16; i += 256) {
            int r = i >> 4, c4 = (i & 15) * 4;
            cpa16(&Ks[r * KST + c4], &Kg[((long long)kt * 128 + r) * 64 + c4]);
        }
    };
    auto loadV = [&](int kt) {
        for (int i = tid; i < 64 * 32; i += 256) {
            int d = i >> 5, c4 = (i & 31) * 4;
            cpa16(&Vs[d * VST + c4], &VgT[(long long)kt * 8192 + d * 128 + c4]);
        }
    };

    const unsigned* Qw = &Qs[(warp * 16) * QST];
    const int rq = lane >> 2;
    const int q4 = lane & 3;
    const int rbase = qt * 128 + warp * 16 + rq;
    const int hlo = (lane & ~3) | (q4 >> 1);
    const int hhi = hlo | 2;
    const bool odd = lane & 1;

    float cacc[8][4] = {};
    float l0 = 0.f, l1 = 0.f;
    float p[8][4];

    loadK(0); cp_commit();
    loadV(0); cp_commit();

    for (int kt = 0; kt <= qt; kt++) {
        // in flight at top: K(kt), V(kt)
        cp_wait1();                      // K(kt) arrived (V may still fly)
        __syncthreads();                 // all threads' K parts visible

        bool diag = (kt == qt);

        // ---- S half 0 (K only; overlaps V load) ----
#pragma unroll
        for (int j = 0; j < 8; j++) { p[j][0] = p[j][1] = p[j][2] = p[j][3] = 0.f; }
#pragma unroll
        for (int ks = 0; ks < 8; ks++) {
            const int kp = ks * 8 + 2 * q4;
            uint2 qlo = *(const uint2*)&Qw[rq * QST + kp];
            uint2 qhi = *(const uint2*)&Qw[(rq + 8) * QST + kp];
#pragma unroll
            for (int j = 0; j < 8; j++) {
                int n = j * 8 + rq;
                uint2 kb = *(const uint2*)&Ks[n * KST + kp];
                mma8(p[j], qlo.x, qhi.x, qlo.y, qhi.y, kb.x, kb.y);
            }
        }
#pragma unroll
        for (int j = 0; j < 8; j++) {
            int c0 = kt * 128 + j * 8 + 2 * q4;
            float e0 = (!diag || c0     <= rbase    ) ? __expf(p[j][0]) : 0.f;
            float e1 = (!diag || c0 + 1 <= rbase    ) ? __expf(p[j][1]) : 0.f;
            float e2 = (!diag || c0     <= rbase + 8) ? __expf(p[j][2]) : 0.f;
            float e3 = (!diag || c0 + 1 <= rbase + 8) ? __expf(p[j][3]) : 0.f;
            p[j][0] = e0; p[j][1] = e1; p[j][2] = e2; p[j][3] = e3;
            l0 += e0 + e1; l1 += e2 + e3;
        }

        cp_wait0();                      // V(kt) arrived
        __syncthreads();

        // ---- PV half 0 ----
#pragma unroll
        for (int t = 0; t < 8; t++) {
            float v00 = __shfl_sync(0xffffffffu, p[t][0], hlo);
            float v01 = __shfl_sync(0xffffffffu, p[t][1], hlo);
            float v20 = __shfl_sync(0xffffffffu, p[t][2], hlo);
            float v21 = __shfl_sync(0xffffffffu, p[t][3], hlo);
            float w00 = __shfl_sync(0xffffffffu, p[t][0], hhi);
            float w01 = __shfl_sync(0xffffffffu, p[t][1], hhi);
            float w20 = __shfl_sync(0xffffffffu, p[t][2], hhi);
            float w21 = __shfl_sync(0xffffffffu, p[t][3], hhi);
            unsigned a0 = f2tf32(odd ? v01 : v00);
            unsigned a1 = f2tf32(odd ? v21 : v20);
            unsigned a2 = f2tf32(odd ? w01 : w00);
            unsigned a3 = f2tf32(odd ? w21 : w20);
            int krp = t * 8 + 2 * q4;
#pragma unroll
            for (int j = 0; j < 8; j++) {
                int n = j * 8 + rq;
                uint2 vb = *(const uint2*)&Vs[n * VST + krp];
                mma8(cacc[j], a0, a1, a2, a3, vb.x, vb.y);
            }
        }

        // ---- S half 1 (last K reader) ----
#pragma unroll
        for (int j = 0; j < 8; j++) { p[j][0] = p[j][1] = p[j][2] = p[j][3] = 0.f; }
#pragma unroll
        for (int ks = 0; ks < 8; ks++) {
            const int kp = ks * 8 + 2 * q4;
            uint2 qlo = *(const uint2*)&Qw[rq * QST + kp];
            uint2 qhi = *(const uint2*)&Qw[(rq + 8) * QST + kp];
#pragma unroll
            for (int j = 0; j < 8; j++) {
                int n = (8 + j) * 8 + rq;
                uint2 kb = *(const uint2*)&Ks[n * KST + kp];
                mma8(p[j], qlo.x, qhi.x, qlo.y, qhi.y, kb.x, kb.y);
            }
        }
#pragma unroll
        for (int j = 0; j < 8; j++) {
            int c0 = kt * 128 + (8 + j) * 8 + 2 * q4;
            float e0 = (!diag || c0     <= rbase    ) ? __expf(p[j][0]) : 0.f;
            float e1 = (!diag || c0 + 1 <= rbase    ) ? __expf(p[j][1]) : 0.f;
            float e2 = (!diag || c0     <= rbase + 8) ? __expf(p[j][2]) : 0.f;
            float e3 = (!diag || c0 + 1 <= rbase + 8) ? __expf(p[j][3]) : 0.f;
            p[j][0] = e0; p[j][1] = e1; p[j][2] = e2; p[j][3] = e3;
            l0 += e0 + e1; l1 += e2 + e3;
        }

        __syncthreads();                 // all warps done reading Ks
        if (kt < qt) { loadK(kt + 1); cp_commit(); }   // hidden behind PV1

        // ---- PV half 1 (last V reader) ----
#pragma unroll
        for (int t = 0; t < 8; t++) {
            float v00 = __shfl_sync(0xffffffffu, p[t][0], hlo);
            float v01 = __shfl_sync(0xffffffffu, p[t][1], hlo);
            float v20 = __shfl_sync(0xffffffffu, p[t][2], hlo);
            float v21 = __shfl_sync(0xffffffffu, p[t][3], hlo);
            float w00 = __shfl_sync(0xffffffffu, p[t][0], hhi);
            float w01 = __shfl_sync(0xffffffffu, p[t][1], hhi);
            float w20 = __shfl_sync(0xffffffffu, p[t][2], hhi);
            float w21 = __shfl_sync(0xffffffffu, p[t][3], hhi);
            unsigned a0 = f2tf32(odd ? v01 : v00);
            unsigned a1 = f2tf32(odd ? v21 : v20);
            unsigned a2 = f2tf32(odd ? w01 : w00);
            unsigned a3 = f2tf32(odd ? w21 : w20);
            int krp = (8 + t) * 8 + 2 * q4;
#pragma unroll
            for (int j = 0; j < 8; j++) {
                int n = j * 8 + rq;
                uint2 vb = *(const uint2*)&Vs[n * VST + krp];
                mma8(cacc[j], a0, a1, a2, a3, vb.x, vb.y);
            }
        }

        __syncthreads();                 // all warps done reading Vs
        if (kt < qt) { loadV(kt + 1); cp_commit(); }   // hidden behind next S0
    }

    l0 += __shfl_xor_sync(0xffffffffu, l0, 1);
    l0 += __shfl_xor_sync(0xffffffffu, l0, 2);
    l1 += __shfl_xor_sync(0xffffffffu, l1, 1);
    l1 += __shfl_xor_sync(0xffffffffu, l1, 2);
    float inv0 = 1.0f / l0, inv1 = 1.0f / l1;

    // ---- ctx epilogue -> tf32 bits, d-permuted ----
    {
        int b_ = z >> 4, h_ = z & 15;
        long long base0 = ((long long)b_ * Sq + rbase) * DM + h_ * 64;
        long long base1 = base0 + 8LL * DM;
        int r0 = 2 * q4;
        int p0 = perm8(r0), p1 = perm8(r0 + 1);
#pragma unroll
        for (int j = 0; j < 8; j++) {
            int g = j * 8;
            ctx[base0 + g + p0] = f2tf32(cacc[j][0] * inv0);
            ctx[base0 + g + p1] = f2tf32(cacc[j][1] * inv0);
            ctx[base1 + g + p0] = f2tf32(cacc[j][2] * inv1);
            ctx[base1 + g + p1] = f2tf32(cacc[j][3] * inv1);
        }
    }

    // ---- Pass B: recompute S, write normalized attn (K prefetch overlaps
    //      the exp1/write1 epilogue) ----
    if (write_attn) {
        float* A = attn + (long long)z * Sq * Sq;
        __syncthreads();
        loadK(0); cp_commit();
        for (int kt = 0; kt <= qt; kt++) {
            cp_wait0();
            __syncthreads();

            bool diag = (kt == qt);
            long long row0 = (long long)rbase * Sq;
            long long row1 = (long long)(rbase + 8) * Sq;

            // S half 0 + write
#pragma unroll
            for (int j = 0; j < 8; j++) { p[j][0] = p[j][1] = p[j][2] = p[j][3] = 0.f; }
#pragma unroll
            for (int ks = 0; ks < 8; ks++) {
                const int kp = ks * 8 + 2 * q4;
                uint2 qlo = *(const uint2*)&Qw[rq * QST + kp];
                uint2 qhi = *(const uint2*)&Qw[(rq + 8) * QST + kp];
#pragma unroll
                for (int j = 0; j < 8; j++) {
                    int n = j * 8 + rq;
                    uint2 kb = *(const uint2*)&Ks[n * KST + kp];
                    mma8(p[j], qlo.x, qhi.x, qlo.y, qhi.y, kb.x, kb.y);
                }
            }
#pragma unroll
            for (int j = 0; j < 8; j++) {
                int c0 = kt * 128 + j * 8 + 2 * q4;
                float e0 = (!diag || c0     <= rbase    ) ? __expf(p[j][0]) * inv0 : 0.f;
                float e1 = (!diag || c0 + 1 <= rbase    ) ? __expf(p[j][1]) * inv0 : 0.f;
                float e2 = (!diag || c0     <= rbase + 8) ? __expf(p[j][2]) * inv1 : 0.f;
                float e3 = (!diag || c0 + 1 <= rbase + 8) ? __expf(p[j][3]) * inv1 : 0.f;
                *(float2*)&A[row0 + c0] = make_float2(e0, e1);
                *(float2*)&A[row1 + c0] = make_float2(e2, e3);
            }

            // S half 1 mma (last K reader), then prefetch K overlapped with epilogue
#pragma unroll
            for (int j = 0; j < 8; j++) { p[j][0] = p[j][1] = p[j][2] = p[j][3] = 0.f; }
#pragma unroll
            for (int ks = 0; ks < 8; ks++) {
                const int kp = ks * 8 + 2 * q4;
                uint2 qlo = *(const uint2*)&Qw[rq * QST + kp];
                uint2 qhi = *(const uint2*)&Qw[(rq + 8) * QST + kp];
#pragma unroll
                for (int j = 0; j < 8; j++) {
                    int n = (8 + j) * 8 + rq;
                    uint2 kb = *(const uint2*)&Ks[n * KST + kp];
                    mma8(p[j], qlo.x, qhi.x, qlo.y, qhi.y, kb.x, kb.y);
                }
            }
            __syncthreads();             // all warps done reading Ks
            if (kt < qt) { loadK(kt + 1); cp_commit(); }
#pragma unroll
            for (int j = 0; j < 8; j++) {
                int c0 = kt * 128 + (8 + j) * 8 + 2 * q4;
                float e0 = (!diag || c0     <= rbase    ) ? __expf(p[j][0]) * inv0 : 0.f;
                float e1 = (!diag || c0 + 1 <= rbase    ) ? __expf(p[j][1]) * inv0 : 0.f;
                float e2 = (!diag || c0     <= rbase + 8) ? __expf(p[j][2]) * inv1 : 0.f;
                float e3 = (!diag || c0 + 1 <= rbase + 8) ? __expf(p[j][3]) * inv1 : 0.f;
                *(float2*)&A[row0 + c0] = make_float2(e0, e1);
                *(float2*)&A[row1 + c0] = make_float2(e2, e3);
            }
        }
        int cEnd = (qt + 1) * 128;
        int nz4 = (Sq - cEnd) >> 2;
        if (nz4 > 0) {
            float4 z4 = make_float4(0.f, 0.f, 0.f, 0.f);
            for (int i = tid; i < 128 * nz4; i += 256) {
                int r = i / nz4, c = (i - r * nz4) * 4;
                *(float4*)&A[(long long)(qt * 128 + r) * Sq + cEnd + c] = z4;
            }
        }
    }
}

// ---------------------------------------------------------------------------
// kernel_launch
// ---------------------------------------------------------------------------
extern "C" void kernel_launch(void* const* d_in, const int* in_sizes, int n_in,
                              void* d_out, int out_size)
{
    const float* q  = (const float*)d_in[0];
    const float* k  = (const float*)d_in[1];
    const float* v  = (const float*)d_in[2];
    // d_in[3] = causal tril mask (handled analytically)
    const float* wq = (const float*)d_in[4];
    const float* bq = (const float*)d_in[5];
    const float* wk = (const float*)d_in[6];
    const float* bk = (const float*)d_in[7];
    const float* wv = (const float*)d_in[8];
    const float* bv = (const float*)d_in[9];
    const float* wo = (const float*)d_in[10];
    const float* bo = (const float*)d_in[11];
    float* out = (float*)d_out;

    unsigned *qh, *kh, *vh, *ctx, *pwq, *pwk, *pwv, *pwo;
    cudaGetSymbolAddress((void**)&qh,  g_qh);
    cudaGetSymbolAddress((void**)&kh,  g_kh);
    cudaGetSymbolAddress((void**)&vh,  g_vh);
    cudaGetSymbolAddress((void**)&ctx, g_ctx);
    cudaGetSymbolAddress((void**)&pwq, g_wq);
    cudaGetSymbolAddress((void**)&pwk, g_wk);
    cudaGetSymbolAddress((void**)&pwv, g_wv);
    cudaGetSymbolAddress((void**)&pwo, g_wo);

    const long long OUT_E  = (long long)Bq * Sq * DM;
    const long long ATTN_E = (long long)Bq * Hq * Sq * Sq;
    int write_attn = ((long long)out_size >= OUT_E + ATTN_E) ? 1 : 0;
    float* attn = out + OUT_E;

    static int attr_done = 0;
    if (!attr_done) {
        cudaFuncSetAttribute(gemm_tc<true, true>,
                             cudaFuncAttributeMaxDynamicSharedMemorySize, G_SMEM_BYTES);
        cudaFuncSetAttribute(gemm_tc<false, false>,
                             cudaFuncAttributeMaxDynamicSharedMemorySize, G_SMEM_BYTES);
        cudaFuncSetAttribute(attn_flash,
                             cudaFuncAttributeMaxDynamicSharedMemorySize, F_SMEM_BYTES);
        attr_done = 1;
    }

    // 0: prep — WEIGHTS only -> tf32 bits, K-permuted (~8 us)
    PrepP pp;
    pp.in[0] = wq; pp.out[0] = pwq;
    pp.in[1] = wk; pp.out[1] = pwk;
    pp.in[2] = wv; pp.out[2] = pwv;
    pp.in[3] = wo; pp.out[3] = pwo;
    prep_cvt<<<dim3((DM * DM) / (256 * 4), 4), 256>>>(pp);

    // 1: fused QKV projections (A raw fp32 + cvt; B raw tf32 paired)
    GemmP pq = {};
    pq.X  = (const unsigned*)q; pq.W  = pwq; pq.b0_ = bq; pq.Y  = qh;
    pq.X1 = (const unsigned*)k; pq.W1 = pwk; pq.b1_ = bk; pq.Y1 = kh;
    pq.X2 = (const unsigned*)v; pq.W2 = pwv; pq.b2_ = bv; pq.Y2 = vh;
    pq.M = Bq * Sq; pq.N = DM; pq.K = DM; pq.qkv = 1;
    pq.ps[0] = 0.125f; pq.ps[1] = 1.f; pq.ps[2] = 1.f;
    pq.nperm[0] = 1; pq.nperm[1] = 1; pq.nperm[2] = 2;
    gemm_tc<true, true><<<dim3(DM / 128, (Bq * Sq) / 128, 3), 256, G_SMEM_BYTES>>>(pq);

    // 2: fused flash attention (2 CTAs/SM; pipelined K/V prefetch)
    attn_flash<<<dim3(Sq / 128, Bq * Hq, 1), 256, F_SMEM_BYTES>>>(
        qh, kh, vh, ctx, attn, write_attn);

    // 3: out = ctx @ wo^T + bo (both operands raw tf32 paired)
    GemmP po = {};
    po.X = ctx; po.W = pwo; po.b0_ = bo; po.Y = out;
    po.M = Bq * Sq; po.N = DM; po.K = DM; po.qkv = 0;
    po.ps[0] = 1.f; po.nperm[0] = 0;
    gemm_tc<false, false><<<dim3(DM / 128, (Bq * Sq) / 128, 1), 256, G_SMEM_BYTES>>>(po);
}

// round 14
// speedup vs baseline: 1.4808x; 1.0220x over previous
#include <cuda_runtime.h>
#include <math.h>

// Problem constants
#define Bq 2
#define Sq 2048
#define DM 1024
#define Hq 16
#define DHq 64

// ---------------------------------------------------------------------------
// Scratch (__device__ globals)
// tf32 BIT PATTERNS; K/D permutation within 8-groups: k -> ((k&3)<<1)|(k>>2)
// qh carries the 1/8 score scale. vh transposed per 128-tile: [z][kt][d][128]
// in NATURAL row order (PV uses the delta=perm8 k-relabeling, so adjacent
// V rows pair with the S-output register layout directly).
// ---------------------------------------------------------------------------
__device__ unsigned g_qh [(size_t)Bq * Hq * Sq * DHq];   // tf32, d-perm, x0.125
__device__ unsigned g_kh [(size_t)Bq * Hq * Sq * DHq];   // tf32, d-perm
__device__ unsigned g_vh [(size_t)Bq * Hq * Sq * DHq];   // [z][16][64][128] tf32, natural rows
__device__ unsigned g_ctx[(size_t)Bq * Sq * DM];          // tf32, d-perm
__device__ unsigned g_wq[(size_t)DM * DM];                // weights tf32, k-perm
__device__ unsigned g_wk[(size_t)DM * DM];
__device__ unsigned g_wv[(size_t)DM * DM];
__device__ unsigned g_wo[(size_t)DM * DM];

// ---------------------------------------------------------------------------
// Helpers
// ---------------------------------------------------------------------------
__device__ __forceinline__ unsigned f2tf32(float f) {
    unsigned r; asm("cvt.rna.tf32.f32 %0, %1;" : "=r"(r) : "f"(f)); return r;
}
__device__ __forceinline__ int perm8(int r) { return ((r & 3) << 1) | (r >> 2); }
__device__ __forceinline__ void cpa16(void* dst, const void* src) {
    unsigned d = (unsigned)__cvta_generic_to_shared(dst);
    asm volatile("cp.async.cg.shared.global [%0], [%1], 16;" :: "r"(d), "l"(src));
}
__device__ __forceinline__ void cp_commit() { asm volatile("cp.async.commit_group;"); }
__device__ __forceinline__ void cp_wait1()  { asm volatile("cp.async.wait_group 1;"); }
__device__ __forceinline__ void cp_wait0()  { asm volatile("cp.async.wait_group 0;"); }

__device__ __forceinline__ void mma8(float* c, unsigned a0, unsigned a1, unsigned a2,
                                     unsigned a3, unsigned b0, unsigned b1) {
    asm volatile(
        "mma.sync.aligned.m16n8k8.row.col.f32.tf32.tf32.f32 "
        "{%0,%1,%2,%3}, {%4,%5,%6,%7}, {%8,%9}, {%0,%1,%2,%3};"
        : "+f"(c[0]), "+f"(c[1]), "+f"(c[2]), "+f"(c[3])
        : "r"(a0), "r"(a1), "r"(a2), "r"(a3), "r"(b0), "r"(b1));
}

// ---------------------------------------------------------------------------
// Prep: WEIGHTS ONLY -> tf32 bits, K-dim permuted within 8-groups (~8 us).
// ---------------------------------------------------------------------------
struct PrepP { const float* in[4]; unsigned* out[4]; };

__global__ __launch_bounds__(256)
void prep_cvt(PrepP pp)
{
    int z = blockIdx.y;
    int idx4 = (blockIdx.x * 256 + threadIdx.x) * 4;
    const float* in = pp.in[z];
    unsigned* out = pp.out[z];
    float4 v = *(const float4*)&in[idx4];
    int base = idx4 & ~7;
    int off  = (idx4 & 7) ? 1 : 0;
    out[base + off + 0] = f2tf32(v.x);
    out[base + off + 2] = f2tf32(v.y);
    out[base + off + 4] = f2tf32(v.z);
    out[base + off + 6] = f2tf32(v.w);
}

// ---------------------------------------------------------------------------
// GEMM: Y = A @ W^T + bias. W always tf32 k-permuted (paired LDS.64, stride 40).
// A_F32=true: A raw fp32 (scalar LDS + cvt, stride 36, conflict-free).
// A_F32=false: A tf32 k/d-permuted (paired LDS.64, stride 40).
// OUT_HEAD epilogues per nperm: 0 plain head uint2; 1 d-perm scatter (q/k);
// 2 transposed V tile [z][kt][d][128], natural row order.
// ---------------------------------------------------------------------------
struct GemmP {
    const unsigned *X, *X1, *X2;
    const unsigned *W, *W1, *W2;
    const float *b0_, *b1_, *b2_;
    void *Y, *Y1, *Y2;
    int M, N, K;
    int qkv;
    float ps[3];
    int nperm[3];
};

#define BUF_WORDS 5120     // 128*40 (max of the two strides)
#define G_SMEM_BYTES (4 * BUF_WORDS * 4)

template <bool A_F32, bool OUT_HEAD>
__global__ __launch_bounds__(256, 2)
void gemm_tc(GemmP p)
{
    constexpr int ASA = A_F32 ? 36 : 40;   // A-tile stride
    constexpr int ASB = 40;                // B-tile stride

    const int m0 = blockIdx.y * 128;
    const int n0 = blockIdx.x * 128;
    const int z  = blockIdx.z;
    const int tid = threadIdx.x, lane = tid & 31, warp = tid >> 5;
    const int wm = warp & 1, wn = warp >> 1;

    const unsigned *X = p.X, *W = p.W; const float* bias = p.b0_; void* Y = p.Y;
    float pscale = p.ps[0]; int nperm = p.nperm[0];
    if (p.qkv) {
        if (z == 1) { X = p.X1; W = p.W1; bias = p.b1_; Y = p.Y1; pscale = p.ps[1]; nperm = p.nperm[1]; }
        else if (z == 2) { X = p.X2; W = p.W2; bias = p.b2_; Y = p.Y2; pscale = p.ps[2]; nperm = p.nperm[2]; }
    }

    extern __shared__ unsigned smu[];
    unsigned* Abuf[2] = { smu,                 smu + BUF_WORDS     };
    unsigned* Bbuf[2] = { smu + 2 * BUF_WORDS, smu + 3 * BUF_WORDS };

    auto loadA = [&](unsigned* As_, int k0) {
        int r0 = tid >> 3, c = (tid & 7) * 4;
#pragma unroll
        for (int it = 0; it < 4; it++) {
            int r = r0 + it * 32;
            cpa16(&As_[r * ASA + c], &X[(long long)(m0 + r) * p.K + k0 + c]);
        }
    };
    auto loadB = [&](unsigned* Bs_, int k0) {
        int r0 = tid >> 3, c = (tid & 7) * 4;
#pragma unroll
        for (int it = 0; it < 4; it++) {
            int r = r0 + it * 32;
            cpa16(&Bs_[r * ASB + c], &W[(long long)(n0 + r) * p.K + k0 + c]);
        }
    };

    float acc[4][4][4] = {};

    loadA(Abuf[0], 0); loadB(Bbuf[0], 0); cp_commit();
    int st = 0;
    for (int k0 = 0; k0 < p.K; k0 += 32) {
        if (k0 + 32 < p.K) { loadA(Abuf[st ^ 1], k0 + 32); loadB(Bbuf[st ^ 1], k0 + 32); }
        cp_commit();
        cp_wait1();
        __syncthreads();

        const unsigned* As_ = Abuf[st];
        const unsigned* Bs_ = Bbuf[st];
        const float* Af = (const float*)As_;
#pragma unroll
        for (int kk = 0; kk < 32; kk += 8) {
            const int kc = kk + (lane & 3);          // natural-k column (A_F32)
            const int kp = kk + 2 * (lane & 3);      // permuted pair base
            unsigned a[4][4];
#pragma unroll
            for (int i = 0; i < 4; i++) {
                int mr = wm * 64 + i * 16 + (lane >> 2);
                if (A_F32) {
                    a[i][0] = f2tf32(Af[mr * ASA + kc]);
                    a[i][1] = f2tf32(Af[(mr + 8) * ASA + kc]);
                    a[i][2] = f2tf32(Af[mr * ASA + kc + 4]);
                    a[i][3] = f2tf32(Af[(mr + 8) * ASA + kc + 4]);
                } else {
                    uint2 lo = *(const uint2*)&As_[mr * ASA + kp];
                    uint2 hi = *(const uint2*)&As_[(mr + 8) * ASA + kp];
                    a[i][0] = lo.x; a[i][1] = hi.x; a[i][2] = lo.y; a[i][3] = hi.y;
                }
            }
            unsigned b[4][2];
#pragma unroll
            for (int j = 0; j < 4; j++) {
                int nr = wn * 32 + j * 8 + (lane >> 2);
                uint2 bb = *(const uint2*)&Bs_[nr * ASB + kp];
                b[j][0] = bb.x; b[j][1] = bb.y;
            }
#pragma unroll
            for (int i = 0; i < 4; i++)
#pragma unroll
                for (int j = 0; j < 4; j++)
                    mma8(acc[i][j], a[i][0], a[i][1], a[i][2], a[i][3], b[j][0], b[j][1]);
        }
        __syncthreads();
        st ^= 1;
    }

#pragma unroll
    for (int i = 0; i < 4; i++)
#pragma unroll
        for (int j = 0; j < 4; j++)
#pragma unroll
            for (int h = 0; h < 2; h++) {
                int m = m0 + wm * 64 + i * 16 + (lane >> 2) + h * 8;
                int n = n0 + wn * 32 + j * 8 + (lane & 3) * 2;
                float v0 = acc[i][j][h * 2]     + (bias ? bias[n]     : 0.f);
                float v1 = acc[i][j][h * 2 + 1] + (bias ? bias[n + 1] : 0.f);
                if (OUT_HEAD) {
                    int b_ = m >> 11;
                    int s  = m & (Sq - 1);
                    int hh = n >> 6;
                    int d  = n & (DHq - 1);
                    unsigned u0 = f2tf32(v0 * pscale);
                    unsigned u1 = f2tf32(v1 * pscale);
                    unsigned* Yu = (unsigned*)Y;
                    int zz = b_ * Hq + hh;
                    if (nperm == 2) {
                        // V transposed tile layout [z][s>>7][d][128], NATURAL rows
                        long long a0 = (((long long)zz * 16 + (s >> 7)) * 64 + d) * 128
                                       + (s & 127);
                        Yu[a0]       = u0;
                        Yu[a0 + 128] = u1;   // d+1
                    } else {
                        long long rowb = ((long long)zz * Sq + s) * DHq;
                        if (nperm == 1) {
                            int r0 = d & 7;
                            Yu[rowb + (d & ~7) + perm8(r0)]     = u0;
                            Yu[rowb + (d & ~7) + perm8(r0 + 1)] = u1;
                        } else {
                            *(uint2*)&Yu[rowb + d] = make_uint2(u0, u1);
                        }
                    }
                } else {
                    long long idx = (long long)m * p.N + n;
                    *(float2*)((float*)Y + idx) = make_float2(v0, v1);
                }
            }
}

// ---------------------------------------------------------------------------
// Fused flash attention. 256 threads, 8 warps x 16 rows, 2 CTAs/SM.
// Software-pipelined single-buffer (K/V separate cp.async groups; prefetch
// rotation). PV uses the delta=perm8 k-relabeling: A-frags come DIRECTLY
// from the S-output registers (zero shuffles); V stored natural-row
// transposed so B-frags are adjacent uint2 loads.
// ---------------------------------------------------------------------------
#define QST 72
#define KST 72
#define VST 136
#define FQ_OFF 0
#define FK_OFF 9216
#define FV_OFF 18432
#define F_SMEM_WORDS 27136        // 9216 + 9216 + 64*136
#define F_SMEM_BYTES (F_SMEM_WORDS * 4)

__global__ __launch_bounds__(256, 2)
void attn_flash(const unsigned* __restrict__ qh, const unsigned* __restrict__ kh,
                const unsigned* __restrict__ vhT, unsigned* __restrict__ ctx,
                float* __restrict__ attn, int write_attn)
{
    const int qt = (int)gridDim.x - 1 - (int)blockIdx.x;
    const int z  = blockIdx.y;
    const int tid = threadIdx.x, lane = tid & 31, warp = tid >> 5;

    extern __shared__ unsigned smu[];
    unsigned* Qs = smu + FQ_OFF;
    unsigned* Ks = smu + FK_OFF;
    unsigned* Vs = smu + FV_OFF;

    const unsigned* Qg  = qh  + ((long long)z * Sq + qt * 128) * DHq;
    const unsigned* Kg  = kh  + (long long)z * Sq * DHq;
    const unsigned* VgT = vhT + (long long)z * Sq * DHq;

    for (int i = tid; i < 128 * 16; i += 256) {
        int r = i >> 4, c4 = (i & 15) * 4;
        *(uint4*)&Qs[r * QST + c4] = *(const uint4*)&Qg[r * 64 + c4];
    }

    auto loadK = [&](int kt) {
        for (int i = tid; i < 128 * 16; i += 256) {
            int r = i >> 4, c4 = (i & 15) * 4;
            cpa16(&Ks[r * KST + c4], &Kg[((long long)kt * 128 + r) * 64 + c4]);
        }
    };
    auto loadV = [&](int kt) {
        for (int i = tid; i < 64 * 32; i += 256) {
            int d = i >> 5, c4 = (i & 31) * 4;
            cpa16(&Vs[d * VST + c4], &VgT[(long long)kt * 8192 + d * 128 + c4]);
        }
    };

    const unsigned* Qw = &Qs[(warp * 16) * QST];
    const int rq = lane >> 2;
    const int q4 = lane & 3;
    const int rbase = qt * 128 + warp * 16 + rq;

    float cacc[8][4] = {};
    float l0 = 0.f, l1 = 0.f;
    float p[8][4];

    loadK(0); cp_commit();
    loadV(0); cp_commit();

    for (int kt = 0; kt <= qt; kt++) {
        // in flight at top: K(kt), V(kt)
        cp_wait1();                      // K(kt) arrived (V may still fly)
        __syncthreads();                 // covers Q fill + prev readers

        bool diag = (kt == qt);

        // ---- S half 0 (K only; overlaps V load) ----
#pragma unroll
        for (int j = 0; j < 8; j++) { p[j][0] = p[j][1] = p[j][2] = p[j][3] = 0.f; }
#pragma unroll
        for (int ks = 0; ks < 8; ks++) {
            const int kp = ks * 8 + 2 * q4;
            uint2 qlo = *(const uint2*)&Qw[rq * QST + kp];
            uint2 qhi = *(const uint2*)&Qw[(rq + 8) * QST + kp];
#pragma unroll
            for (int j = 0; j < 8; j++) {
                int n = j * 8 + rq;
                uint2 kb = *(const uint2*)&Ks[n * KST + kp];
                mma8(p[j], qlo.x, qhi.x, qlo.y, qhi.y, kb.x, kb.y);
            }
        }
#pragma unroll
        for (int j = 0; j < 8; j++) {
            int c0 = kt * 128 + j * 8 + 2 * q4;
            float e0 = (!diag || c0     <= rbase    ) ? __expf(p[j][0]) : 0.f;
            float e1 = (!diag || c0 + 1 <= rbase    ) ? __expf(p[j][1]) : 0.f;
            float e2 = (!diag || c0     <= rbase + 8) ? __expf(p[j][2]) : 0.f;
            float e3 = (!diag || c0 + 1 <= rbase + 8) ? __expf(p[j][3]) : 0.f;
            p[j][0] = e0; p[j][1] = e1; p[j][2] = e2; p[j][3] = e3;
            l0 += e0 + e1; l1 += e2 + e3;
        }

        cp_wait0();                      // V(kt) arrived
        __syncthreads();

        // ---- PV half 0 (A-frags straight from p registers; zero shuffles) ----
#pragma unroll
        for (int t = 0; t < 8; t++) {
            unsigned a0 = f2tf32(p[t][0]);
            unsigned a1 = f2tf32(p[t][2]);
            unsigned a2 = f2tf32(p[t][1]);
            unsigned a3 = f2tf32(p[t][3]);
            int krp = t * 8 + 2 * q4;
#pragma unroll
            for (int j = 0; j < 8; j++) {
                int n = j * 8 + rq;
                uint2 vb = *(const uint2*)&Vs[n * VST + krp];
                mma8(cacc[j], a0, a1, a2, a3, vb.x, vb.y);
            }
        }

        // ---- S half 1 (last K reader) ----
#pragma unroll
        for (int j = 0; j < 8; j++) { p[j][0] = p[j][1] = p[j][2] = p[j][3] = 0.f; }
#pragma unroll
        for (int ks = 0; ks < 8; ks++) {
            const int kp = ks * 8 + 2 * q4;
            uint2 qlo = *(const uint2*)&Qw[rq * QST + kp];
            uint2 qhi = *(const uint2*)&Qw[(rq + 8) * QST + kp];
#pragma unroll
            for (int j = 0; j < 8; j++) {
                int n = (8 + j) * 8 + rq;
                uint2 kb = *(const uint2*)&Ks[n * KST + kp];
                mma8(p[j], qlo.x, qhi.x, qlo.y, qhi.y, kb.x, kb.y);
            }
        }
#pragma unroll
        for (int j = 0; j < 8; j++) {
            int c0 = kt * 128 + (8 + j) * 8 + 2 * q4;
            float e0 = (!diag || c0     <= rbase    ) ? __expf(p[j][0]) : 0.f;
            float e1 = (!diag || c0 + 1 <= rbase    ) ? __expf(p[j][1]) : 0.f;
            float e2 = (!diag || c0     <= rbase + 8) ? __expf(p[j][2]) : 0.f;
            float e3 = (!diag || c0 + 1 <= rbase + 8) ? __expf(p[j][3]) : 0.f;
            p[j][0] = e0; p[j][1] = e1; p[j][2] = e2; p[j][3] = e3;
            l0 += e0 + e1; l1 += e2 + e3;
        }

        __syncthreads();                 // all warps done reading Ks
        if (kt < qt) { loadK(kt + 1); cp_commit(); }   // hidden behind PV1

        // ---- PV half 1 (last V reader) ----
#pragma unroll
        for (int t = 0; t < 8; t++) {
            unsigned a0 = f2tf32(p[t][0]);
            unsigned a1 = f2tf32(p[t][2]);
            unsigned a2 = f2tf32(p[t][1]);
            unsigned a3 = f2tf32(p[t][3]);
            int krp = (8 + t) * 8 + 2 * q4;
#pragma unroll
            for (int j = 0; j < 8; j++) {
                int n = j * 8 + rq;
                uint2 vb = *(const uint2*)&Vs[n * VST + krp];
                mma8(cacc[j], a0, a1, a2, a3, vb.x, vb.y);
            }
        }

        __syncthreads();                 // all warps done reading Vs
        if (kt < qt) { loadV(kt + 1); cp_commit(); }   // hidden behind next S0
    }

    l0 += __shfl_xor_sync(0xffffffffu, l0, 1);
    l0 += __shfl_xor_sync(0xffffffffu, l0, 2);
    l1 += __shfl_xor_sync(0xffffffffu, l1, 1);
    l1 += __shfl_xor_sync(0xffffffffu, l1, 2);
    float inv0 = 1.0f / l0, inv1 = 1.0f / l1;

    // ---- ctx epilogue -> tf32 bits, d-permuted ----
    {
        int b_ = z >> 4, h_ = z & 15;
        long long base0 = ((long long)b_ * Sq + rbase) * DM + h_ * 64;
        long long base1 = base0 + 8LL * DM;
        int r0 = 2 * q4;
        int p0 = perm8(r0), p1 = perm8(r0 + 1);
#pragma unroll
        for (int j = 0; j < 8; j++) {
            int g = j * 8;
            ctx[base0 + g + p0] = f2tf32(cacc[j][0] * inv0);
            ctx[base0 + g + p1] = f2tf32(cacc[j][1] * inv0);
            ctx[base1 + g + p0] = f2tf32(cacc[j][2] * inv1);
            ctx[base1 + g + p1] = f2tf32(cacc[j][3] * inv1);
        }
    }

    // ---- Pass B: recompute S, write normalized attn (K prefetch overlaps
    //      the exp1/write1 epilogue) ----
    if (write_attn) {
        float* A = attn + (long long)z * Sq * Sq;
        __syncthreads();
        loadK(0); cp_commit();
        for (int kt = 0; kt <= qt; kt++) {
            cp_wait0();
            __syncthreads();

            bool diag = (kt == qt);
            long long row0 = (long long)rbase * Sq;
            long long row1 = (long long)(rbase + 8) * Sq;

            // S half 0 + write
#pragma unroll
            for (int j = 0; j < 8; j++) { p[j][0] = p[j][1] = p[j][2] = p[j][3] = 0.f; }
#pragma unroll
            for (int ks = 0; ks < 8; ks++) {
                const int kp = ks * 8 + 2 * q4;
                uint2 qlo = *(const uint2*)&Qw[rq * QST + kp];
                uint2 qhi = *(const uint2*)&Qw[(rq + 8) * QST + kp];
#pragma unroll
                for (int j = 0; j < 8; j++) {
                    int n = j * 8 + rq;
                    uint2 kb = *(const uint2*)&Ks[n * KST + kp];
                    mma8(p[j], qlo.x, qhi.x, qlo.y, qhi.y, kb.x, kb.y);
                }
            }
#pragma unroll
            for (int j = 0; j < 8; j++) {
                int c0 = kt * 128 + j * 8 + 2 * q4;
                float e0 = (!diag || c0     <= rbase    ) ? __expf(p[j][0]) * inv0 : 0.f;
                float e1 = (!diag || c0 + 1 <= rbase    ) ? __expf(p[j][1]) * inv0 : 0.f;
                float e2 = (!diag || c0     <= rbase + 8) ? __expf(p[j][2]) * inv1 : 0.f;
                float e3 = (!diag || c0 + 1 <= rbase + 8) ? __expf(p[j][3]) * inv1 : 0.f;
                *(float2*)&A[row0 + c0] = make_float2(e0, e1);
                *(float2*)&A[row1 + c0] = make_float2(e2, e3);
            }

            // S half 1 mma (last K reader), prefetch overlapped with epilogue
#pragma unroll
            for (int j = 0; j < 8; j++) { p[j][0] = p[j][1] = p[j][2] = p[j][3] = 0.f; }
#pragma unroll
            for (int ks = 0; ks < 8; ks++) {
                const int kp = ks * 8 + 2 * q4;
                uint2 qlo = *(const uint2*)&Qw[rq * QST + kp];
                uint2 qhi = *(const uint2*)&Qw[(rq + 8) * QST + kp];
#pragma unroll
                for (int j = 0; j < 8; j++) {
                    int n = (8 + j) * 8 + rq;
                    uint2 kb = *(const uint2*)&Ks[n * KST + kp];
                    mma8(p[j], qlo.x, qhi.x, qlo.y, qhi.y, kb.x, kb.y);
                }
            }
            __syncthreads();             // all warps done reading Ks
            if (kt < qt) { loadK(kt + 1); cp_commit(); }
#pragma unroll
            for (int j = 0; j < 8; j++) {
                int c0 = kt * 128 + (8 + j) * 8 + 2 * q4;
                float e0 = (!diag || c0     <= rbase    ) ? __expf(p[j][0]) * inv0 : 0.f;
                float e1 = (!diag || c0 + 1 <= rbase    ) ? __expf(p[j][1]) * inv0 : 0.f;
                float e2 = (!diag || c0     <= rbase + 8) ? __expf(p[j][2]) * inv1 : 0.f;
                float e3 = (!diag || c0 + 1 <= rbase + 8) ? __expf(p[j][3]) * inv1 : 0.f;
                *(float2*)&A[row0 + c0] = make_float2(e0, e1);
                *(float2*)&A[row1 + c0] = make_float2(e2, e3);
            }
        }
        int cEnd = (qt + 1) * 128;
        int nz4 = (Sq - cEnd) >> 2;
        if (nz4 > 0) {
            float4 z4 = make_float4(0.f, 0.f, 0.f, 0.f);
            for (int i = tid; i < 128 * nz4; i += 256) {
                int r = i / nz4, c = (i - r * nz4) * 4;
                *(float4*)&A[(long long)(qt * 128 + r) * Sq + cEnd + c] = z4;
            }
        }
    }
}

// ---------------------------------------------------------------------------
// kernel_launch
// ---------------------------------------------------------------------------
extern "C" void kernel_launch(void* const* d_in, const int* in_sizes, int n_in,
                              void* d_out, int out_size)
{
    const float* q  = (const float*)d_in[0];
    const float* k  = (const float*)d_in[1];
    const float* v  = (const float*)d_in[2];
    // d_in[3] = causal tril mask (handled analytically)
    const float* wq = (const float*)d_in[4];
    const float* bq = (const float*)d_in[5];
    const float* wk = (const float*)d_in[6];
    const float* bk = (const float*)d_in[7];
    const float* wv = (const float*)d_in[8];
    const float* bv = (const float*)d_in[9];
    const float* wo = (const float*)d_in[10];
    const float* bo = (const float*)d_in[11];
    float* out = (float*)d_out;

    unsigned *qh, *kh, *vh, *ctx, *pwq, *pwk, *pwv, *pwo;
    cudaGetSymbolAddress((void**)&qh,  g_qh);
    cudaGetSymbolAddress((void**)&kh,  g_kh);
    cudaGetSymbolAddress((void**)&vh,  g_vh);
    cudaGetSymbolAddress((void**)&ctx, g_ctx);
    cudaGetSymbolAddress((void**)&pwq, g_wq);
    cudaGetSymbolAddress((void**)&pwk, g_wk);
    cudaGetSymbolAddress((void**)&pwv, g_wv);
    cudaGetSymbolAddress((void**)&pwo, g_wo);

    const long long OUT_E  = (long long)Bq * Sq * DM;
    const long long ATTN_E = (long long)Bq * Hq * Sq * Sq;
    int write_attn = ((long long)out_size >= OUT_E + ATTN_E) ? 1 : 0;
    float* attn = out + OUT_E;

    static int attr_done = 0;
    if (!attr_done) {
        cudaFuncSetAttribute(gemm_tc<true, true>,
                             cudaFuncAttributeMaxDynamicSharedMemorySize, G_SMEM_BYTES);
        cudaFuncSetAttribute(gemm_tc<false, false>,
                             cudaFuncAttributeMaxDynamicSharedMemorySize, G_SMEM_BYTES);
        cudaFuncSetAttribute(attn_flash,
                             cudaFuncAttributeMaxDynamicSharedMemorySize, F_SMEM_BYTES);
        attr_done = 1;
    }

    // 0: prep — WEIGHTS only -> tf32 bits, K-permuted (~8 us)
    PrepP pp;
    pp.in[0] = wq; pp.out[0] = pwq;
    pp.in[1] = wk; pp.out[1] = pwk;
    pp.in[2] = wv; pp.out[2] = pwv;
    pp.in[3] = wo; pp.out[3] = pwo;
    prep_cvt<<<dim3((DM * DM) / (256 * 4), 4), 256>>>(pp);

    // 1: fused QKV projections (A raw fp32 + cvt; B raw tf32 paired)
    GemmP pq = {};
    pq.X  = (const unsigned*)q; pq.W  = pwq; pq.b0_ = bq; pq.Y  = qh;
    pq.X1 = (const unsigned*)k; pq.W1 = pwk; pq.b1_ = bk; pq.Y1 = kh;
    pq.X2 = (const unsigned*)v; pq.W2 = pwv; pq.b2_ = bv; pq.Y2 = vh;
    pq.M = Bq * Sq; pq.N = DM; pq.K = DM; pq.qkv = 1;
    pq.ps[0] = 0.125f; pq.ps[1] = 1.f; pq.ps[2] = 1.f;
    pq.nperm[0] = 1; pq.nperm[1] = 1; pq.nperm[2] = 2;
    gemm_tc<true, true><<<dim3(DM / 128, (Bq * Sq) / 128, 3), 256, G_SMEM_BYTES>>>(pq);

    // 2: fused flash attention (2 CTAs/SM; pipelined; shuffle-free PV)
    attn_flash<<<dim3(Sq / 128, Bq * Hq, 1), 256, F_SMEM_BYTES>>>(
        qh, kh, vh, ctx, attn, write_attn);

    // 3: out = ctx @ wo^T + bo (both operands raw tf32 paired)
    GemmP po = {};
    po.X = ctx; po.W = pwo; po.b0_ = bo; po.Y = out;
    po.M = Bq * Sq; po.N = DM; po.K = DM; po.qkv = 0;
    po.ps[0] = 1.f; po.nperm[0] = 0;
    gemm_tc<false, false><<<dim3(DM / 128, (Bq * Sq) / 128, 1), 256, G_SMEM_BYTES>>>(po);
}

// round 15
// speedup vs baseline: 1.5350x; 1.0367x over previous
#include <cuda_runtime.h>
#include <math.h>

// Problem constants
#define Bq 2
#define Sq 2048
#define DM 1024
#define Hq 16
#define DHq 64

// ---------------------------------------------------------------------------
// Scratch (__device__ globals)
// tf32 BIT PATTERNS; K/D perm within 8-groups: k -> ((k&3)<<1)|(k>>2)
// qh carries the 1/8 score scale. vh transposed per 128-tile: [z][kt][d][128],
// natural row order (PV uses the delta=perm8 k-relabeling).
// ---------------------------------------------------------------------------
__device__ unsigned g_qh [(size_t)Bq * Hq * Sq * DHq];   // tf32, d-perm, x0.125
__device__ unsigned g_kh [(size_t)Bq * Hq * Sq * DHq];   // tf32, d-perm
__device__ unsigned g_vh [(size_t)Bq * Hq * Sq * DHq];   // [z][16][64][128] tf32
__device__ unsigned g_ctx[(size_t)Bq * Sq * DM];          // tf32, d-perm
__device__ float    g_linv[(size_t)Bq * Hq * Sq];         // per-row 1/l
__device__ unsigned g_wq[(size_t)DM * DM];                // weights tf32, k-perm
__device__ unsigned g_wk[(size_t)DM * DM];
__device__ unsigned g_wv[(size_t)DM * DM];
__device__ unsigned g_wo[(size_t)DM * DM];

// ---------------------------------------------------------------------------
// Helpers
// ---------------------------------------------------------------------------
__device__ __forceinline__ unsigned f2tf32(float f) {
    unsigned r; asm("cvt.rna.tf32.f32 %0, %1;" : "=r"(r) : "f"(f)); return r;
}
__device__ __forceinline__ int perm8(int r) { return ((r & 3) << 1) | (r >> 2); }
__device__ __forceinline__ void cpa16(void* dst, const void* src) {
    unsigned d = (unsigned)__cvta_generic_to_shared(dst);
    asm volatile("cp.async.cg.shared.global [%0], [%1], 16;" :: "r"(d), "l"(src));
}
__device__ __forceinline__ void cp_commit() { asm volatile("cp.async.commit_group;"); }
__device__ __forceinline__ void cp_wait1()  { asm volatile("cp.async.wait_group 1;"); }
__device__ __forceinline__ void cp_wait0()  { asm volatile("cp.async.wait_group 0;"); }

__device__ __forceinline__ void mma8(float* c, unsigned a0, unsigned a1, unsigned a2,
                                     unsigned a3, unsigned b0, unsigned b1) {
    asm volatile(
        "mma.sync.aligned.m16n8k8.row.col.f32.tf32.tf32.f32 "
        "{%0,%1,%2,%3}, {%4,%5,%6,%7}, {%8,%9}, {%0,%1,%2,%3};"
        : "+f"(c[0]), "+f"(c[1]), "+f"(c[2]), "+f"(c[3])
        : "r"(a0), "r"(a1), "r"(a2), "r"(a3), "r"(b0), "r"(b1));
}

// ---------------------------------------------------------------------------
// Prep: WEIGHTS ONLY -> tf32 bits, K-dim permuted within 8-groups.
// ---------------------------------------------------------------------------
struct PrepP { const float* in[4]; unsigned* out[4]; };

__global__ __launch_bounds__(256)
void prep_cvt(PrepP pp)
{
    int z = blockIdx.y;
    int idx4 = (blockIdx.x * 256 + threadIdx.x) * 4;
    const float* in = pp.in[z];
    unsigned* out = pp.out[z];
    float4 v = *(const float4*)&in[idx4];
    int base = idx4 & ~7;
    int off  = (idx4 & 7) ? 1 : 0;
    out[base + off + 0] = f2tf32(v.x);
    out[base + off + 2] = f2tf32(v.y);
    out[base + off + 4] = f2tf32(v.z);
    out[base + off + 6] = f2tf32(v.w);
}

// ---------------------------------------------------------------------------
// QKV GEMM (A raw fp32 + cvt; W tf32 k-perm paired). Head-layout epilogues:
// nperm 1 = d-perm scatter (q/k); 2 = transposed V tile, natural rows.
// ---------------------------------------------------------------------------
struct GemmP {
    const unsigned *X, *X1, *X2;
    const unsigned *W, *W1, *W2;
    const float *b0_, *b1_, *b2_;
    void *Y, *Y1, *Y2;
    int K;
    float ps[3];
    int nperm[3];
};

#define BUF_WORDS 5120     // 128*40
#define G_SMEM_BYTES (4 * BUF_WORDS * 4)

__global__ __launch_bounds__(256, 2)
void gemm_qkv(GemmP p)
{
    constexpr int ASA = 36;
    constexpr int ASB = 40;

    const int m0 = blockIdx.y * 128;
    const int n0 = blockIdx.x * 128;
    const int z  = blockIdx.z;
    const int tid = threadIdx.x, lane = tid & 31, warp = tid >> 5;
    const int wm = warp & 1, wn = warp >> 1;

    const unsigned *X = p.X, *W = p.W; const float* bias = p.b0_; void* Y = p.Y;
    float pscale = p.ps[0]; int nperm = p.nperm[0];
    if (z == 1) { X = p.X1; W = p.W1; bias = p.b1_; Y = p.Y1; pscale = p.ps[1]; nperm = p.nperm[1]; }
    else if (z == 2) { X = p.X2; W = p.W2; bias = p.b2_; Y = p.Y2; pscale = p.ps[2]; nperm = p.nperm[2]; }

    extern __shared__ unsigned smu[];
    unsigned* Abuf[2] = { smu,                 smu + BUF_WORDS     };
    unsigned* Bbuf[2] = { smu + 2 * BUF_WORDS, smu + 3 * BUF_WORDS };

    auto loadA = [&](unsigned* As_, int k0) {
        int r0 = tid >> 3, c = (tid & 7) * 4;
#pragma unroll
        for (int it = 0; it < 4; it++) {
            int r = r0 + it * 32;
            cpa16(&As_[r * ASA + c], &X[(long long)(m0 + r) * p.K + k0 + c]);
        }
    };
    auto loadB = [&](unsigned* Bs_, int k0) {
        int r0 = tid >> 3, c = (tid & 7) * 4;
#pragma unroll
        for (int it = 0; it < 4; it++) {
            int r = r0 + it * 32;
            cpa16(&Bs_[r * ASB + c], &W[(long long)(n0 + r) * p.K + k0 + c]);
        }
    };

    float acc[4][4][4] = {};

    loadA(Abuf[0], 0); loadB(Bbuf[0], 0); cp_commit();
    int st = 0;
    for (int k0 = 0; k0 < p.K; k0 += 32) {
        if (k0 + 32 < p.K) { loadA(Abuf[st ^ 1], k0 + 32); loadB(Bbuf[st ^ 1], k0 + 32); }
        cp_commit();
        cp_wait1();
        __syncthreads();

        const unsigned* As_ = Abuf[st];
        const unsigned* Bs_ = Bbuf[st];
        const float* Af = (const float*)As_;
#pragma unroll
        for (int kk = 0; kk < 32; kk += 8) {
            const int kc = kk + (lane & 3);
            const int kp = kk + 2 * (lane & 3);
            unsigned a[4][4];
#pragma unroll
            for (int i = 0; i < 4; i++) {
                int mr = wm * 64 + i * 16 + (lane >> 2);
                a[i][0] = f2tf32(Af[mr * ASA + kc]);
                a[i][1] = f2tf32(Af[(mr + 8) * ASA + kc]);
                a[i][2] = f2tf32(Af[mr * ASA + kc + 4]);
                a[i][3] = f2tf32(Af[(mr + 8) * ASA + kc + 4]);
            }
            unsigned b[4][2];
#pragma unroll
            for (int j = 0; j < 4; j++) {
                int nr = wn * 32 + j * 8 + (lane >> 2);
                uint2 bb = *(const uint2*)&Bs_[nr * ASB + kp];
                b[j][0] = bb.x; b[j][1] = bb.y;
            }
#pragma unroll
            for (int i = 0; i < 4; i++)
#pragma unroll
                for (int j = 0; j < 4; j++)
                    mma8(acc[i][j], a[i][0], a[i][1], a[i][2], a[i][3], b[j][0], b[j][1]);
        }
        __syncthreads();
        st ^= 1;
    }

#pragma unroll
    for (int i = 0; i < 4; i++)
#pragma unroll
        for (int j = 0; j < 4; j++)
#pragma unroll
            for (int h = 0; h < 2; h++) {
                int m = m0 + wm * 64 + i * 16 + (lane >> 2) + h * 8;
                int n = n0 + wn * 32 + j * 8 + (lane & 3) * 2;
                float v0 = acc[i][j][h * 2]     + bias[n];
                float v1 = acc[i][j][h * 2 + 1] + bias[n + 1];
                int b_ = m >> 11;
                int s  = m & (Sq - 1);
                int hh = n >> 6;
                int d  = n & (DHq - 1);
                unsigned u0 = f2tf32(v0 * pscale);
                unsigned u1 = f2tf32(v1 * pscale);
                unsigned* Yu = (unsigned*)Y;
                int zz = b_ * Hq + hh;
                if (nperm == 2) {
                    long long a0 = (((long long)zz * 16 + (s >> 7)) * 64 + d) * 128 + (s & 127);
                    Yu[a0]       = u0;
                    Yu[a0 + 128] = u1;
                } else {
                    long long rowb = ((long long)zz * Sq + s) * DHq;
                    int r0 = d & 7;
                    Yu[rowb + (d & ~7) + perm8(r0)]     = u0;
                    Yu[rowb + (d & ~7) + perm8(r0 + 1)] = u1;
                }
            }
}

// ---------------------------------------------------------------------------
// Flash pass A only: ctx + row inverse sums. (Pass B moved to fused_bo.)
// 256 threads, 8 warps x 16 rows, 2 CTAs/SM, pipelined K/V prefetch,
// shuffle-free PV via delta=perm8 k-relabeling.
// ---------------------------------------------------------------------------
#define QST 72
#define KST 72
#define VST 136
#define FK_OFF 9216
#define FV_OFF 18432
#define F_SMEM_BYTES (27136 * 4)

__global__ __launch_bounds__(256, 2)
void attn_flash_a(const unsigned* __restrict__ qh, const unsigned* __restrict__ kh,
                  const unsigned* __restrict__ vhT, unsigned* __restrict__ ctx,
                  float* __restrict__ linv)
{
    const int qt = (int)gridDim.x - 1 - (int)blockIdx.x;
    const int z  = blockIdx.y;
    const int tid = threadIdx.x, lane = tid & 31, warp = tid >> 5;

    extern __shared__ unsigned smu[];
    unsigned* Qs = smu;
    unsigned* Ks = smu + FK_OFF;
    unsigned* Vs = smu + FV_OFF;

    const unsigned* Qg  = qh  + ((long long)z * Sq + qt * 128) * DHq;
    const unsigned* Kg  = kh  + (long long)z * Sq * DHq;
    const unsigned* VgT = vhT + (long long)z * Sq * DHq;

    for (int i = tid; i < 128 * 16; i += 256) {
        int r = i >> 4, c4 = (i & 15) * 4;
        *(uint4*)&Qs[r * QST + c4] = *(const uint4*)&Qg[r * 64 + c4];
    }

    auto loadK = [&](int kt) {
        for (int i = tid; i < 128 * 16; i += 256) {
            int r = i >> 4, c4 = (i & 15) * 4;
            cpa16(&Ks[r * KST + c4], &Kg[((long long)kt * 128 + r) * 64 + c4]);
        }
    };
    auto loadV = [&](int kt) {
        for (int i = tid; i < 64 * 32; i += 256) {
            int d = i >> 5, c4 = (i & 31) * 4;
            cpa16(&Vs[d * VST + c4], &VgT[(long long)kt * 8192 + d * 128 + c4]);
        }
    };

    const unsigned* Qw = &Qs[(warp * 16) * QST];
    const int rq = lane >> 2;
    const int q4 = lane & 3;
    const int rbase = qt * 128 + warp * 16 + rq;

    float cacc[8][4] = {};
    float l0 = 0.f, l1 = 0.f;
    float p[8][4];

    loadK(0); cp_commit();
    loadV(0); cp_commit();

    for (int kt = 0; kt <= qt; kt++) {
        cp_wait1();
        __syncthreads();

        bool diag = (kt == qt);

        // S half 0 (overlaps V load)
#pragma unroll
        for (int j = 0; j < 8; j++) { p[j][0] = p[j][1] = p[j][2] = p[j][3] = 0.f; }
#pragma unroll
        for (int ks = 0; ks < 8; ks++) {
            const int kp = ks * 8 + 2 * q4;
            uint2 qlo = *(const uint2*)&Qw[rq * QST + kp];
            uint2 qhi = *(const uint2*)&Qw[(rq + 8) * QST + kp];
#pragma unroll
            for (int j = 0; j < 8; j++) {
                int n = j * 8 + rq;
                uint2 kb = *(const uint2*)&Ks[n * KST + kp];
                mma8(p[j], qlo.x, qhi.x, qlo.y, qhi.y, kb.x, kb.y);
            }
        }
#pragma unroll
        for (int j = 0; j < 8; j++) {
            int c0 = kt * 128 + j * 8 + 2 * q4;
            float e0 = (!diag || c0     <= rbase    ) ? __expf(p[j][0]) : 0.f;
            float e1 = (!diag || c0 + 1 <= rbase    ) ? __expf(p[j][1]) : 0.f;
            float e2 = (!diag || c0     <= rbase + 8) ? __expf(p[j][2]) : 0.f;
            float e3 = (!diag || c0 + 1 <= rbase + 8) ? __expf(p[j][3]) : 0.f;
            p[j][0] = e0; p[j][1] = e1; p[j][2] = e2; p[j][3] = e3;
            l0 += e0 + e1; l1 += e2 + e3;
        }

        cp_wait0();
        __syncthreads();

        // PV half 0 (A-frags straight from p registers)
#pragma unroll
        for (int t = 0; t < 8; t++) {
            unsigned a0 = f2tf32(p[t][0]);
            unsigned a1 = f2tf32(p[t][2]);
            unsigned a2 = f2tf32(p[t][1]);
            unsigned a3 = f2tf32(p[t][3]);
            int krp = t * 8 + 2 * q4;
#pragma unroll
            for (int j = 0; j < 8; j++) {
                int n = j * 8 + rq;
                uint2 vb = *(const uint2*)&Vs[n * VST + krp];
                mma8(cacc[j], a0, a1, a2, a3, vb.x, vb.y);
            }
        }

        // S half 1
#pragma unroll
        for (int j = 0; j < 8; j++) { p[j][0] = p[j][1] = p[j][2] = p[j][3] = 0.f; }
#pragma unroll
        for (int ks = 0; ks < 8; ks++) {
            const int kp = ks * 8 + 2 * q4;
            uint2 qlo = *(const uint2*)&Qw[rq * QST + kp];
            uint2 qhi = *(const uint2*)&Qw[(rq + 8) * QST + kp];
#pragma unroll
            for (int j = 0; j < 8; j++) {
                int n = (8 + j) * 8 + rq;
                uint2 kb = *(const uint2*)&Ks[n * KST + kp];
                mma8(p[j], qlo.x, qhi.x, qlo.y, qhi.y, kb.x, kb.y);
            }
        }
#pragma unroll
        for (int j = 0; j < 8; j++) {
            int c0 = kt * 128 + (8 + j) * 8 + 2 * q4;
            float e0 = (!diag || c0     <= rbase    ) ? __expf(p[j][0]) : 0.f;
            float e1 = (!diag || c0 + 1 <= rbase    ) ? __expf(p[j][1]) : 0.f;
            float e2 = (!diag || c0     <= rbase + 8) ? __expf(p[j][2]) : 0.f;
            float e3 = (!diag || c0 + 1 <= rbase + 8) ? __expf(p[j][3]) : 0.f;
            p[j][0] = e0; p[j][1] = e1; p[j][2] = e2; p[j][3] = e3;
            l0 += e0 + e1; l1 += e2 + e3;
        }

        __syncthreads();
        if (kt < qt) { loadK(kt + 1); cp_commit(); }

        // PV half 1
#pragma unroll
        for (int t = 0; t < 8; t++) {
            unsigned a0 = f2tf32(p[t][0]);
            unsigned a1 = f2tf32(p[t][2]);
            unsigned a2 = f2tf32(p[t][1]);
            unsigned a3 = f2tf32(p[t][3]);
            int krp = (8 + t) * 8 + 2 * q4;
#pragma unroll
            for (int j = 0; j < 8; j++) {
                int n = j * 8 + rq;
                uint2 vb = *(const uint2*)&Vs[n * VST + krp];
                mma8(cacc[j], a0, a1, a2, a3, vb.x, vb.y);
            }
        }

        __syncthreads();
        if (kt < qt) { loadV(kt + 1); cp_commit(); }
    }

    l0 += __shfl_xor_sync(0xffffffffu, l0, 1);
    l0 += __shfl_xor_sync(0xffffffffu, l0, 2);
    l1 += __shfl_xor_sync(0xffffffffu, l1, 1);
    l1 += __shfl_xor_sync(0xffffffffu, l1, 2);
    float inv0 = 1.0f / l0, inv1 = 1.0f / l1;

    // row inverses for pass B
    if (q4 == 0) {
        linv[(long long)z * Sq + rbase]     = inv0;
        linv[(long long)z * Sq + rbase + 8] = inv1;
    }

    // ctx epilogue -> tf32 bits, d-permuted
    {
        int b_ = z >> 4, h_ = z & 15;
        long long base0 = ((long long)b_ * Sq + rbase) * DM + h_ * 64;
        long long base1 = base0 + 8LL * DM;
        int r0 = 2 * q4;
        int p0 = perm8(r0), p1 = perm8(r0 + 1);
#pragma unroll
        for (int j = 0; j < 8; j++) {
            int g = j * 8;
            ctx[base0 + g + p0] = f2tf32(cacc[j][0] * inv0);
            ctx[base0 + g + p1] = f2tf32(cacc[j][1] * inv0);
            ctx[base1 + g + p0] = f2tf32(cacc[j][2] * inv1);
            ctx[base1 + g + p1] = f2tf32(cacc[j][3] * inv1);
        }
    }
}

// ---------------------------------------------------------------------------
// Fused tail: blocks 0..511 = attn pass B (write normalized attn, long-qt
// first); blocks 512..767 = out-projection GEMM. Independent workloads
// overlap across SM waves (memory-bound pass B + tensor-bound GEMM).
// ---------------------------------------------------------------------------
struct FuseP {
    const unsigned *ctx, *wo; const float* bo; float* Y;   // out-proj
    const unsigned *qh, *kh; float* attn; const float* linv;
    int write_attn;
};

#define FB_SMEM_BYTES (4 * BUF_WORDS * 4)   // 80 KB covers both roles

__global__ __launch_bounds__(256, 2)
void fused_bo(FuseP f)
{
    extern __shared__ unsigned smu[];
    const int tid = threadIdx.x, lane = tid & 31, warp = tid >> 5;

    if (blockIdx.x >= 512) {
        // ================= out-proj GEMM (A tf32 d-perm, W tf32 k-perm) =====
        constexpr int AS_ = 40;
        int obx = blockIdx.x - 512;
        const int n0 = (obx & 7) * 128;
        const int m0 = (obx >> 3) * 128;
        const int wm = warp & 1, wn = warp >> 1;

        unsigned* Abuf[2] = { smu,                 smu + BUF_WORDS     };
        unsigned* Bbuf[2] = { smu + 2 * BUF_WORDS, smu + 3 * BUF_WORDS };

        auto loadA = [&](unsigned* As_, int k0) {
            int r0 = tid >> 3, c = (tid & 7) * 4;
#pragma unroll
            for (int it = 0; it < 4; it++) {
                int r = r0 + it * 32;
                cpa16(&As_[r * AS_ + c], &f.ctx[(long long)(m0 + r) * DM + k0 + c]);
            }
        };
        auto loadB = [&](unsigned* Bs_, int k0) {
            int r0 = tid >> 3, c = (tid & 7) * 4;
#pragma unroll
            for (int it = 0; it < 4; it++) {
                int r = r0 + it * 32;
                cpa16(&Bs_[r * AS_ + c], &f.wo[(long long)(n0 + r) * DM + k0 + c]);
            }
        };

        float acc[4][4][4] = {};
        loadA(Abuf[0], 0); loadB(Bbuf[0], 0); cp_commit();
        int st = 0;
        for (int k0 = 0; k0 < DM; k0 += 32) {
            if (k0 + 32 < DM) { loadA(Abuf[st ^ 1], k0 + 32); loadB(Bbuf[st ^ 1], k0 + 32); }
            cp_commit();
            cp_wait1();
            __syncthreads();

            const unsigned* As_ = Abuf[st];
            const unsigned* Bs_ = Bbuf[st];
#pragma unroll
            for (int kk = 0; kk < 32; kk += 8) {
                const int kp = kk + 2 * (lane & 3);
                unsigned a[4][4];
#pragma unroll
                for (int i = 0; i < 4; i++) {
                    int mr = wm * 64 + i * 16 + (lane >> 2);
                    uint2 lo = *(const uint2*)&As_[mr * AS_ + kp];
                    uint2 hi = *(const uint2*)&As_[(mr + 8) * AS_ + kp];
                    a[i][0] = lo.x; a[i][1] = hi.x; a[i][2] = lo.y; a[i][3] = hi.y;
                }
                unsigned b[4][2];
#pragma unroll
                for (int j = 0; j < 4; j++) {
                    int nr = wn * 32 + j * 8 + (lane >> 2);
                    uint2 bb = *(const uint2*)&Bs_[nr * AS_ + kp];
                    b[j][0] = bb.x; b[j][1] = bb.y;
                }
#pragma unroll
                for (int i = 0; i < 4; i++)
#pragma unroll
                    for (int j = 0; j < 4; j++)
                        mma8(acc[i][j], a[i][0], a[i][1], a[i][2], a[i][3], b[j][0], b[j][1]);
            }
            __syncthreads();
            st ^= 1;
        }

#pragma unroll
        for (int i = 0; i < 4; i++)
#pragma unroll
            for (int j = 0; j < 4; j++)
#pragma unroll
                for (int h = 0; h < 2; h++) {
                    int m = m0 + wm * 64 + i * 16 + (lane >> 2) + h * 8;
                    int n = n0 + wn * 32 + j * 8 + (lane & 3) * 2;
                    float v0 = acc[i][j][h * 2]     + f.bo[n];
                    float v1 = acc[i][j][h * 2 + 1] + f.bo[n + 1];
                    *(float2*)&f.Y[(long long)m * DM + n] = make_float2(v0, v1);
                }
        return;
    }

    // ================= attn pass B =========================================
    if (!f.write_attn) return;
    const int z  = blockIdx.x & 31;
    const int qt = 15 - ((int)blockIdx.x >> 5);      // long blocks first

    unsigned* Qs = smu;
    unsigned* Ks = smu + FK_OFF;

    const unsigned* Qg = f.qh + ((long long)z * Sq + qt * 128) * DHq;
    const unsigned* Kg = f.kh + (long long)z * Sq * DHq;
    float* A = f.attn + (long long)z * Sq * Sq;

    for (int i = tid; i < 128 * 16; i += 256) {
        int r = i >> 4, c4 = (i & 15) * 4;
        *(uint4*)&Qs[r * QST + c4] = *(const uint4*)&Qg[r * 64 + c4];
    }

    auto loadK = [&](int kt) {
        for (int i = tid; i < 128 * 16; i += 256) {
            int r = i >> 4, c4 = (i & 15) * 4;
            cpa16(&Ks[r * KST + c4], &Kg[((long long)kt * 128 + r) * 64 + c4]);
        }
    };

    const unsigned* Qw = &Qs[(warp * 16) * QST];
    const int rq = lane >> 2;
    const int q4 = lane & 3;
    const int rbase = qt * 128 + warp * 16 + rq;

    float inv0 = f.linv[(long long)z * Sq + rbase];
    float inv1 = f.linv[(long long)z * Sq + rbase + 8];

    float p[8][4];

    loadK(0); cp_commit();
    for (int kt = 0; kt <= qt; kt++) {
        cp_wait0();
        __syncthreads();

        bool diag = (kt == qt);
        long long row0 = (long long)rbase * Sq;
        long long row1 = (long long)(rbase + 8) * Sq;

        // S half 0 + write
#pragma unroll
        for (int j = 0; j < 8; j++) { p[j][0] = p[j][1] = p[j][2] = p[j][3] = 0.f; }
#pragma unroll
        for (int ks = 0; ks < 8; ks++) {
            const int kp = ks * 8 + 2 * q4;
            uint2 qlo = *(const uint2*)&Qw[rq * QST + kp];
            uint2 qhi = *(const uint2*)&Qw[(rq + 8) * QST + kp];
#pragma unroll
            for (int j = 0; j < 8; j++) {
                int n = j * 8 + rq;
                uint2 kb = *(const uint2*)&Ks[n * KST + kp];
                mma8(p[j], qlo.x, qhi.x, qlo.y, qhi.y, kb.x, kb.y);
            }
        }
#pragma unroll
        for (int j = 0; j < 8; j++) {
            int c0 = kt * 128 + j * 8 + 2 * q4;
            float e0 = (!diag || c0     <= rbase    ) ? __expf(p[j][0]) * inv0 : 0.f;
            float e1 = (!diag || c0 + 1 <= rbase    ) ? __expf(p[j][1]) * inv0 : 0.f;
            float e2 = (!diag || c0     <= rbase + 8) ? __expf(p[j][2]) * inv1 : 0.f;
            float e3 = (!diag || c0 + 1 <= rbase + 8) ? __expf(p[j][3]) * inv1 : 0.f;
            *(float2*)&A[row0 + c0] = make_float2(e0, e1);
            *(float2*)&A[row1 + c0] = make_float2(e2, e3);
        }

        // S half 1 mma, prefetch K overlapped with epilogue
#pragma unroll
        for (int j = 0; j < 8; j++) { p[j][0] = p[j][1] = p[j][2] = p[j][3] = 0.f; }
#pragma unroll
        for (int ks = 0; ks < 8; ks++) {
            const int kp = ks * 8 + 2 * q4;
            uint2 qlo = *(const uint2*)&Qw[rq * QST + kp];
            uint2 qhi = *(const uint2*)&Qw[(rq + 8) * QST + kp];
#pragma unroll
            for (int j = 0; j < 8; j++) {
                int n = (8 + j) * 8 + rq;
                uint2 kb = *(const uint2*)&Ks[n * KST + kp];
                mma8(p[j], qlo.x, qhi.x, qlo.y, qhi.y, kb.x, kb.y);
            }
        }
        __syncthreads();
        if (kt < qt) { loadK(kt + 1); cp_commit(); }
#pragma unroll
        for (int j = 0; j < 8; j++) {
            int c0 = kt * 128 + (8 + j) * 8 + 2 * q4;
            float e0 = (!diag || c0     <= rbase    ) ? __expf(p[j][0]) * inv0 : 0.f;
            float e1 = (!diag || c0 + 1 <= rbase    ) ? __expf(p[j][1]) * inv0 : 0.f;
            float e2 = (!diag || c0     <= rbase + 8) ? __expf(p[j][2]) * inv1 : 0.f;
            float e3 = (!diag || c0 + 1 <= rbase + 8) ? __expf(p[j][3]) * inv1 : 0.f;
            *(float2*)&A[row0 + c0] = make_float2(e0, e1);
            *(float2*)&A[row1 + c0] = make_float2(e2, e3);
        }
    }

    // zero-fill the strictly-causal-upper region
    int cEnd = (qt + 1) * 128;
    int nz4 = (Sq - cEnd) >> 2;
    if (nz4 > 0) {
        float4 z4 = make_float4(0.f, 0.f, 0.f, 0.f);
        for (int i = tid; i < 128 * nz4; i += 256) {
            int r = i / nz4, c = (i - r * nz4) * 4;
            *(float4*)&A[(long long)(qt * 128 + r) * Sq + cEnd + c] = z4;
        }
    }
}

// ---------------------------------------------------------------------------
// kernel_launch
// ---------------------------------------------------------------------------
extern "C" void kernel_launch(void* const* d_in, const int* in_sizes, int n_in,
                              void* d_out, int out_size)
{
    const float* q  = (const float*)d_in[0];
    const float* k  = (const float*)d_in[1];
    const float* v  = (const float*)d_in[2];
    // d_in[3] = causal tril mask (handled analytically)
    const float* wq = (const float*)d_in[4];
    const float* bq = (const float*)d_in[5];
    const float* wk = (const float*)d_in[6];
    const float* bk = (const float*)d_in[7];
    const float* wv = (const float*)d_in[8];
    const float* bv = (const float*)d_in[9];
    const float* wo = (const float*)d_in[10];
    const float* bo = (const float*)d_in[11];
    float* out = (float*)d_out;

    unsigned *qh, *kh, *vh, *ctx, *pwq, *pwk, *pwv, *pwo;
    float* linv;
    cudaGetSymbolAddress((void**)&qh,   g_qh);
    cudaGetSymbolAddress((void**)&kh,   g_kh);
    cudaGetSymbolAddress((void**)&vh,   g_vh);
    cudaGetSymbolAddress((void**)&ctx,  g_ctx);
    cudaGetSymbolAddress((void**)&linv, g_linv);
    cudaGetSymbolAddress((void**)&pwq,  g_wq);
    cudaGetSymbolAddress((void**)&pwk,  g_wk);
    cudaGetSymbolAddress((void**)&pwv,  g_wv);
    cudaGetSymbolAddress((void**)&pwo,  g_wo);

    const long long OUT_E  = (long long)Bq * Sq * DM;
    const long long ATTN_E = (long long)Bq * Hq * Sq * Sq;
    int write_attn = ((long long)out_size >= OUT_E + ATTN_E) ? 1 : 0;
    float* attn = out + OUT_E;

    static int attr_done = 0;
    if (!attr_done) {
        cudaFuncSetAttribute(gemm_qkv,
                             cudaFuncAttributeMaxDynamicSharedMemorySize, G_SMEM_BYTES);
        cudaFuncSetAttribute(attn_flash_a,
                             cudaFuncAttributeMaxDynamicSharedMemorySize, F_SMEM_BYTES);
        cudaFuncSetAttribute(fused_bo,
                             cudaFuncAttributeMaxDynamicSharedMemorySize, FB_SMEM_BYTES);
        attr_done = 1;
    }

    // 0: prep — WEIGHTS only -> tf32 bits, K-permuted
    PrepP pp;
    pp.in[0] = wq; pp.out[0] = pwq;
    pp.in[1] = wk; pp.out[1] = pwk;
    pp.in[2] = wv; pp.out[2] = pwv;
    pp.in[3] = wo; pp.out[3] = pwo;
    prep_cvt<<<dim3((DM * DM) / (256 * 4), 4), 256>>>(pp);

    // 1: fused QKV projections
    GemmP pq = {};
    pq.X  = (const unsigned*)q; pq.W  = pwq; pq.b0_ = bq; pq.Y  = qh;
    pq.X1 = (const unsigned*)k; pq.W1 = pwk; pq.b1_ = bk; pq.Y1 = kh;
    pq.X2 = (const unsigned*)v; pq.W2 = pwv; pq.b2_ = bv; pq.Y2 = vh;
    pq.K = DM;
    pq.ps[0] = 0.125f; pq.ps[1] = 1.f; pq.ps[2] = 1.f;
    pq.nperm[0] = 1; pq.nperm[1] = 1; pq.nperm[2] = 2;
    gemm_qkv<<<dim3(DM / 128, (Bq * Sq) / 128, 3), 256, G_SMEM_BYTES>>>(pq);

    // 2: flash pass A (ctx + row inverses)
    attn_flash_a<<<dim3(Sq / 128, Bq * Hq, 1), 256, F_SMEM_BYTES>>>(
        qh, kh, vh, ctx, linv);

    // 3: fused tail — attn pass B (512 blocks) + out-proj (256 blocks)
    FuseP f = {};
    f.ctx = ctx; f.wo = pwo; f.bo = bo; f.Y = out;
    f.qh = qh; f.kh = kh; f.attn = attn; f.linv = linv;
    f.write_attn = write_attn;
    fused_bo<<<768, 256, FB_SMEM_BYTES>>>(f);
}

// round 16
// speedup vs baseline: 1.5418x; 1.0044x over previous
#include <cuda_runtime.h>
#include <math.h>

// Problem constants
#define Bq 2
#define Sq 2048
#define DM 1024
#define Hq 16
#define DHq 64

// ---------------------------------------------------------------------------
// Scratch (__device__ globals)
// tf32 BIT PATTERNS; K/D perm within 8-groups: k -> ((k&3)<<1)|(k>>2)
// qh carries the 1/8 score scale. vh transposed per 128-tile: [z][kt][d][128],
// natural row order (PV uses the delta=perm8 k-relabeling).
// ---------------------------------------------------------------------------
__device__ unsigned g_qh [(size_t)Bq * Hq * Sq * DHq];   // tf32, d-perm, x0.125
__device__ unsigned g_kh [(size_t)Bq * Hq * Sq * DHq];   // tf32, d-perm
__device__ unsigned g_vh [(size_t)Bq * Hq * Sq * DHq];   // [z][16][64][128] tf32
__device__ unsigned g_ctx[(size_t)Bq * Sq * DM];          // tf32, d-perm
__device__ float    g_linv[(size_t)Bq * Hq * Sq];         // per-row 1/l
__device__ unsigned g_wq[(size_t)DM * DM];                // weights tf32, k-perm
__device__ unsigned g_wk[(size_t)DM * DM];
__device__ unsigned g_wv[(size_t)DM * DM];
__device__ unsigned g_wo[(size_t)DM * DM];

// ---------------------------------------------------------------------------
// Helpers
// ---------------------------------------------------------------------------
__device__ __forceinline__ unsigned f2tf32(float f) {
    unsigned r; asm("cvt.rna.tf32.f32 %0, %1;" : "=r"(r) : "f"(f)); return r;
}
__device__ __forceinline__ int perm8(int r) { return ((r & 3) << 1) | (r >> 2); }
__device__ __forceinline__ void cpa16(void* dst, const void* src) {
    unsigned d = (unsigned)__cvta_generic_to_shared(dst);
    asm volatile("cp.async.cg.shared.global [%0], [%1], 16;" :: "r"(d), "l"(src));
}
__device__ __forceinline__ void cp_commit() { asm volatile("cp.async.commit_group;"); }
__device__ __forceinline__ void cp_wait1()  { asm volatile("cp.async.wait_group 1;"); }
__device__ __forceinline__ void cp_wait0()  { asm volatile("cp.async.wait_group 0;"); }

__device__ __forceinline__ void mma8(float* c, unsigned a0, unsigned a1, unsigned a2,
                                     unsigned a3, unsigned b0, unsigned b1) {
    asm volatile(
        "mma.sync.aligned.m16n8k8.row.col.f32.tf32.tf32.f32 "
        "{%0,%1,%2,%3}, {%4,%5,%6,%7}, {%8,%9}, {%0,%1,%2,%3};"
        : "+f"(c[0]), "+f"(c[1]), "+f"(c[2]), "+f"(c[3])
        : "r"(a0), "r"(a1), "r"(a2), "r"(a3), "r"(b0), "r"(b1));
}

// ---------------------------------------------------------------------------
// Prep: WEIGHTS ONLY -> tf32 bits, K-dim permuted within 8-groups.
// ---------------------------------------------------------------------------
struct PrepP { const float* in[4]; unsigned* out[4]; };

__global__ __launch_bounds__(256)
void prep_cvt(PrepP pp)
{
    int z = blockIdx.y;
    int idx4 = (blockIdx.x * 256 + threadIdx.x) * 4;
    const float* in = pp.in[z];
    unsigned* out = pp.out[z];
    float4 v = *(const float4*)&in[idx4];
    int base = idx4 & ~7;
    int off  = (idx4 & 7) ? 1 : 0;
    out[base + off + 0] = f2tf32(v.x);
    out[base + off + 2] = f2tf32(v.y);
    out[base + off + 4] = f2tf32(v.z);
    out[base + off + 6] = f2tf32(v.w);
}

// ---------------------------------------------------------------------------
// QKV GEMM (A raw fp32 + cvt; W tf32 k-perm paired). Head-layout epilogues:
// nperm 1 = d-perm scatter (q/k); 2 = transposed V tile, natural rows.
// ---------------------------------------------------------------------------
struct GemmP {
    const unsigned *X, *X1, *X2;
    const unsigned *W, *W1, *W2;
    const float *b0_, *b1_, *b2_;
    void *Y, *Y1, *Y2;
    int K;
    float ps[3];
    int nperm[3];
};

#define BUF_WORDS 5120     // 128*40
#define G_SMEM_BYTES (4 * BUF_WORDS * 4)

__global__ __launch_bounds__(256, 2)
void gemm_qkv(GemmP p)
{
    constexpr int ASA = 36;
    constexpr int ASB = 40;

    const int m0 = blockIdx.y * 128;
    const int n0 = blockIdx.x * 128;
    const int z  = blockIdx.z;
    const int tid = threadIdx.x, lane = tid & 31, warp = tid >> 5;
    const int wm = warp & 1, wn = warp >> 1;

    const unsigned *X = p.X, *W = p.W; const float* bias = p.b0_; void* Y = p.Y;
    float pscale = p.ps[0]; int nperm = p.nperm[0];
    if (z == 1) { X = p.X1; W = p.W1; bias = p.b1_; Y = p.Y1; pscale = p.ps[1]; nperm = p.nperm[1]; }
    else if (z == 2) { X = p.X2; W = p.W2; bias = p.b2_; Y = p.Y2; pscale = p.ps[2]; nperm = p.nperm[2]; }

    extern __shared__ unsigned smu[];
    unsigned* Abuf[2] = { smu,                 smu + BUF_WORDS     };
    unsigned* Bbuf[2] = { smu + 2 * BUF_WORDS, smu + 3 * BUF_WORDS };

    auto loadA = [&](unsigned* As_, int k0) {
        int r0 = tid >> 3, c = (tid & 7) * 4;
#pragma unroll
        for (int it = 0; it < 4; it++) {
            int r = r0 + it * 32;
            cpa16(&As_[r * ASA + c], &X[(long long)(m0 + r) * p.K + k0 + c]);
        }
    };
    auto loadB = [&](unsigned* Bs_, int k0) {
        int r0 = tid >> 3, c = (tid & 7) * 4;
#pragma unroll
        for (int it = 0; it < 4; it++) {
            int r = r0 + it * 32;
            cpa16(&Bs_[r * ASB + c], &W[(long long)(n0 + r) * p.K + k0 + c]);
        }
    };

    float acc[4][4][4] = {};

    loadA(Abuf[0], 0); loadB(Bbuf[0], 0); cp_commit();
    int st = 0;
    for (int k0 = 0; k0 < p.K; k0 += 32) {
        if (k0 + 32 < p.K) { loadA(Abuf[st ^ 1], k0 + 32); loadB(Bbuf[st ^ 1], k0 + 32); }
        cp_commit();
        cp_wait1();
        __syncthreads();

        const unsigned* As_ = Abuf[st];
        const unsigned* Bs_ = Bbuf[st];
        const float* Af = (const float*)As_;
#pragma unroll
        for (int kk = 0; kk < 32; kk += 8) {
            const int kc = kk + (lane & 3);
            const int kp = kk + 2 * (lane & 3);
            unsigned a[4][4];
#pragma unroll
            for (int i = 0; i < 4; i++) {
                int mr = wm * 64 + i * 16 + (lane >> 2);
                a[i][0] = f2tf32(Af[mr * ASA + kc]);
                a[i][1] = f2tf32(Af[(mr + 8) * ASA + kc]);
                a[i][2] = f2tf32(Af[mr * ASA + kc + 4]);
                a[i][3] = f2tf32(Af[(mr + 8) * ASA + kc + 4]);
            }
            unsigned b[4][2];
#pragma unroll
            for (int j = 0; j < 4; j++) {
                int nr = wn * 32 + j * 8 + (lane >> 2);
                uint2 bb = *(const uint2*)&Bs_[nr * ASB + kp];
                b[j][0] = bb.x; b[j][1] = bb.y;
            }
#pragma unroll
            for (int i = 0; i < 4; i++)
#pragma unroll
                for (int j = 0; j < 4; j++)
                    mma8(acc[i][j], a[i][0], a[i][1], a[i][2], a[i][3], b[j][0], b[j][1]);
        }
        __syncthreads();
        st ^= 1;
    }

#pragma unroll
    for (int i = 0; i < 4; i++)
#pragma unroll
        for (int j = 0; j < 4; j++)
#pragma unroll
            for (int h = 0; h < 2; h++) {
                int m = m0 + wm * 64 + i * 16 + (lane >> 2) + h * 8;
                int n = n0 + wn * 32 + j * 8 + (lane & 3) * 2;
                float v0 = acc[i][j][h * 2]     + bias[n];
                float v1 = acc[i][j][h * 2 + 1] + bias[n + 1];
                int b_ = m >> 11;
                int s  = m & (Sq - 1);
                int hh = n >> 6;
                int d  = n & (DHq - 1);
                unsigned u0 = f2tf32(v0 * pscale);
                unsigned u1 = f2tf32(v1 * pscale);
                unsigned* Yu = (unsigned*)Y;
                int zz = b_ * Hq + hh;
                if (nperm == 2) {
                    long long a0 = (((long long)zz * 16 + (s >> 7)) * 64 + d) * 128 + (s & 127);
                    Yu[a0]       = u0;
                    Yu[a0 + 128] = u1;
                } else {
                    long long rowb = ((long long)zz * Sq + s) * DHq;
                    int r0 = d & 7;
                    Yu[rowb + (d & ~7) + perm8(r0)]     = u0;
                    Yu[rowb + (d & ~7) + perm8(r0 + 1)] = u1;
                }
            }
}

// ---------------------------------------------------------------------------
// Flash pass A only: ctx + row inverse sums.
// 256 threads, 8 warps x 16 rows, 2 CTAs/SM, pipelined K/V prefetch,
// shuffle-free PV via delta=perm8 k-relabeling.
// ---------------------------------------------------------------------------
#define QST 72
#define KST 72
#define VST 136
#define FK_OFF 9216
#define FV_OFF 18432
#define F_SMEM_BYTES (27136 * 4)

__global__ __launch_bounds__(256, 2)
void attn_flash_a(const unsigned* __restrict__ qh, const unsigned* __restrict__ kh,
                  const unsigned* __restrict__ vhT, unsigned* __restrict__ ctx,
                  float* __restrict__ linv)
{
    const int qt = (int)gridDim.x - 1 - (int)blockIdx.x;
    const int z  = blockIdx.y;
    const int tid = threadIdx.x, lane = tid & 31, warp = tid >> 5;

    extern __shared__ unsigned smu[];
    unsigned* Qs = smu;
    unsigned* Ks = smu + FK_OFF;
    unsigned* Vs = smu + FV_OFF;

    const unsigned* Qg  = qh  + ((long long)z * Sq + qt * 128) * DHq;
    const unsigned* Kg  = kh  + (long long)z * Sq * DHq;
    const unsigned* VgT = vhT + (long long)z * Sq * DHq;

    for (int i = tid; i < 128 * 16; i += 256) {
        int r = i >> 4, c4 = (i & 15) * 4;
        *(uint4*)&Qs[r * QST + c4] = *(const uint4*)&Qg[r * 64 + c4];
    }

    auto loadK = [&](int kt) {
        for (int i = tid; i < 128 * 16; i += 256) {
            int r = i >> 4, c4 = (i & 15) * 4;
            cpa16(&Ks[r * KST + c4], &Kg[((long long)kt * 128 + r) * 64 + c4]);
        }
    };
    auto loadV = [&](int kt) {
        for (int i = tid; i < 64 * 32; i += 256) {
            int d = i >> 5, c4 = (i & 31) * 4;
            cpa16(&Vs[d * VST + c4], &VgT[(long long)kt * 8192 + d * 128 + c4]);
        }
    };

    const unsigned* Qw = &Qs[(warp * 16) * QST];
    const int rq = lane >> 2;
    const int q4 = lane & 3;
    const int rbase = qt * 128 + warp * 16 + rq;

    float cacc[8][4] = {};
    float l0 = 0.f, l1 = 0.f;
    float p[8][4];

    loadK(0); cp_commit();
    loadV(0); cp_commit();

    for (int kt = 0; kt <= qt; kt++) {
        cp_wait1();
        __syncthreads();

        bool diag = (kt == qt);

        // S half 0 (overlaps V load)
#pragma unroll
        for (int j = 0; j < 8; j++) { p[j][0] = p[j][1] = p[j][2] = p[j][3] = 0.f; }
#pragma unroll
        for (int ks = 0; ks < 8; ks++) {
            const int kp = ks * 8 + 2 * q4;
            uint2 qlo = *(const uint2*)&Qw[rq * QST + kp];
            uint2 qhi = *(const uint2*)&Qw[(rq + 8) * QST + kp];
#pragma unroll
            for (int j = 0; j < 8; j++) {
                int n = j * 8 + rq;
                uint2 kb = *(const uint2*)&Ks[n * KST + kp];
                mma8(p[j], qlo.x, qhi.x, qlo.y, qhi.y, kb.x, kb.y);
            }
        }
#pragma unroll
        for (int j = 0; j < 8; j++) {
            int c0 = kt * 128 + j * 8 + 2 * q4;
            float e0 = (!diag || c0     <= rbase    ) ? __expf(p[j][0]) : 0.f;
            float e1 = (!diag || c0 + 1 <= rbase    ) ? __expf(p[j][1]) : 0.f;
            float e2 = (!diag || c0     <= rbase + 8) ? __expf(p[j][2]) : 0.f;
            float e3 = (!diag || c0 + 1 <= rbase + 8) ? __expf(p[j][3]) : 0.f;
            p[j][0] = e0; p[j][1] = e1; p[j][2] = e2; p[j][3] = e3;
            l0 += e0 + e1; l1 += e2 + e3;
        }

        cp_wait0();
        __syncthreads();

        // PV half 0 (A-frags straight from p registers)
#pragma unroll
        for (int t = 0; t < 8; t++) {
            unsigned a0 = f2tf32(p[t][0]);
            unsigned a1 = f2tf32(p[t][2]);
            unsigned a2 = f2tf32(p[t][1]);
            unsigned a3 = f2tf32(p[t][3]);
            int krp = t * 8 + 2 * q4;
#pragma unroll
            for (int j = 0; j < 8; j++) {
                int n = j * 8 + rq;
                uint2 vb = *(const uint2*)&Vs[n * VST + krp];
                mma8(cacc[j], a0, a1, a2, a3, vb.x, vb.y);
            }
        }

        // S half 1
#pragma unroll
        for (int j = 0; j < 8; j++) { p[j][0] = p[j][1] = p[j][2] = p[j][3] = 0.f; }
#pragma unroll
        for (int ks = 0; ks < 8; ks++) {
            const int kp = ks * 8 + 2 * q4;
            uint2 qlo = *(const uint2*)&Qw[rq * QST + kp];
            uint2 qhi = *(const uint2*)&Qw[(rq + 8) * QST + kp];
#pragma unroll
            for (int j = 0; j < 8; j++) {
                int n = (8 + j) * 8 + rq;
                uint2 kb = *(const uint2*)&Ks[n * KST + kp];
                mma8(p[j], qlo.x, qhi.x, qlo.y, qhi.y, kb.x, kb.y);
            }
        }
#pragma unroll
        for (int j = 0; j < 8; j++) {
            int c0 = kt * 128 + (8 + j) * 8 + 2 * q4;
            float e0 = (!diag || c0     <= rbase    ) ? __expf(p[j][0]) : 0.f;
            float e1 = (!diag || c0 + 1 <= rbase    ) ? __expf(p[j][1]) : 0.f;
            float e2 = (!diag || c0     <= rbase + 8) ? __expf(p[j][2]) : 0.f;
            float e3 = (!diag || c0 + 1 <= rbase + 8) ? __expf(p[j][3]) : 0.f;
            p[j][0] = e0; p[j][1] = e1; p[j][2] = e2; p[j][3] = e3;
            l0 += e0 + e1; l1 += e2 + e3;
        }

        __syncthreads();
        if (kt < qt) { loadK(kt + 1); cp_commit(); }

        // PV half 1
#pragma unroll
        for (int t = 0; t < 8; t++) {
            unsigned a0 = f2tf32(p[t][0]);
            unsigned a1 = f2tf32(p[t][2]);
            unsigned a2 = f2tf32(p[t][1]);
            unsigned a3 = f2tf32(p[t][3]);
            int krp = (8 + t) * 8 + 2 * q4;
#pragma unroll
            for (int j = 0; j < 8; j++) {
                int n = j * 8 + rq;
                uint2 vb = *(const uint2*)&Vs[n * VST + krp];
                mma8(cacc[j], a0, a1, a2, a3, vb.x, vb.y);
            }
        }

        __syncthreads();
        if (kt < qt) { loadV(kt + 1); cp_commit(); }
    }

    l0 += __shfl_xor_sync(0xffffffffu, l0, 1);
    l0 += __shfl_xor_sync(0xffffffffu, l0, 2);
    l1 += __shfl_xor_sync(0xffffffffu, l1, 1);
    l1 += __shfl_xor_sync(0xffffffffu, l1, 2);
    float inv0 = 1.0f / l0, inv1 = 1.0f / l1;

    // row inverses for pass B
    if (q4 == 0) {
        linv[(long long)z * Sq + rbase]     = inv0;
        linv[(long long)z * Sq + rbase + 8] = inv1;
    }

    // ctx epilogue -> tf32 bits, d-permuted
    {
        int b_ = z >> 4, h_ = z & 15;
        long long base0 = ((long long)b_ * Sq + rbase) * DM + h_ * 64;
        long long base1 = base0 + 8LL * DM;
        int r0 = 2 * q4;
        int p0 = perm8(r0), p1 = perm8(r0 + 1);
#pragma unroll
        for (int j = 0; j < 8; j++) {
            int g = j * 8;
            ctx[base0 + g + p0] = f2tf32(cacc[j][0] * inv0);
            ctx[base0 + g + p1] = f2tf32(cacc[j][1] * inv0);
            ctx[base1 + g + p0] = f2tf32(cacc[j][2] * inv1);
            ctx[base1 + g + p1] = f2tf32(cacc[j][3] * inv1);
        }
    }
}

// ---------------------------------------------------------------------------
// Fused tail: blocks 0..255 = out-projection GEMM (dispatched FIRST so the
// tensor-heavy GEMM co-runs under the DRAM-heavy pass B); blocks 256..767 =
// attn pass B (long-qt first).
// ---------------------------------------------------------------------------
struct FuseP {
    const unsigned *ctx, *wo; const float* bo; float* Y;   // out-proj
    const unsigned *qh, *kh; float* attn; const float* linv;
    int write_attn;
};

#define FB_SMEM_BYTES (4 * BUF_WORDS * 4)   // 80 KB covers both roles

__global__ __launch_bounds__(256, 2)
void fused_bo(FuseP f)
{
    extern __shared__ unsigned smu[];
    const int tid = threadIdx.x, lane = tid & 31, warp = tid >> 5;

    if (blockIdx.x < 256) {
        // ================= out-proj GEMM (A tf32 d-perm, W tf32 k-perm) =====
        constexpr int AS_ = 40;
        int obx = blockIdx.x;
        const int n0 = (obx & 7) * 128;
        const int m0 = (obx >> 3) * 128;
        const int wm = warp & 1, wn = warp >> 1;

        unsigned* Abuf[2] = { smu,                 smu + BUF_WORDS     };
        unsigned* Bbuf[2] = { smu + 2 * BUF_WORDS, smu + 3 * BUF_WORDS };

        auto loadA = [&](unsigned* As_, int k0) {
            int r0 = tid >> 3, c = (tid & 7) * 4;
#pragma unroll
            for (int it = 0; it < 4; it++) {
                int r = r0 + it * 32;
                cpa16(&As_[r * AS_ + c], &f.ctx[(long long)(m0 + r) * DM + k0 + c]);
            }
        };
        auto loadB = [&](unsigned* Bs_, int k0) {
            int r0 = tid >> 3, c = (tid & 7) * 4;
#pragma unroll
            for (int it = 0; it < 4; it++) {
                int r = r0 + it * 32;
                cpa16(&Bs_[r * AS_ + c], &f.wo[(long long)(n0 + r) * DM + k0 + c]);
            }
        };

        float acc[4][4][4] = {};
        loadA(Abuf[0], 0); loadB(Bbuf[0], 0); cp_commit();
        int st = 0;
        for (int k0 = 0; k0 < DM; k0 += 32) {
            if (k0 + 32 < DM) { loadA(Abuf[st ^ 1], k0 + 32); loadB(Bbuf[st ^ 1], k0 + 32); }
            cp_commit();
            cp_wait1();
            __syncthreads();

            const unsigned* As_ = Abuf[st];
            const unsigned* Bs_ = Bbuf[st];
#pragma unroll
            for (int kk = 0; kk < 32; kk += 8) {
                const int kp = kk + 2 * (lane & 3);
                unsigned a[4][4];
#pragma unroll
                for (int i = 0; i < 4; i++) {
                    int mr = wm * 64 + i * 16 + (lane >> 2);
                    uint2 lo = *(const uint2*)&As_[mr * AS_ + kp];
                    uint2 hi = *(const uint2*)&As_[(mr + 8) * AS_ + kp];
                    a[i][0] = lo.x; a[i][1] = hi.x; a[i][2] = lo.y; a[i][3] = hi.y;
                }
                unsigned b[4][2];
#pragma unroll
                for (int j = 0; j < 4; j++) {
                    int nr = wn * 32 + j * 8 + (lane >> 2);
                    uint2 bb = *(const uint2*)&Bs_[nr * AS_ + kp];
                    b[j][0] = bb.x; b[j][1] = bb.y;
                }
#pragma unroll
                for (int i = 0; i < 4; i++)
#pragma unroll
                    for (int j = 0; j < 4; j++)
                        mma8(acc[i][j], a[i][0], a[i][1], a[i][2], a[i][3], b[j][0], b[j][1]);
            }
            __syncthreads();
            st ^= 1;
        }

#pragma unroll
        for (int i = 0; i < 4; i++)
#pragma unroll
            for (int j = 0; j < 4; j++)
#pragma unroll
                for (int h = 0; h < 2; h++) {
                    int m = m0 + wm * 64 + i * 16 + (lane >> 2) + h * 8;
                    int n = n0 + wn * 32 + j * 8 + (lane & 3) * 2;
                    float v0 = acc[i][j][h * 2]     + f.bo[n];
                    float v1 = acc[i][j][h * 2 + 1] + f.bo[n + 1];
                    *(float2*)&f.Y[(long long)m * DM + n] = make_float2(v0, v1);
                }
        return;
    }

    // ================= attn pass B =========================================
    if (!f.write_attn) return;
    const int pb = blockIdx.x - 256;
    const int z  = pb & 31;
    const int qt = 15 - (pb >> 5);                   // long blocks first

    unsigned* Qs = smu;
    unsigned* Ks = smu + FK_OFF;

    const unsigned* Qg = f.qh + ((long long)z * Sq + qt * 128) * DHq;
    const unsigned* Kg = f.kh + (long long)z * Sq * DHq;
    float* A = f.attn + (long long)z * Sq * Sq;

    for (int i = tid; i < 128 * 16; i += 256) {
        int r = i >> 4, c4 = (i & 15) * 4;
        *(uint4*)&Qs[r * QST + c4] = *(const uint4*)&Qg[r * 64 + c4];
    }

    auto loadK = [&](int kt) {
        for (int i = tid; i < 128 * 16; i += 256) {
            int r = i >> 4, c4 = (i & 15) * 4;
            cpa16(&Ks[r * KST + c4], &Kg[((long long)kt * 128 + r) * 64 + c4]);
        }
    };

    const unsigned* Qw = &Qs[(warp * 16) * QST];
    const int rq = lane >> 2;
    const int q4 = lane & 3;
    const int rbase = qt * 128 + warp * 16 + rq;

    float inv0 = f.linv[(long long)z * Sq + rbase];
    float inv1 = f.linv[(long long)z * Sq + rbase + 8];

    float p[8][4];

    loadK(0); cp_commit();
    for (int kt = 0; kt <= qt; kt++) {
        cp_wait0();
        __syncthreads();

        bool diag = (kt == qt);
        long long row0 = (long long)rbase * Sq;
        long long row1 = (long long)(rbase + 8) * Sq;

        // S half 0 + write
#pragma unroll
        for (int j = 0; j < 8; j++) { p[j][0] = p[j][1] = p[j][2] = p[j][3] = 0.f; }
#pragma unroll
        for (int ks = 0; ks < 8; ks++) {
            const int kp = ks * 8 + 2 * q4;
            uint2 qlo = *(const uint2*)&Qw[rq * QST + kp];
            uint2 qhi = *(const uint2*)&Qw[(rq + 8) * QST + kp];
#pragma unroll
            for (int j = 0; j < 8; j++) {
                int n = j * 8 + rq;
                uint2 kb = *(const uint2*)&Ks[n * KST + kp];
                mma8(p[j], qlo.x, qhi.x, qlo.y, qhi.y, kb.x, kb.y);
            }
        }
#pragma unroll
        for (int j = 0; j < 8; j++) {
            int c0 = kt * 128 + j * 8 + 2 * q4;
            float e0 = (!diag || c0     <= rbase    ) ? __expf(p[j][0]) * inv0 : 0.f;
            float e1 = (!diag || c0 + 1 <= rbase    ) ? __expf(p[j][1]) * inv0 : 0.f;
            float e2 = (!diag || c0     <= rbase + 8) ? __expf(p[j][2]) * inv1 : 0.f;
            float e3 = (!diag || c0 + 1 <= rbase + 8) ? __expf(p[j][3]) * inv1 : 0.f;
            *(float2*)&A[row0 + c0] = make_float2(e0, e1);
            *(float2*)&A[row1 + c0] = make_float2(e2, e3);
        }

        // S half 1 mma, prefetch K overlapped with epilogue
#pragma unroll
        for (int j = 0; j < 8; j++) { p[j][0] = p[j][1] = p[j][2] = p[j][3] = 0.f; }
#pragma unroll
        for (int ks = 0; ks < 8; ks++) {
            const int kp = ks * 8 + 2 * q4;
            uint2 qlo = *(const uint2*)&Qw[rq * QST + kp];
            uint2 qhi = *(const uint2*)&Qw[(rq + 8) * QST + kp];
#pragma unroll
            for (int j = 0; j < 8; j++) {
                int n = (8 + j) * 8 + rq;
                uint2 kb = *(const uint2*)&Ks[n * KST + kp];
                mma8(p[j], qlo.x, qhi.x, qlo.y, qhi.y, kb.x, kb.y);
            }
        }
        __syncthreads();
        if (kt < qt) { loadK(kt + 1); cp_commit(); }
#pragma unroll
        for (int j = 0; j < 8; j++) {
            int c0 = kt * 128 + (8 + j) * 8 + 2 * q4;
            float e0 = (!diag || c0     <= rbase    ) ? __expf(p[j][0]) * inv0 : 0.f;
            float e1 = (!diag || c0 + 1 <= rbase    ) ? __expf(p[j][1]) * inv0 : 0.f;
            float e2 = (!diag || c0     <= rbase + 8) ? __expf(p[j][2]) * inv1 : 0.f;
            float e3 = (!diag || c0 + 1 <= rbase + 8) ? __expf(p[j][3]) * inv1 : 0.f;
            *(float2*)&A[row0 + c0] = make_float2(e0, e1);
            *(float2*)&A[row1 + c0] = make_float2(e2, e3);
        }
    }

    // zero-fill the strictly-causal-upper region (division-free, coalesced:
    // one row per warp, lanes stride the columns with float4 stores)
    int cEnd = (qt + 1) * 128;
    if (cEnd < Sq) {
        float4 z4 = make_float4(0.f, 0.f, 0.f, 0.f);
        for (int r = warp; r < 128; r += 8) {
            float* row = &A[(long long)(qt * 128 + r) * Sq];
            for (int c = cEnd + lane * 4; c < Sq; c += 128)
                *(float4*)&row[c] = z4;
        }
    }
}

// ---------------------------------------------------------------------------
// kernel_launch
// ---------------------------------------------------------------------------
extern "C" void kernel_launch(void* const* d_in, const int* in_sizes, int n_in,
                              void* d_out, int out_size)
{
    const float* q  = (const float*)d_in[0];
    const float* k  = (const float*)d_in[1];
    const float* v  = (const float*)d_in[2];
    // d_in[3] = causal tril mask (handled analytically)
    const float* wq = (const float*)d_in[4];
    const float* bq = (const float*)d_in[5];
    const float* wk = (const float*)d_in[6];
    const float* bk = (const float*)d_in[7];
    const float* wv = (const float*)d_in[8];
    const float* bv = (const float*)d_in[9];
    const float* wo = (const float*)d_in[10];
    const float* bo = (const float*)d_in[11];
    float* out = (float*)d_out;

    unsigned *qh, *kh, *vh, *ctx, *pwq, *pwk, *pwv, *pwo;
    float* linv;
    cudaGetSymbolAddress((void**)&qh,   g_qh);
    cudaGetSymbolAddress((void**)&kh,   g_kh);
    cudaGetSymbolAddress((void**)&vh,   g_vh);
    cudaGetSymbolAddress((void**)&ctx,  g_ctx);
    cudaGetSymbolAddress((void**)&linv, g_linv);
    cudaGetSymbolAddress((void**)&pwq,  g_wq);
    cudaGetSymbolAddress((void**)&pwk,  g_wk);
    cudaGetSymbolAddress((void**)&pwv,  g_wv);
    cudaGetSymbolAddress((void**)&pwo,  g_wo);

    const long long OUT_E  = (long long)Bq * Sq * DM;
    const long long ATTN_E = (long long)Bq * Hq * Sq * Sq;
    int write_attn = ((long long)out_size >= OUT_E + ATTN_E) ? 1 : 0;
    float* attn = out + OUT_E;

    static int attr_done = 0;
    if (!attr_done) {
        cudaFuncSetAttribute(gemm_qkv,
                             cudaFuncAttributeMaxDynamicSharedMemorySize, G_SMEM_BYTES);
        cudaFuncSetAttribute(attn_flash_a,
                             cudaFuncAttributeMaxDynamicSharedMemorySize, F_SMEM_BYTES);
        cudaFuncSetAttribute(fused_bo,
                             cudaFuncAttributeMaxDynamicSharedMemorySize, FB_SMEM_BYTES);
        attr_done = 1;
    }

    // 0: prep — WEIGHTS only -> tf32 bits, K-permuted
    PrepP pp;
    pp.in[0] = wq; pp.out[0] = pwq;
    pp.in[1] = wk; pp.out[1] = pwk;
    pp.in[2] = wv; pp.out[2] = pwv;
    pp.in[3] = wo; pp.out[3] = pwo;
    prep_cvt<<<dim3((DM * DM) / (256 * 4), 4), 256>>>(pp);

    // 1: fused QKV projections
    GemmP pq = {};
    pq.X  = (const unsigned*)q; pq.W  = pwq; pq.b0_ = bq; pq.Y  = qh;
    pq.X1 = (const unsigned*)k; pq.W1 = pwk; pq.b1_ = bk; pq.Y1 = kh;
    pq.X2 = (const unsigned*)v; pq.W2 = pwv; pq.b2_ = bv; pq.Y2 = vh;
    pq.K = DM;
    pq.ps[0] = 0.125f; pq.ps[1] = 1.f; pq.ps[2] = 1.f;
    pq.nperm[0] = 1; pq.nperm[1] = 1; pq.nperm[2] = 2;
    gemm_qkv<<<dim3(DM / 128, (Bq * Sq) / 128, 3), 256, G_SMEM_BYTES>>>(pq);

    // 2: flash pass A (ctx + row inverses)
    attn_flash_a<<<dim3(Sq / 128, Bq * Hq, 1), 256, F_SMEM_BYTES>>>(
        qh, kh, vh, ctx, linv);

    // 3: fused tail — out-proj first (256 blocks), then attn pass B (512)
    FuseP f = {};
    f.ctx = ctx; f.wo = pwo; f.bo = bo; f.Y = out;
    f.qh = qh; f.kh = kh; f.attn = attn; f.linv = linv;
    f.write_attn = write_attn;
    fused_bo<<<768, 256, FB_SMEM_BYTES>>>(f);
}